// round 7
// baseline (speedup 1.0000x reference)
#include <cuda_runtime.h>
#include <cuda_bf16.h>
#include <cstdint>

#define NB   4
#define CCH  512
#define NPIX 2304
#define CR   64
#define CH4  128
#define HW   48
#define KCONV 4608

// ---------------- fp32 scratch ----------------
__device__ float g_E[(size_t)NB*NPIX*NPIX];
__device__ float g_stats[6*NB*NPIX];
__device__ float g_buf0[NB*CCH*NPIX];
__device__ float g_buf1[NB*CCH*NPIX];
__device__ float g_out1[NB*CCH*NPIX];
__device__ float g_expd[NB*CCH*CCH];

// ---------------- bf16 split scratch ----------------
__device__ __nv_bfloat16 g_wq_h[CR*CCH],  g_wq_l[CR*CCH];
__device__ __nv_bfloat16 g_wk_h[CR*CCH],  g_wk_l[CR*CCH];
__device__ __nv_bfloat16 g_wv_h[CCH*CCH], g_wv_l[CCH*CCH];
__device__ __nv_bfloat16 g_cw1_h[CCH*KCONV], g_cw1_l[CCH*KCONV];
__device__ __nv_bfloat16 g_cw2_h[CCH*KCONV], g_cw2_l[CCH*KCONV];
__device__ __nv_bfloat16 g_qw1_h[CH4*CCH], g_qw1_l[CH4*CCH];
__device__ __nv_bfloat16 g_qw2_h[CH4*CCH], g_qw2_l[CH4*CCH];
__device__ __nv_bfloat16 g_ew1_h[CCH*CH4], g_ew1_l[CCH*CH4];
__device__ __nv_bfloat16 g_ew2_h[CCH*CH4], g_ew2_l[CCH*CH4];
__device__ uint32_t g_xi_h[(size_t)NB*(CCH/2)*NPIX], g_xi_l[(size_t)NB*(CCH/2)*NPIX];
__device__ __nv_bfloat16 g_qT_h[NB*NPIX*CR], g_qT_l[NB*NPIX*CR];
__device__ __nv_bfloat16 g_k_h[NB*CR*NPIX],  g_k_l[NB*CR*NPIX];
__device__ __nv_bfloat16 g_v_h[NB*CCH*NPIX], g_v_l[NB*CCH*NPIX];
__device__ __nv_bfloat16 g_at_h[(size_t)NB*NPIX*NPIX], g_at_l[(size_t)NB*NPIX*NPIX];
__device__ uint32_t g_ci_h[(size_t)NB*(KCONV/2)*NPIX], g_ci_l[(size_t)NB*(KCONV/2)*NPIX];
__device__ __nv_bfloat16 g_b0_h[NB*CCH*NPIX], g_b0_l[NB*CCH*NPIX];
__device__ __nv_bfloat16 g_o1_h[NB*CCH*NPIX], g_o1_l[NB*CCH*NPIX];
__device__ __nv_bfloat16 g_qc_h[NB*CH4*NPIX], g_qc_l[NB*CH4*NPIX];
__device__ __nv_bfloat16 g_e2_h[NB*CH4*CCH],  g_e2_l[NB*CH4*CCH];
__device__ __nv_bfloat16 g_ac_h[NB*CCH*CCH],  g_ac_l[NB*CCH*CCH];
__device__ __nv_bfloat16 g_vc_h[NB*CCH*NPIX], g_vc_l[NB*CCH*NPIX];

// ---------------- reductions ----------------
__device__ __forceinline__ float warpMax(float v){
  #pragma unroll
  for (int o=16;o;o>>=1) v = fmaxf(v, __shfl_xor_sync(0xffffffffu, v, o));
  return v;
}
__device__ __forceinline__ float warpMin(float v){
  #pragma unroll
  for (int o=16;o;o>>=1) v = fminf(v, __shfl_xor_sync(0xffffffffu, v, o));
  return v;
}
__device__ __forceinline__ float warpSum(float v){
  #pragma unroll
  for (int o=16;o;o>>=1) v += __shfl_xor_sync(0xffffffffu, v, o);
  return v;
}
__device__ float blockMax(float v, float* sh){
  v = warpMax(v);
  if ((threadIdx.x & 31) == 0) sh[threadIdx.x >> 5] = v;
  __syncthreads();
  if (threadIdx.x < 32){
    float t = (threadIdx.x < (blockDim.x>>5)) ? sh[threadIdx.x] : -3.4e38f;
    t = warpMax(t);
    if (threadIdx.x == 0) sh[0] = t;
  }
  __syncthreads();
  float r = sh[0]; __syncthreads(); return r;
}
__device__ float blockMin(float v, float* sh){
  v = warpMin(v);
  if ((threadIdx.x & 31) == 0) sh[threadIdx.x >> 5] = v;
  __syncthreads();
  if (threadIdx.x < 32){
    float t = (threadIdx.x < (blockDim.x>>5)) ? sh[threadIdx.x] : 3.4e38f;
    t = warpMin(t);
    if (threadIdx.x == 0) sh[0] = t;
  }
  __syncthreads();
  float r = sh[0]; __syncthreads(); return r;
}
__device__ float blockSum(float v, float* sh){
  v = warpSum(v);
  if ((threadIdx.x & 31) == 0) sh[threadIdx.x >> 5] = v;
  __syncthreads();
  if (threadIdx.x < 32){
    float t = (threadIdx.x < (blockDim.x>>5)) ? sh[threadIdx.x] : 0.f;
    t = warpSum(t);
    if (threadIdx.x == 0) sh[0] = t;
  }
  __syncthreads();
  float r = sh[0]; __syncthreads(); return r;
}

// ---------------- helpers ----------------
__device__ __forceinline__ void mma_bf16(float* c, const uint32_t* a, const uint32_t* b){
  asm volatile("mma.sync.aligned.m16n8k16.row.col.f32.bf16.bf16.f32 "
    "{%0,%1,%2,%3}, {%4,%5,%6,%7}, {%8,%9}, {%0,%1,%2,%3};\n"
    : "+f"(c[0]), "+f"(c[1]), "+f"(c[2]), "+f"(c[3])
    : "r"(a[0]), "r"(a[1]), "r"(a[2]), "r"(a[3]), "r"(b[0]), "r"(b[1]));
}
__device__ __forceinline__ void cpasync16(void* dst, const void* src, int szbytes){
  uint32_t d = (uint32_t)__cvta_generic_to_shared(dst);
  asm volatile("cp.async.cg.shared.global [%0], [%1], 16, %2;\n"
               :: "r"(d), "l"(src), "r"(szbytes));
}
__device__ __forceinline__ void cp_commit(){ asm volatile("cp.async.commit_group;\n"); }
__device__ __forceinline__ void cp_wait1(){ asm volatile("cp.async.wait_group 1;\n"); }

__device__ __forceinline__ void bsplit(float v, __nv_bfloat16& h, __nv_bfloat16& l){
  h = __float2bfloat16(v);
  l = __float2bfloat16(v - __bfloat162float(h));
}
__device__ __forceinline__ uint32_t bpack(__nv_bfloat16 a, __nv_bfloat16 b){
  return (uint32_t)__bfloat16_as_ushort(a) | ((uint32_t)__bfloat16_as_ushort(b) << 16);
}

// ---------------- BF16x3 tensor-core GEMM ----------------
// A always bf16 [M][K] row-major (hi/lo arrays).
// BI: 0 = B bf16 [K][N] (k-major rows), 1 = B uint32 [K/2][N] (k-pair interleaved),
//     2 = B bf16 [N][K] (NT).
// EPI: 0 fp32 (+opt bias p0[m]); 2 fp32 gamma*acc+res; 3 relu(acc*p0+p1)->fp32+split;
//      4 relu->split only; 5 (+opt bias)->split only; 6 (+bias)->transposed split (ldT).
// Block tile 128x128x16; N%128==0, K%16==0, K>=32.
template<int BI, int EPI>
__global__ void __launch_bounds__(256,2) gemm3_kernel(
    const __nv_bfloat16* __restrict__ Ah, const __nv_bfloat16* __restrict__ Al, long sA,
    const void* __restrict__ Bh_, const void* __restrict__ Bl_, long sB,
    float* __restrict__ Cm, long sC,
    __nv_bfloat16* __restrict__ Dh, __nv_bfloat16* __restrict__ Dl, long sD,
    int M, int N, int K,
    const float* __restrict__ p0, const float* __restrict__ p1,
    const float* __restrict__ res, long sRes,
    const float* __restrict__ gamma, int ldT)
{
  constexpr int AROW = 24;         // bf16 stride per row (16 data + pad)
  constexpr int ABF  = 128*AROW;   // bf16 per A array per stage
  constexpr int ABYTES = 2*ABF*2;  // hi+lo bytes
  constexpr int BBYTES = (BI==2) ? 2*ABF*2 : 2*16*136*2;  // BI1: 2*8*136*4 = same
  constexpr int STAGEB = ABYTES + BBYTES;

  extern __shared__ char smc[];

  const int bz = blockIdx.z;
  Ah += (long)bz * sA;  Al += (long)bz * sA;
  const char* Bhp = (const char*)Bh_;
  const char* Blp = (const char*)Bl_;
  if (Cm) Cm += (long)bz * sC;
  if (EPI >= 3){ Dh += (long)bz * sD; Dl += (long)bz * sD; }
  if (EPI == 2) res += (long)bz * sRes;

  const int tid  = threadIdx.x;
  const int warp = tid >> 5;
  const int lane = tid & 31;
  const int g    = lane >> 2;
  const int ct   = lane & 3;
  const int warpM = warp >> 2;
  const int warpN = warp & 3;
  const int m0 = blockIdx.y * 128;
  const int n0 = blockIdx.x * 128;

  float acc[4][4][4];
  #pragma unroll
  for (int i=0;i<4;i++)
    #pragma unroll
    for (int j=0;j<4;j++)
      #pragma unroll
      for (int c=0;c<4;c++) acc[i][j][c]=0.f;

  auto loadT = [&](int s, int k0){
    char* st = smc + s*STAGEB;
    __nv_bfloat16* Ahs = (__nv_bfloat16*)st;
    // A (hi then lo)
    #pragma unroll
    for (int c = tid; c < 512; c += 256){
      const __nv_bfloat16* base = (c < 256) ? Ah : Al;
      __nv_bfloat16* dst = Ahs + ((c < 256) ? 0 : ABF);
      int e = c & 255, row = e >> 1, half = e & 1;
      int gm = m0 + row;
      int sz = (gm < M) ? 16 : 0; if (gm >= M) gm = 0;
      cpasync16(dst + row*AROW + half*8, base + (long)gm*K + k0 + half*8, sz);
    }
    char* bst = st + ABYTES;
    if (BI == 2){
      __nv_bfloat16* Bs = (__nv_bfloat16*)bst;
      const __nv_bfloat16* BH = (const __nv_bfloat16*)Bhp + (long)bz*sB;
      const __nv_bfloat16* BL = (const __nv_bfloat16*)Blp + (long)bz*sB;
      #pragma unroll
      for (int c = tid; c < 512; c += 256){
        const __nv_bfloat16* base = (c < 256) ? BH : BL;
        __nv_bfloat16* dst = Bs + ((c < 256) ? 0 : ABF);
        int e = c & 255, row = e >> 1, half = e & 1;
        cpasync16(dst + row*AROW + half*8, base + (long)(n0+row)*K + k0 + half*8, 16);
      }
    } else if (BI == 0){
      __nv_bfloat16* Bs = (__nv_bfloat16*)bst;
      const __nv_bfloat16* BH = (const __nv_bfloat16*)Bhp + (long)bz*sB;
      const __nv_bfloat16* BL = (const __nv_bfloat16*)Blp + (long)bz*sB;
      #pragma unroll
      for (int c = tid; c < 512; c += 256){
        const __nv_bfloat16* base = (c < 256) ? BH : BL;
        __nv_bfloat16* dst = Bs + ((c < 256) ? 0 : 16*136);
        int e = c & 255, row = e >> 4, ch = e & 15;
        cpasync16(dst + row*136 + ch*8, base + (long)(k0+row)*N + n0 + ch*8, 16);
      }
    } else {
      uint32_t* Bs = (uint32_t*)bst;
      const uint32_t* BH = (const uint32_t*)Bhp + (long)bz*sB;
      const uint32_t* BL = (const uint32_t*)Blp + (long)bz*sB;
      #pragma unroll
      for (int c = tid; c < 512; c += 256){
        const uint32_t* base = (c < 256) ? BH : BL;
        uint32_t* dst = Bs + ((c < 256) ? 0 : 8*136);
        int e = c & 255, row = e >> 5, ch = e & 31;
        cpasync16(dst + row*136 + ch*4, base + (long)(k0/2+row)*N + n0 + ch*4, 16);
      }
    }
  };

  const int T = K/16;
  loadT(0, 0);  cp_commit();
  loadT(1, 16); cp_commit();

  for (int i = 0; i < T; i++){
    cp_wait1();
    __syncthreads();
    if (i + 2 < T) loadT((i+2)%3, (i+2)*16);
    cp_commit();

    const char* st = smc + (i%3)*STAGEB;
    const __nv_bfloat16* Ahs = (const __nv_bfloat16*)st;
    const __nv_bfloat16* Als = Ahs + ABF;
    const char* bst = st + ABYTES;

    uint32_t ah[4][4], al[4][4], bh[4][2], bl[4][2];
    #pragma unroll
    for (int mi=0; mi<4; mi++){
      int r = warpM*64 + mi*16 + g;
      ah[mi][0] = *(const uint32_t*)&Ahs[(r  )*AROW + 2*ct  ];
      ah[mi][1] = *(const uint32_t*)&Ahs[(r+8)*AROW + 2*ct  ];
      ah[mi][2] = *(const uint32_t*)&Ahs[(r  )*AROW + 2*ct+8];
      ah[mi][3] = *(const uint32_t*)&Ahs[(r+8)*AROW + 2*ct+8];
      al[mi][0] = *(const uint32_t*)&Als[(r  )*AROW + 2*ct  ];
      al[mi][1] = *(const uint32_t*)&Als[(r+8)*AROW + 2*ct  ];
      al[mi][2] = *(const uint32_t*)&Als[(r  )*AROW + 2*ct+8];
      al[mi][3] = *(const uint32_t*)&Als[(r+8)*AROW + 2*ct+8];
    }
    #pragma unroll
    for (int nj=0; nj<4; nj++){
      int cl = warpN*32 + nj*8 + g;
      if (BI == 2){
        const __nv_bfloat16* Bhs = (const __nv_bfloat16*)bst;
        const __nv_bfloat16* Bls = Bhs + ABF;
        bh[nj][0] = *(const uint32_t*)&Bhs[cl*AROW + 2*ct  ];
        bh[nj][1] = *(const uint32_t*)&Bhs[cl*AROW + 2*ct+8];
        bl[nj][0] = *(const uint32_t*)&Bls[cl*AROW + 2*ct  ];
        bl[nj][1] = *(const uint32_t*)&Bls[cl*AROW + 2*ct+8];
      } else if (BI == 1){
        const uint32_t* Bhs = (const uint32_t*)bst;
        const uint32_t* Bls = Bhs + 8*136;
        bh[nj][0] = Bhs[(ct  )*136 + cl];
        bh[nj][1] = Bhs[(ct+4)*136 + cl];
        bl[nj][0] = Bls[(ct  )*136 + cl];
        bl[nj][1] = Bls[(ct+4)*136 + cl];
      } else {
        const __nv_bfloat16* Bhs = (const __nv_bfloat16*)bst;
        const __nv_bfloat16* Bls = Bhs + 16*136;
        #pragma unroll
        for (int hv=0; hv<2; hv++){
          int kb = 2*ct + hv*8;
          bh[nj][hv] = (uint32_t)(*(const uint16_t*)&Bhs[(kb  )*136 + cl])
                     | ((uint32_t)(*(const uint16_t*)&Bhs[(kb+1)*136 + cl]) << 16);
          bl[nj][hv] = (uint32_t)(*(const uint16_t*)&Bls[(kb  )*136 + cl])
                     | ((uint32_t)(*(const uint16_t*)&Bls[(kb+1)*136 + cl]) << 16);
        }
      }
    }
    #pragma unroll
    for (int mi=0; mi<4; mi++)
      #pragma unroll
      for (int nj=0; nj<4; nj++){
        mma_bf16(acc[mi][nj], ah[mi], bh[nj]);
        mma_bf16(acc[mi][nj], ah[mi], bl[nj]);
        mma_bf16(acc[mi][nj], al[mi], bh[nj]);
      }
  }

  __syncthreads();

  // ---- epilogue
  #pragma unroll
  for (int mi=0; mi<4; mi++){
    int rr[2] = { m0 + warpM*64 + mi*16 + g, m0 + warpM*64 + mi*16 + g + 8 };
    float sc[2] = {0.f,0.f}, of[2] = {0.f,0.f};
    #pragma unroll
    for (int h=0; h<2; h++){
      if (rr[h] < M){
        if (EPI == 1 || EPI == 3 || EPI == 4){ sc[h] = p0[rr[h]]; of[h] = p1[rr[h]]; }
        else if (EPI == 0 || EPI == 5 || EPI == 6){ if (p0) of[h] = p0[rr[h]]; }
      }
    }
    #pragma unroll
    for (int nj=0; nj<4; nj++){
      int n = n0 + warpN*32 + nj*8 + 2*ct;
      #pragma unroll
      for (int h=0; h<2; h++){
        int r = rr[h];
        if (r >= M) continue;
        float wx = acc[mi][nj][2*h], wy = acc[mi][nj][2*h+1];
        if (EPI == 0){ wx += of[h]; wy += of[h]; }
        else if (EPI == 2){
          float2 rv = *(const float2*)&res[(long)r*N + n];
          wx = gamma[0]*wx + rv.x; wy = gamma[0]*wy + rv.y;
        } else if (EPI == 3 || EPI == 4){
          wx = fmaxf(wx*sc[h] + of[h], 0.f);
          wy = fmaxf(wy*sc[h] + of[h], 0.f);
        } else { wx += of[h]; wy += of[h]; }
        if (EPI == 0 || EPI == 2 || EPI == 3){
          float2 w; w.x = wx; w.y = wy;
          *(float2*)&Cm[(long)r*N + n] = w;
        }
        if (EPI >= 3){
          __nv_bfloat16 hx, lx, hy, ly;
          bsplit(wx, hx, lx); bsplit(wy, hy, ly);
          if (EPI == 6){
            Dh[(long)n*ldT + r] = hx;       Dl[(long)n*ldT + r] = lx;
            Dh[(long)(n+1)*ldT + r] = hy;   Dl[(long)(n+1)*ldT + r] = ly;
          } else {
            *(uint32_t*)&Dh[(long)r*N + n] = bpack(hx, hy);
            *(uint32_t*)&Dl[(long)r*N + n] = bpack(lx, ly);
          }
        }
      }
    }
  }
}

// ---------------- softmax row stats ----------------
__global__ __launch_bounds__(256) void softmax_stats_kernel(
    const float* __restrict__ E, const float* __restrict__ M1,
    const float* __restrict__ M2, float* __restrict__ st)
{
  __shared__ float sh[32];
  const int R = NB*NPIX;
  int row = blockIdx.x;
  int mr  = row % NPIX;
  const float* e  = E  + (long)row * NPIX;
  const float* m1 = M1 + (long)mr  * NPIX;
  const float* m2 = M2 + (long)mr  * NPIX;
  int tid = threadIdx.x;
  float ev[9], w1[9], w2[9];
  float mx0=-3.4e38f, mx1=-3.4e38f, mx2=-3.4e38f;
  #pragma unroll
  for (int i=0;i<9;i++){
    int n = tid + i*256;
    ev[i]=e[n]; w1[i]=m1[n]; w2[i]=m2[n];
    mx0 = fmaxf(mx0, ev[i]);
    if (w1[i] > 0.f) mx1 = fmaxf(mx1, ev[i]);
    if (w2[i] > 0.f) mx2 = fmaxf(mx2, ev[i]);
  }
  mx0 = blockMax(mx0, sh); mx1 = blockMax(mx1, sh); mx2 = blockMax(mx2, sh);
  float s0=0.f, s1=0.f, s2=0.f;
  #pragma unroll
  for (int i=0;i<9;i++){
    s0 += __expf(ev[i]-mx0);
    s1 += (w1[i] > 0.f) ? __expf(ev[i]-mx1) : 0.f;
    s2 += (w2[i] > 0.f) ? __expf(ev[i]-mx2) : 0.f;
  }
  s0 = blockSum(s0, sh); s1 = blockSum(s1, sh); s2 = blockSum(s2, sh);
  if (tid == 0){
    st[row]       = mx0;  st[R   + row] = 1.f/s0;
    st[2*R + row] = mx1;  st[3*R + row] = 1.f/s1;
    st[4*R + row] = mx2;  st[5*R + row] = 1.f/s2;
  }
}

// ---------------- attention matrix -> bf16 split ----------------
__global__ __launch_bounds__(256) void attn_mat_kernel(
    const float* __restrict__ E, const float* __restrict__ mask,
    const float* __restrict__ st, __nv_bfloat16* __restrict__ Ahd,
    __nv_bfloat16* __restrict__ Ald, long total4)
{
  const long NN2 = (long)NPIX*NPIX;
  long i4 = (long)blockIdx.x * 256 + threadIdx.x;
  if (i4 >= total4) return;
  long idx = i4 * 4;
  int  b   = (int)(idx / NN2);
  long rem = idx - (long)b * NN2;
  int  mr  = (int)(rem / NPIX);
  float mx   = st[b*NPIX + mr];
  float rinv = st[NB*NPIX + b*NPIX + mr];
  float4 e = *(const float4*)&E[idx];
  float4 a;
  a.x = __expf(e.x-mx)*rinv; a.y = __expf(e.y-mx)*rinv;
  a.z = __expf(e.z-mx)*rinv; a.w = __expf(e.w-mx)*rinv;
  if (mask){
    float4 mk = *(const float4*)&mask[rem];
    if (mk.x <= 0.f) a.x = 0.f;
    if (mk.y <= 0.f) a.y = 0.f;
    if (mk.z <= 0.f) a.z = 0.f;
    if (mk.w <= 0.f) a.w = 0.f;
  }
  __nv_bfloat16 h0,l0,h1,l1,h2,l2,h3,l3;
  bsplit(a.x,h0,l0); bsplit(a.y,h1,l1); bsplit(a.z,h2,l2); bsplit(a.w,h3,l3);
  *(uint32_t*)&Ahd[idx]   = bpack(h0,h1);
  *(uint32_t*)&Ahd[idx+2] = bpack(h2,h3);
  *(uint32_t*)&Ald[idx]   = bpack(l0,l1);
  *(uint32_t*)&Ald[idx+2] = bpack(l2,l3);
}

// ---------------- chl softmax -> bf16 split ----------------
__global__ __launch_bounds__(256) void chl_softmax_kernel(
    const float* __restrict__ E, __nv_bfloat16* __restrict__ Ahd,
    __nv_bfloat16* __restrict__ Ald)
{
  __shared__ float sh[32];
  long row = blockIdx.x;
  const float* e = E + row * CCH;
  int tid = threadIdx.x;
  float v0 = e[tid], v1 = e[tid+256];
  float mn = blockMin(fminf(v0, v1), sh);
  float t0 = __expf(mn - v0), t1 = __expf(mn - v1);
  float s = blockSum(t0 + t1, sh);
  float rinv = 1.f/s;
  __nv_bfloat16 h,l;
  bsplit(t0*rinv, h, l); Ahd[row*CCH + tid]     = h; Ald[row*CCH + tid]     = l;
  bsplit(t1*rinv, h, l); Ahd[row*CCH + tid+256] = h; Ald[row*CCH + tid+256] = l;
}

// ---------------- im2col -> interleaved bf16 split ----------------
__global__ __launch_bounds__(256) void im2col_kernel(const float* __restrict__ X,
    uint32_t* __restrict__ Ch, uint32_t* __restrict__ Cl)
{
  const long total = (long)NB*(KCONV/2)*NPIX;
  long w = (long)blockIdx.x * 256 + threadIdx.x;
  if (w >= total) return;
  int n = (int)(w % NPIX);
  long t = w / NPIX;
  int k2 = (int)(t % (KCONV/2));
  int b  = (int)(t / (KCONV/2));
  int y0 = n / HW, x0 = n - y0*HW;
  float v[2];
  #pragma unroll
  for (int u=0; u<2; u++){
    int k = 2*k2 + u;
    int ic = k/9, kk = k - ic*9;
    int ky = kk/3, kx = kk - ky*3;
    int y = y0 + ky - 1, x = x0 + kx - 1;
    v[u] = (y >= 0 && y < HW && x >= 0 && x < HW)
         ? X[((long)(b*CCH + ic))*NPIX + y*HW + x] : 0.f;
  }
  __nv_bfloat16 h0,l0,h1,l1;
  bsplit(v[0],h0,l0); bsplit(v[1],h1,l1);
  Ch[w] = bpack(h0,h1);
  Cl[w] = bpack(l0,l1);
}

// ---------------- prepass: plain split ----------------
__global__ __launch_bounds__(256) void split_nat_kernel(const float* __restrict__ X,
    __nv_bfloat16* __restrict__ H, __nv_bfloat16* __restrict__ L, long total)
{
  for (long i = (long)blockIdx.x*256 + threadIdx.x; i < total; i += (long)gridDim.x*256){
    __nv_bfloat16 h,l; bsplit(X[i], h, l); H[i] = h; L[i] = l;
  }
}

// ---------------- prepass: x -> channel-pair interleaved ----------------
__global__ __launch_bounds__(256) void x_inter_kernel(const float* __restrict__ X,
    uint32_t* __restrict__ Hd, uint32_t* __restrict__ Ld)
{
  const long total = (long)NB*(CCH/2)*NPIX;
  long w = (long)blockIdx.x*256 + threadIdx.x;
  if (w >= total) return;
  int n = (int)(w % NPIX);
  long t = w / NPIX;
  int c2 = (int)(t % (CCH/2));
  int b  = (int)(t / (CCH/2));
  float v0 = X[((long)(b*CCH + 2*c2  ))*NPIX + n];
  float v1 = X[((long)(b*CCH + 2*c2+1))*NPIX + n];
  __nv_bfloat16 h0,l0,h1,l1;
  bsplit(v0,h0,l0); bsplit(v1,h1,l1);
  Hd[w] = bpack(h0,h1);
  Ld[w] = bpack(l0,l1);
}

// ---------------- host ----------------
template<int BI, int EPI>
static void rg(const __nv_bfloat16* Ah, const __nv_bfloat16* Al, long sA,
               const void* Bh, const void* Bl, long sB,
               float* C, long sC,
               __nv_bfloat16* Dh, __nv_bfloat16* Dl, long sD,
               int M, int N, int K,
               const float* p0, const float* p1,
               const float* res, long sRes, const float* gamma, int ldT)
{
  constexpr int ABYTES = 2*128*24*2;
  constexpr int BBYTES = (BI==2) ? ABYTES : 2*16*136*2;
  constexpr int SMEM = 3*(ABYTES + BBYTES);
  cudaFuncSetAttribute(gemm3_kernel<BI,EPI>,
                       cudaFuncAttributeMaxDynamicSharedMemorySize, SMEM);
  dim3 grid(N/128, (M+127)/128, NB);
  gemm3_kernel<BI,EPI><<<grid, 256, SMEM>>>(Ah, Al, sA, Bh, Bl, sB, C, sC,
                                            Dh, Dl, sD, M, N, K, p0, p1, res, sRes, gamma, ldT);
}

template<typename T>
static T* sym(const void* s){ void* p = nullptr; cudaGetSymbolAddress(&p, s); return (T*)p; }

extern "C" void kernel_launch(void* const* d_in, const int* in_sizes, int n_in,
                              void* d_out, int out_size)
{
  const float* x       = (const float*)d_in[0];
  const float* wq      = (const float*)d_in[1];
  const float* bq      = (const float*)d_in[2];
  const float* wk      = (const float*)d_in[3];
  const float* bk      = (const float*)d_in[4];
  const float* wv0     = (const float*)d_in[5];
  const float* bv0     = (const float*)d_in[6];
  const float* conv1_w = (const float*)d_in[7];
  const float* conv1_s = (const float*)d_in[8];
  const float* conv1_b = (const float*)d_in[9];
  const float* conv2_w = (const float*)d_in[10];
  const float* conv2_s = (const float*)d_in[11];
  const float* conv2_b = (const float*)d_in[12];
  const float* gamma   = (const float*)d_in[13];
  const float* gamma1  = (const float*)d_in[14];
  const float* gamma2  = (const float*)d_in[15];
  const float* c1_qw   = (const float*)d_in[16];
  const float* c1_qs   = (const float*)d_in[17];
  const float* c1_qb   = (const float*)d_in[18];
  const float* c1_ew   = (const float*)d_in[19];
  const float* c1_eb   = (const float*)d_in[20];
  const float* c2_qw   = (const float*)d_in[21];
  const float* c2_qs   = (const float*)d_in[22];
  const float* c2_qb   = (const float*)d_in[23];
  const float* c2_ew   = (const float*)d_in[24];
  const float* c2_eb   = (const float*)d_in[25];
  const float* mask1   = (const float*)d_in[26];
  const float* mask2   = (const float*)d_in[27];

  typedef __nv_bfloat16 bf;
  float* E    = sym<float>(g_E);    float* st   = sym<float>(g_stats);
  float* buf0 = sym<float>(g_buf0); float* buf1 = sym<float>(g_buf1);
  float* out1 = sym<float>(g_out1); float* expd = sym<float>(g_expd);
  bf *wq_h = sym<bf>(g_wq_h), *wq_l = sym<bf>(g_wq_l);
  bf *wk_h = sym<bf>(g_wk_h), *wk_l = sym<bf>(g_wk_l);
  bf *wv_h = sym<bf>(g_wv_h), *wv_l = sym<bf>(g_wv_l);
  bf *cw1_h = sym<bf>(g_cw1_h), *cw1_l = sym<bf>(g_cw1_l);
  bf *cw2_h = sym<bf>(g_cw2_h), *cw2_l = sym<bf>(g_cw2_l);
  bf *qw1_h = sym<bf>(g_qw1_h), *qw1_l = sym<bf>(g_qw1_l);
  bf *qw2_h = sym<bf>(g_qw2_h), *qw2_l = sym<bf>(g_qw2_l);
  bf *ew1_h = sym<bf>(g_ew1_h), *ew1_l = sym<bf>(g_ew1_l);
  bf *ew2_h = sym<bf>(g_ew2_h), *ew2_l = sym<bf>(g_ew2_l);
  uint32_t *xi_h = sym<uint32_t>(g_xi_h), *xi_l = sym<uint32_t>(g_xi_l);
  bf *qT_h = sym<bf>(g_qT_h), *qT_l = sym<bf>(g_qT_l);
  bf *k_h  = sym<bf>(g_k_h),  *k_l  = sym<bf>(g_k_l);
  bf *v_h  = sym<bf>(g_v_h),  *v_l  = sym<bf>(g_v_l);
  bf *at_h = sym<bf>(g_at_h), *at_l = sym<bf>(g_at_l);
  uint32_t *ci_h = sym<uint32_t>(g_ci_h), *ci_l = sym<uint32_t>(g_ci_l);
  bf *b0_h = sym<bf>(g_b0_h), *b0_l = sym<bf>(g_b0_l);
  bf *o1_h = sym<bf>(g_o1_h), *o1_l = sym<bf>(g_o1_l);
  bf *qc_h = sym<bf>(g_qc_h), *qc_l = sym<bf>(g_qc_l);
  bf *e2_h = sym<bf>(g_e2_h), *e2_l = sym<bf>(g_e2_l);
  bf *ac_h = sym<bf>(g_ac_h), *ac_l = sym<bf>(g_ac_l);
  bf *vc_h = sym<bf>(g_vc_h), *vc_l = sym<bf>(g_vc_l);
  float* out = (float*)d_out;

  const long sX  = (long)CCH*NPIX;
  const long sE  = (long)NPIX*NPIX;
  const long sXI = (long)(CCH/2)*NPIX;
  const long sCI = (long)(KCONV/2)*NPIX;
  const long sQT = (long)NPIX*CR;
  const long sK  = (long)CR*NPIX;
  const long sQC = (long)CH4*NPIX;
  const long sE2 = (long)CH4*CCH;
  const long sCC = (long)CCH*CCH;
  const int  R   = NB*NPIX;
  const long total4 = (long)NB*NPIX*NPIX/4;
  const int  amg = (int)((total4 + 255)/256);
  auto gsz = [](long t){ return (int)((t + 255)/256); };

  // ---- prepass splits (weights + x interleave) ----
  split_nat_kernel<<<gsz(CR*CCH),256>>>(wq, wq_h, wq_l, CR*CCH);
  split_nat_kernel<<<gsz(CR*CCH),256>>>(wk, wk_h, wk_l, CR*CCH);
  split_nat_kernel<<<gsz(CCH*CCH),256>>>(wv0, wv_h, wv_l, CCH*CCH);
  split_nat_kernel<<<gsz((long)CCH*KCONV),256>>>(conv1_w, cw1_h, cw1_l, (long)CCH*KCONV);
  split_nat_kernel<<<gsz((long)CCH*KCONV),256>>>(conv2_w, cw2_h, cw2_l, (long)CCH*KCONV);
  split_nat_kernel<<<gsz(CH4*CCH),256>>>(c1_qw, qw1_h, qw1_l, CH4*CCH);
  split_nat_kernel<<<gsz(CH4*CCH),256>>>(c2_qw, qw2_h, qw2_l, CH4*CCH);
  split_nat_kernel<<<gsz(CCH*CH4),256>>>(c1_ew, ew1_h, ew1_l, CCH*CH4);
  split_nat_kernel<<<gsz(CCH*CH4),256>>>(c2_ew, ew2_h, ew2_l, CCH*CH4);
  x_inter_kernel<<<gsz((long)NB*sXI),256>>>(x, xi_h, xi_l);

  // ---- Q (transposed split), K, V ----
  rg<1,6>(wq_h, wq_l, 0, xi_h, xi_l, sXI, nullptr,0, qT_h, qT_l, sQT,
          CR, NPIX, CCH, bq, nullptr, nullptr,0, nullptr, CR);
  rg<1,5>(wk_h, wk_l, 0, xi_h, xi_l, sXI, nullptr,0, k_h, k_l, sK,
          CR, NPIX, CCH, bk, nullptr, nullptr,0, nullptr, 0);
  rg<1,5>(wv_h, wv_l, 0, xi_h, xi_l, sXI, nullptr,0, v_h, v_l, sX,
          CCH, NPIX, CCH, bv0, nullptr, nullptr,0, nullptr, 0);

  // ---- energy = qT * k ----
  rg<0,0>(qT_h, qT_l, sQT, k_h, k_l, sK, E, sE, nullptr,nullptr,0,
          NPIX, NPIX, CR, nullptr, nullptr, nullptr,0, nullptr, 0);

  softmax_stats_kernel<<<R, 256>>>(E, mask1, mask2, st);

  // ---- pass 0 ----
  attn_mat_kernel<<<amg, 256>>>(E, nullptr, st, at_h, at_l, total4);
  rg<2,2>(v_h, v_l, sX, at_h, at_l, sE, buf1, sX, nullptr,nullptr,0,
          CCH, NPIX, NPIX, nullptr, nullptr, (const float*)x, sX, gamma, 0);
  im2col_kernel<<<gsz((long)NB*sCI), 256>>>(buf1, ci_h, ci_l);
  rg<1,3>(cw1_h, cw1_l, 0, ci_h, ci_l, sCI, buf0, sX, b0_h, b0_l, sX,
          CCH, NPIX, KCONV, conv1_s, conv1_b, nullptr,0, nullptr, 0);

  // chl #1
  rg<0,4>(qw1_h, qw1_l, 0, b0_h, b0_l, sX, nullptr,0, qc_h, qc_l, sQC,
          CH4, NPIX, CCH, c1_qs, c1_qb, nullptr,0, nullptr, 0);
  rg<2,5>(qc_h, qc_l, sQC, b0_h, b0_l, sX, nullptr,0, e2_h, e2_l, sE2,
          CH4, CCH, NPIX, nullptr, nullptr, nullptr,0, nullptr, 0);
  rg<0,0>(ew1_h, ew1_l, 0, e2_h, e2_l, sE2, expd, sCC, nullptr,nullptr,0,
          CCH, CCH, CH4, c1_eb, nullptr, nullptr,0, nullptr, 0);
  chl_softmax_kernel<<<NB*CCH, 256>>>(expd, ac_h, ac_l);
  rg<0,5>(ac_h, ac_l, sCC, b0_h, b0_l, sX, nullptr,0, vc_h, vc_l, sX,
          CCH, NPIX, CCH, nullptr, nullptr, nullptr,0, nullptr, 0);

  // ---- pass 1 ----
  attn_mat_kernel<<<amg, 256>>>(E, mask1, st + 2*R, at_h, at_l, total4);
  rg<2,2>(vc_h, vc_l, sX, at_h, at_l, sE, buf1, sX, nullptr,nullptr,0,
          CCH, NPIX, NPIX, nullptr, nullptr, buf0, sX, gamma1, 0);
  im2col_kernel<<<gsz((long)NB*sCI), 256>>>(buf1, ci_h, ci_l);
  rg<1,3>(cw2_h, cw2_l, 0, ci_h, ci_l, sCI, out1, sX, o1_h, o1_l, sX,
          CCH, NPIX, KCONV, conv2_s, conv2_b, nullptr,0, nullptr, 0);

  // chl #2
  rg<0,4>(qw2_h, qw2_l, 0, o1_h, o1_l, sX, nullptr,0, qc_h, qc_l, sQC,
          CH4, NPIX, CCH, c2_qs, c2_qb, nullptr,0, nullptr, 0);
  rg<2,5>(qc_h, qc_l, sQC, o1_h, o1_l, sX, nullptr,0, e2_h, e2_l, sE2,
          CH4, CCH, NPIX, nullptr, nullptr, nullptr,0, nullptr, 0);
  rg<0,0>(ew2_h, ew2_l, 0, e2_h, e2_l, sE2, expd, sCC, nullptr,nullptr,0,
          CCH, CCH, CH4, c2_eb, nullptr, nullptr,0, nullptr, 0);
  chl_softmax_kernel<<<NB*CCH, 256>>>(expd, ac_h, ac_l);
  rg<0,5>(ac_h, ac_l, sCC, o1_h, o1_l, sX, nullptr,0, vc_h, vc_l, sX,
          CCH, NPIX, CCH, nullptr, nullptr, nullptr,0, nullptr, 0);

  // ---- pass 2 -> out ----
  attn_mat_kernel<<<amg, 256>>>(E, mask2, st + 4*R, at_h, at_l, total4);
  rg<2,2>(vc_h, vc_l, sX, at_h, at_l, sE, out, sX, nullptr,nullptr,0,
          CCH, NPIX, NPIX, nullptr, nullptr, out1, sX, gamma2, 0);

  (void)in_sizes; (void)n_in; (void)out_size;
}

// round 8
// speedup vs baseline: 1.0959x; 1.0959x over previous
#include <cuda_runtime.h>
#include <cuda_bf16.h>
#include <cstdint>

#define NB   4
#define CCH  512
#define NPIX 2304
#define CR   64
#define CH4  128
#define HW   48
#define KCONV 4608

// ---------------- fp32 scratch ----------------
__device__ float g_E[(size_t)NB*NPIX*NPIX];
__device__ float g_stats[6*NB*NPIX];
__device__ float g_buf0[NB*CCH*NPIX];
__device__ float g_buf1[NB*CCH*NPIX];
__device__ float g_out1[NB*CCH*NPIX];
__device__ float g_expd[NB*CCH*CCH];

// ---------------- bf16 split scratch ----------------
__device__ __nv_bfloat16 g_wq_h[CR*CCH],  g_wq_l[CR*CCH];
__device__ __nv_bfloat16 g_wk_h[CR*CCH],  g_wk_l[CR*CCH];
__device__ __nv_bfloat16 g_wv_h[CCH*CCH], g_wv_l[CCH*CCH];
__device__ __nv_bfloat16 g_cw1_h[CCH*KCONV], g_cw1_l[CCH*KCONV];
__device__ __nv_bfloat16 g_cw2_h[CCH*KCONV], g_cw2_l[CCH*KCONV];
__device__ __nv_bfloat16 g_qw1_h[CH4*CCH], g_qw1_l[CH4*CCH];
__device__ __nv_bfloat16 g_qw2_h[CH4*CCH], g_qw2_l[CH4*CCH];
__device__ __nv_bfloat16 g_ew1_h[CCH*CH4], g_ew1_l[CCH*CH4];
__device__ __nv_bfloat16 g_ew2_h[CCH*CH4], g_ew2_l[CCH*CH4];
__device__ __nv_bfloat16 g_x_h[(size_t)NB*CCH*NPIX], g_x_l[(size_t)NB*CCH*NPIX];
__device__ __nv_bfloat16 g_qT_h[NB*NPIX*CR], g_qT_l[NB*NPIX*CR];
__device__ __nv_bfloat16 g_k_h[NB*CR*NPIX],  g_k_l[NB*CR*NPIX];
__device__ __nv_bfloat16 g_v_h[NB*CCH*NPIX], g_v_l[NB*CCH*NPIX];
__device__ __nv_bfloat16 g_at_h[(size_t)NB*NPIX*NPIX], g_at_l[(size_t)NB*NPIX*NPIX];
__device__ __nv_bfloat16 g_ci_h[(size_t)NB*KCONV*NPIX], g_ci_l[(size_t)NB*KCONV*NPIX];
__device__ __nv_bfloat16 g_b0_h[NB*CCH*NPIX], g_b0_l[NB*CCH*NPIX];
__device__ __nv_bfloat16 g_o1_h[NB*CCH*NPIX], g_o1_l[NB*CCH*NPIX];
__device__ __nv_bfloat16 g_qc_h[NB*CH4*NPIX], g_qc_l[NB*CH4*NPIX];
__device__ __nv_bfloat16 g_e2_h[NB*CH4*CCH],  g_e2_l[NB*CH4*CCH];
__device__ __nv_bfloat16 g_ac_h[NB*CCH*CCH],  g_ac_l[NB*CCH*CCH];
__device__ __nv_bfloat16 g_vc_h[NB*CCH*NPIX], g_vc_l[NB*CCH*NPIX];

// ---------------- reductions ----------------
__device__ __forceinline__ float warpMax(float v){
  #pragma unroll
  for (int o=16;o;o>>=1) v = fmaxf(v, __shfl_xor_sync(0xffffffffu, v, o));
  return v;
}
__device__ __forceinline__ float warpMin(float v){
  #pragma unroll
  for (int o=16;o;o>>=1) v = fminf(v, __shfl_xor_sync(0xffffffffu, v, o));
  return v;
}
__device__ __forceinline__ float warpSum(float v){
  #pragma unroll
  for (int o=16;o;o>>=1) v += __shfl_xor_sync(0xffffffffu, v, o);
  return v;
}
__device__ float blockMax(float v, float* sh){
  v = warpMax(v);
  if ((threadIdx.x & 31) == 0) sh[threadIdx.x >> 5] = v;
  __syncthreads();
  if (threadIdx.x < 32){
    float t = (threadIdx.x < (blockDim.x>>5)) ? sh[threadIdx.x] : -3.4e38f;
    t = warpMax(t);
    if (threadIdx.x == 0) sh[0] = t;
  }
  __syncthreads();
  float r = sh[0]; __syncthreads(); return r;
}
__device__ float blockMin(float v, float* sh){
  v = warpMin(v);
  if ((threadIdx.x & 31) == 0) sh[threadIdx.x >> 5] = v;
  __syncthreads();
  if (threadIdx.x < 32){
    float t = (threadIdx.x < (blockDim.x>>5)) ? sh[threadIdx.x] : 3.4e38f;
    t = warpMin(t);
    if (threadIdx.x == 0) sh[0] = t;
  }
  __syncthreads();
  float r = sh[0]; __syncthreads(); return r;
}
__device__ float blockSum(float v, float* sh){
  v = warpSum(v);
  if ((threadIdx.x & 31) == 0) sh[threadIdx.x >> 5] = v;
  __syncthreads();
  if (threadIdx.x < 32){
    float t = (threadIdx.x < (blockDim.x>>5)) ? sh[threadIdx.x] : 0.f;
    t = warpSum(t);
    if (threadIdx.x == 0) sh[0] = t;
  }
  __syncthreads();
  float r = sh[0]; __syncthreads(); return r;
}

// ---------------- helpers ----------------
__device__ __forceinline__ void mma_bf16(float* c, const uint32_t* a, const uint32_t* b){
  asm volatile("mma.sync.aligned.m16n8k16.row.col.f32.bf16.bf16.f32 "
    "{%0,%1,%2,%3}, {%4,%5,%6,%7}, {%8,%9}, {%0,%1,%2,%3};\n"
    : "+f"(c[0]), "+f"(c[1]), "+f"(c[2]), "+f"(c[3])
    : "r"(a[0]), "r"(a[1]), "r"(a[2]), "r"(a[3]), "r"(b[0]), "r"(b[1]));
}
__device__ __forceinline__ void ldsm_x4(uint32_t* r, uint32_t saddr){
  asm volatile("ldmatrix.sync.aligned.m8n8.x4.shared.b16 {%0,%1,%2,%3}, [%4];"
    : "=r"(r[0]), "=r"(r[1]), "=r"(r[2]), "=r"(r[3]) : "r"(saddr));
}
__device__ __forceinline__ void ldsm_x4t(uint32_t* r, uint32_t saddr){
  asm volatile("ldmatrix.sync.aligned.m8n8.x4.trans.shared.b16 {%0,%1,%2,%3}, [%4];"
    : "=r"(r[0]), "=r"(r[1]), "=r"(r[2]), "=r"(r[3]) : "r"(saddr));
}
__device__ __forceinline__ void cpasync16(void* dst, const void* src, int szbytes){
  uint32_t d = (uint32_t)__cvta_generic_to_shared(dst);
  asm volatile("cp.async.cg.shared.global [%0], [%1], 16, %2;\n"
               :: "r"(d), "l"(src), "r"(szbytes));
}
__device__ __forceinline__ void cp_commit(){ asm volatile("cp.async.commit_group;\n"); }
__device__ __forceinline__ void cp_wait1(){ asm volatile("cp.async.wait_group 1;\n"); }

__device__ __forceinline__ void bsplit(float v, __nv_bfloat16& h, __nv_bfloat16& l){
  h = __float2bfloat16(v);
  l = __float2bfloat16(v - __bfloat162float(h));
}
__device__ __forceinline__ uint32_t bpack(__nv_bfloat16 a, __nv_bfloat16 b){
  return (uint32_t)__bfloat16_as_ushort(a) | ((uint32_t)__bfloat16_as_ushort(b) << 16);
}

// ---------------- BF16x3 tensor-core GEMM (ldmatrix fragments) ----------------
// A bf16 [M][K] row-major (hi/lo). BI: 0 = B bf16 [K][N] k-major; 2 = B bf16 [N][K] (NT).
// EPI: 0 fp32(+opt bias p0); 2 fp32 gamma*acc+res; 3 relu(acc*p0+p1)->fp32+split;
//      4 relu->split; 5 (+opt bias)->split; 6 (+bias)->transposed split (ldT).
// Block tile 128x128x16; N%128==0, K%16==0, K>=32.
template<int BI, int EPI>
__global__ void __launch_bounds__(256,2) gemm3_kernel(
    const __nv_bfloat16* __restrict__ Ah, const __nv_bfloat16* __restrict__ Al, long sA,
    const __nv_bfloat16* __restrict__ Bh, const __nv_bfloat16* __restrict__ Bl, long sB,
    float* __restrict__ Cm, long sC,
    __nv_bfloat16* __restrict__ Dh, __nv_bfloat16* __restrict__ Dl, long sD,
    int M, int N, int K,
    const float* __restrict__ p0, const float* __restrict__ p1,
    const float* __restrict__ res, long sRes,
    const float* __restrict__ gamma, int ldT)
{
  constexpr int AROW = 24;          // bf16 stride (16 data + pad)
  constexpr int ABF  = 128*AROW;    // bf16 per A array per stage
  constexpr int ABYTES = 2*ABF*2;   // hi+lo
  constexpr int BBF  = (BI==2) ? ABF : 16*136;
  constexpr int BBYTES = 2*BBF*2;
  constexpr int STAGEB = ABYTES + BBYTES;

  extern __shared__ char smc[];
  const uint32_t smem0 = (uint32_t)__cvta_generic_to_shared(smc);

  const int bz = blockIdx.z;
  Ah += (long)bz * sA;  Al += (long)bz * sA;
  Bh += (long)bz * sB;  Bl += (long)bz * sB;
  if (Cm) Cm += (long)bz * sC;
  if (EPI >= 3){ Dh += (long)bz * sD; Dl += (long)bz * sD; }
  if (EPI == 2) res += (long)bz * sRes;

  const int tid  = threadIdx.x;
  const int warp = tid >> 5;
  const int lane = tid & 31;
  const int g    = lane >> 2;
  const int ct   = lane & 3;
  const int warpM = warp >> 2;
  const int warpN = warp & 3;
  const int m0 = blockIdx.y * 128;
  const int n0 = blockIdx.x * 128;

  // ldmatrix per-lane byte offsets
  const int lo8 = lane & 7, b3 = (lane>>3)&1, b4 = (lane>>4)&1;
  const uint32_t aoff  = ((warpM*64 + lo8 + b3*8)*AROW + b4*8)*2;
  const uint32_t boff2 = ((warpN*32 + lo8 + b4*8)*AROW + b3*8)*2;          // BI2
  const uint32_t boff0 = ((lo8 + b3*8)*136 + warpN*32 + b4*8)*2;           // BI0

  float acc[4][4][4];
  #pragma unroll
  for (int i=0;i<4;i++)
    #pragma unroll
    for (int j=0;j<4;j++)
      #pragma unroll
      for (int c=0;c<4;c++) acc[i][j][c]=0.f;

  auto loadT = [&](int s, int k0){
    char* st = smc + s*STAGEB;
    __nv_bfloat16* Ahs = (__nv_bfloat16*)st;
    #pragma unroll
    for (int c = tid; c < 512; c += 256){
      const __nv_bfloat16* base = (c < 256) ? Ah : Al;
      __nv_bfloat16* dst = Ahs + ((c < 256) ? 0 : ABF);
      int e = c & 255, row = e >> 1, half = e & 1;
      int gm = m0 + row;
      int sz = (gm < M) ? 16 : 0; if (gm >= M) gm = 0;
      cpasync16(dst + row*AROW + half*8, base + (long)gm*K + k0 + half*8, sz);
    }
    __nv_bfloat16* Bs = (__nv_bfloat16*)(st + ABYTES);
    if (BI == 2){
      #pragma unroll
      for (int c = tid; c < 512; c += 256){
        const __nv_bfloat16* base = (c < 256) ? Bh : Bl;
        __nv_bfloat16* dst = Bs + ((c < 256) ? 0 : ABF);
        int e = c & 255, row = e >> 1, half = e & 1;
        cpasync16(dst + row*AROW + half*8, base + (long)(n0+row)*K + k0 + half*8, 16);
      }
    } else {
      #pragma unroll
      for (int c = tid; c < 512; c += 256){
        const __nv_bfloat16* base = (c < 256) ? Bh : Bl;
        __nv_bfloat16* dst = Bs + ((c < 256) ? 0 : 16*136);
        int e = c & 255, row = e >> 4, ch = e & 15;
        cpasync16(dst + row*136 + ch*8, base + (long)(k0+row)*N + n0 + ch*8, 16);
      }
    }
  };

  const int T = K/16;
  loadT(0, 0);  cp_commit();
  loadT(1, 16); cp_commit();

  for (int i = 0; i < T; i++){
    cp_wait1();
    __syncthreads();
    if (i + 2 < T) loadT((i+2)%3, (i+2)*16);
    cp_commit();

    const uint32_t stb = smem0 + (uint32_t)((i%3)*STAGEB);
    const uint32_t aH = stb + aoff;
    const uint32_t aL = stb + ABF*2 + aoff;
    const uint32_t bb = stb + ABYTES;

    uint32_t ah[4][4], al[4][4], bhf[8], blf[8];
    #pragma unroll
    for (int mi=0; mi<4; mi++){
      ldsm_x4(ah[mi], aH + mi*(16*AROW*2));
      ldsm_x4(al[mi], aL + mi*(16*AROW*2));
    }
    if (BI == 2){
      const uint32_t bH = bb + boff2, bL = bb + ABF*2 + boff2;
      ldsm_x4(bhf,   bH);
      ldsm_x4(bhf+4, bH + 16*AROW*2);
      ldsm_x4(blf,   bL);
      ldsm_x4(blf+4, bL + 16*AROW*2);
    } else {
      const uint32_t bH = bb + boff0, bL = bb + 16*136*2 + boff0;
      ldsm_x4t(bhf,   bH);
      ldsm_x4t(bhf+4, bH + 16*2);
      ldsm_x4t(blf,   bL);
      ldsm_x4t(blf+4, bL + 16*2);
    }
    #pragma unroll
    for (int mi=0; mi<4; mi++)
      #pragma unroll
      for (int nj=0; nj<4; nj++){
        mma_bf16(acc[mi][nj], ah[mi], bhf + nj*2);
        mma_bf16(acc[mi][nj], ah[mi], blf + nj*2);
        mma_bf16(acc[mi][nj], al[mi], bhf + nj*2);
      }
  }

  __syncthreads();

  // ---- epilogue
  #pragma unroll
  for (int mi=0; mi<4; mi++){
    int rr[2] = { m0 + warpM*64 + mi*16 + g, m0 + warpM*64 + mi*16 + g + 8 };
    float sc[2] = {0.f,0.f}, of[2] = {0.f,0.f};
    #pragma unroll
    for (int h=0; h<2; h++){
      if (rr[h] < M){
        if (EPI == 3 || EPI == 4){ sc[h] = p0[rr[h]]; of[h] = p1[rr[h]]; }
        else if (EPI == 0 || EPI == 5 || EPI == 6){ if (p0) of[h] = p0[rr[h]]; }
      }
    }
    #pragma unroll
    for (int nj=0; nj<4; nj++){
      int n = n0 + warpN*32 + nj*8 + 2*ct;
      #pragma unroll
      for (int h=0; h<2; h++){
        int r = rr[h];
        if (r >= M) continue;
        float wx = acc[mi][nj][2*h], wy = acc[mi][nj][2*h+1];
        if (EPI == 0){ wx += of[h]; wy += of[h]; }
        else if (EPI == 2){
          float2 rv = *(const float2*)&res[(long)r*N + n];
          wx = gamma[0]*wx + rv.x; wy = gamma[0]*wy + rv.y;
        } else if (EPI == 3 || EPI == 4){
          wx = fmaxf(wx*sc[h] + of[h], 0.f);
          wy = fmaxf(wy*sc[h] + of[h], 0.f);
        } else { wx += of[h]; wy += of[h]; }
        if (EPI == 0 || EPI == 2 || EPI == 3){
          float2 w; w.x = wx; w.y = wy;
          *(float2*)&Cm[(long)r*N + n] = w;
        }
        if (EPI >= 3){
          __nv_bfloat16 hx, lx, hy, ly;
          bsplit(wx, hx, lx); bsplit(wy, hy, ly);
          if (EPI == 6){
            Dh[(long)n*ldT + r] = hx;       Dl[(long)n*ldT + r] = lx;
            Dh[(long)(n+1)*ldT + r] = hy;   Dl[(long)(n+1)*ldT + r] = ly;
          } else {
            *(uint32_t*)&Dh[(long)r*N + n] = bpack(hx, hy);
            *(uint32_t*)&Dl[(long)r*N + n] = bpack(lx, ly);
          }
        }
      }
    }
  }
}

// ---------------- softmax row stats ----------------
__global__ __launch_bounds__(256) void softmax_stats_kernel(
    const float* __restrict__ E, const float* __restrict__ M1,
    const float* __restrict__ M2, float* __restrict__ st)
{
  __shared__ float sh[32];
  const int R = NB*NPIX;
  int row = blockIdx.x;
  int mr  = row % NPIX;
  const float* e  = E  + (long)row * NPIX;
  const float* m1 = M1 + (long)mr  * NPIX;
  const float* m2 = M2 + (long)mr  * NPIX;
  int tid = threadIdx.x;
  float ev[9], w1[9], w2[9];
  float mx0=-3.4e38f, mx1=-3.4e38f, mx2=-3.4e38f;
  #pragma unroll
  for (int i=0;i<9;i++){
    int n = tid + i*256;
    ev[i]=e[n]; w1[i]=m1[n]; w2[i]=m2[n];
    mx0 = fmaxf(mx0, ev[i]);
    if (w1[i] > 0.f) mx1 = fmaxf(mx1, ev[i]);
    if (w2[i] > 0.f) mx2 = fmaxf(mx2, ev[i]);
  }
  mx0 = blockMax(mx0, sh); mx1 = blockMax(mx1, sh); mx2 = blockMax(mx2, sh);
  float s0=0.f, s1=0.f, s2=0.f;
  #pragma unroll
  for (int i=0;i<9;i++){
    s0 += __expf(ev[i]-mx0);
    s1 += (w1[i] > 0.f) ? __expf(ev[i]-mx1) : 0.f;
    s2 += (w2[i] > 0.f) ? __expf(ev[i]-mx2) : 0.f;
  }
  s0 = blockSum(s0, sh); s1 = blockSum(s1, sh); s2 = blockSum(s2, sh);
  if (tid == 0){
    st[row]       = mx0;  st[R   + row] = 1.f/s0;
    st[2*R + row] = mx1;  st[3*R + row] = 1.f/s1;
    st[4*R + row] = mx2;  st[5*R + row] = 1.f/s2;
  }
}

// ---------------- attention matrix -> bf16 split ----------------
__global__ __launch_bounds__(256) void attn_mat_kernel(
    const float* __restrict__ E, const float* __restrict__ mask,
    const float* __restrict__ st, __nv_bfloat16* __restrict__ Ahd,
    __nv_bfloat16* __restrict__ Ald, long total4)
{
  const long NN2 = (long)NPIX*NPIX;
  long i4 = (long)blockIdx.x * 256 + threadIdx.x;
  if (i4 >= total4) return;
  long idx = i4 * 4;
  int  b   = (int)(idx / NN2);
  long rem = idx - (long)b * NN2;
  int  mr  = (int)(rem / NPIX);
  float mx   = st[b*NPIX + mr];
  float rinv = st[NB*NPIX + b*NPIX + mr];
  float4 e = *(const float4*)&E[idx];
  float4 a;
  a.x = __expf(e.x-mx)*rinv; a.y = __expf(e.y-mx)*rinv;
  a.z = __expf(e.z-mx)*rinv; a.w = __expf(e.w-mx)*rinv;
  if (mask){
    float4 mk = *(const float4*)&mask[rem];
    if (mk.x <= 0.f) a.x = 0.f;
    if (mk.y <= 0.f) a.y = 0.f;
    if (mk.z <= 0.f) a.z = 0.f;
    if (mk.w <= 0.f) a.w = 0.f;
  }
  __nv_bfloat16 h0,l0,h1,l1,h2,l2,h3,l3;
  bsplit(a.x,h0,l0); bsplit(a.y,h1,l1); bsplit(a.z,h2,l2); bsplit(a.w,h3,l3);
  *(uint32_t*)&Ahd[idx]   = bpack(h0,h1);
  *(uint32_t*)&Ahd[idx+2] = bpack(h2,h3);
  *(uint32_t*)&Ald[idx]   = bpack(l0,l1);
  *(uint32_t*)&Ald[idx+2] = bpack(l2,l3);
}

// ---------------- chl softmax -> bf16 split ----------------
__global__ __launch_bounds__(256) void chl_softmax_kernel(
    const float* __restrict__ E, __nv_bfloat16* __restrict__ Ahd,
    __nv_bfloat16* __restrict__ Ald)
{
  __shared__ float sh[32];
  long row = blockIdx.x;
  const float* e = E + row * CCH;
  int tid = threadIdx.x;
  float v0 = e[tid], v1 = e[tid+256];
  float mn = blockMin(fminf(v0, v1), sh);
  float t0 = __expf(mn - v0), t1 = __expf(mn - v1);
  float s = blockSum(t0 + t1, sh);
  float rinv = 1.f/s;
  __nv_bfloat16 h,l;
  bsplit(t0*rinv, h, l); Ahd[row*CCH + tid]     = h; Ald[row*CCH + tid]     = l;
  bsplit(t1*rinv, h, l); Ahd[row*CCH + tid+256] = h; Ald[row*CCH + tid+256] = l;
}

// ---------------- im2col -> k-major bf16 split [KCONV][NPIX] ----------------
__global__ __launch_bounds__(256) void im2col_kernel(const float* __restrict__ X,
    __nv_bfloat16* __restrict__ Ch, __nv_bfloat16* __restrict__ Cl)
{
  const long total = (long)NB*KCONV*(NPIX/2);
  long w = (long)blockIdx.x * 256 + threadIdx.x;
  if (w >= total) return;
  int n2 = (int)(w % (NPIX/2));
  long t = w / (NPIX/2);
  int k  = (int)(t % KCONV);
  int b  = (int)(t / KCONV);
  int ic = k/9, kk = k - ic*9;
  int ky = kk/3, kx = kk - ky*3;
  const float* xs = X + ((long)(b*CCH + ic))*NPIX;
  float v[2];
  #pragma unroll
  for (int u=0; u<2; u++){
    int n = 2*n2 + u;
    int y = n/HW + ky - 1, x = n - (n/HW)*HW + kx - 1;
    v[u] = (y >= 0 && y < HW && x >= 0 && x < HW) ? xs[y*HW + x] : 0.f;
  }
  __nv_bfloat16 h0,l0,h1,l1;
  bsplit(v[0],h0,l0); bsplit(v[1],h1,l1);
  long o = ((long)(b*KCONV + k))*NPIX + 2*n2;
  *(uint32_t*)&Ch[o] = bpack(h0,h1);
  *(uint32_t*)&Cl[o] = bpack(l0,l1);
}

// ---------------- prepass: plain split ----------------
__global__ __launch_bounds__(256) void split_nat_kernel(const float* __restrict__ X,
    __nv_bfloat16* __restrict__ H, __nv_bfloat16* __restrict__ L, long total)
{
  for (long i = (long)blockIdx.x*256 + threadIdx.x; i < total; i += (long)gridDim.x*256){
    __nv_bfloat16 h,l; bsplit(X[i], h, l); H[i] = h; L[i] = l;
  }
}

// ---------------- host ----------------
template<int BI, int EPI>
static void rg(const __nv_bfloat16* Ah, const __nv_bfloat16* Al, long sA,
               const __nv_bfloat16* Bh, const __nv_bfloat16* Bl, long sB,
               float* C, long sC,
               __nv_bfloat16* Dh, __nv_bfloat16* Dl, long sD,
               int M, int N, int K,
               const float* p0, const float* p1,
               const float* res, long sRes, const float* gamma, int ldT)
{
  constexpr int ABYTES = 2*128*24*2;
  constexpr int BBYTES = (BI==2) ? ABYTES : 2*16*136*2;
  constexpr int SMEM = 3*(ABYTES + BBYTES);
  cudaFuncSetAttribute(gemm3_kernel<BI,EPI>,
                       cudaFuncAttributeMaxDynamicSharedMemorySize, SMEM);
  dim3 grid(N/128, (M+127)/128, NB);
  gemm3_kernel<BI,EPI><<<grid, 256, SMEM>>>(Ah, Al, sA, Bh, Bl, sB, C, sC,
                                            Dh, Dl, sD, M, N, K, p0, p1, res, sRes, gamma, ldT);
}

template<typename T>
static T* sym(const void* s){ void* p = nullptr; cudaGetSymbolAddress(&p, s); return (T*)p; }

extern "C" void kernel_launch(void* const* d_in, const int* in_sizes, int n_in,
                              void* d_out, int out_size)
{
  const float* x       = (const float*)d_in[0];
  const float* wq      = (const float*)d_in[1];
  const float* bq      = (const float*)d_in[2];
  const float* wk      = (const float*)d_in[3];
  const float* bk      = (const float*)d_in[4];
  const float* wv0     = (const float*)d_in[5];
  const float* bv0     = (const float*)d_in[6];
  const float* conv1_w = (const float*)d_in[7];
  const float* conv1_s = (const float*)d_in[8];
  const float* conv1_b = (const float*)d_in[9];
  const float* conv2_w = (const float*)d_in[10];
  const float* conv2_s = (const float*)d_in[11];
  const float* conv2_b = (const float*)d_in[12];
  const float* gamma   = (const float*)d_in[13];
  const float* gamma1  = (const float*)d_in[14];
  const float* gamma2  = (const float*)d_in[15];
  const float* c1_qw   = (const float*)d_in[16];
  const float* c1_qs   = (const float*)d_in[17];
  const float* c1_qb   = (const float*)d_in[18];
  const float* c1_ew   = (const float*)d_in[19];
  const float* c1_eb   = (const float*)d_in[20];
  const float* c2_qw   = (const float*)d_in[21];
  const float* c2_qs   = (const float*)d_in[22];
  const float* c2_qb   = (const float*)d_in[23];
  const float* c2_ew   = (const float*)d_in[24];
  const float* c2_eb   = (const float*)d_in[25];
  const float* mask1   = (const float*)d_in[26];
  const float* mask2   = (const float*)d_in[27];

  typedef __nv_bfloat16 bf;
  float* E    = sym<float>(g_E);    float* st   = sym<float>(g_stats);
  float* buf0 = sym<float>(g_buf0); float* buf1 = sym<float>(g_buf1);
  float* out1 = sym<float>(g_out1); float* expd = sym<float>(g_expd);
  bf *wq_h = sym<bf>(g_wq_h), *wq_l = sym<bf>(g_wq_l);
  bf *wk_h = sym<bf>(g_wk_h), *wk_l = sym<bf>(g_wk_l);
  bf *wv_h = sym<bf>(g_wv_h), *wv_l = sym<bf>(g_wv_l);
  bf *cw1_h = sym<bf>(g_cw1_h), *cw1_l = sym<bf>(g_cw1_l);
  bf *cw2_h = sym<bf>(g_cw2_h), *cw2_l = sym<bf>(g_cw2_l);
  bf *qw1_h = sym<bf>(g_qw1_h), *qw1_l = sym<bf>(g_qw1_l);
  bf *qw2_h = sym<bf>(g_qw2_h), *qw2_l = sym<bf>(g_qw2_l);
  bf *ew1_h = sym<bf>(g_ew1_h), *ew1_l = sym<bf>(g_ew1_l);
  bf *ew2_h = sym<bf>(g_ew2_h), *ew2_l = sym<bf>(g_ew2_l);
  bf *x_h = sym<bf>(g_x_h), *x_l = sym<bf>(g_x_l);
  bf *qT_h = sym<bf>(g_qT_h), *qT_l = sym<bf>(g_qT_l);
  bf *k_h  = sym<bf>(g_k_h),  *k_l  = sym<bf>(g_k_l);
  bf *v_h  = sym<bf>(g_v_h),  *v_l  = sym<bf>(g_v_l);
  bf *at_h = sym<bf>(g_at_h), *at_l = sym<bf>(g_at_l);
  bf *ci_h = sym<bf>(g_ci_h), *ci_l = sym<bf>(g_ci_l);
  bf *b0_h = sym<bf>(g_b0_h), *b0_l = sym<bf>(g_b0_l);
  bf *o1_h = sym<bf>(g_o1_h), *o1_l = sym<bf>(g_o1_l);
  bf *qc_h = sym<bf>(g_qc_h), *qc_l = sym<bf>(g_qc_l);
  bf *e2_h = sym<bf>(g_e2_h), *e2_l = sym<bf>(g_e2_l);
  bf *ac_h = sym<bf>(g_ac_h), *ac_l = sym<bf>(g_ac_l);
  bf *vc_h = sym<bf>(g_vc_h), *vc_l = sym<bf>(g_vc_l);
  float* out = (float*)d_out;

  const long sX  = (long)CCH*NPIX;
  const long sE  = (long)NPIX*NPIX;
  const long sCI = (long)KCONV*NPIX;
  const long sQT = (long)NPIX*CR;
  const long sK  = (long)CR*NPIX;
  const long sQC = (long)CH4*NPIX;
  const long sE2 = (long)CH4*CCH;
  const long sCC = (long)CCH*CCH;
  const int  R   = NB*NPIX;
  const long total4 = (long)NB*NPIX*NPIX/4;
  const int  amg = (int)((total4 + 255)/256);
  auto gsz = [](long t){ return (int)((t + 255)/256); };

  // ---- prepass splits ----
  split_nat_kernel<<<gsz(CR*CCH),256>>>(wq, wq_h, wq_l, CR*CCH);
  split_nat_kernel<<<gsz(CR*CCH),256>>>(wk, wk_h, wk_l, CR*CCH);
  split_nat_kernel<<<gsz(CCH*CCH),256>>>(wv0, wv_h, wv_l, CCH*CCH);
  split_nat_kernel<<<gsz((long)CCH*KCONV),256>>>(conv1_w, cw1_h, cw1_l, (long)CCH*KCONV);
  split_nat_kernel<<<gsz((long)CCH*KCONV),256>>>(conv2_w, cw2_h, cw2_l, (long)CCH*KCONV);
  split_nat_kernel<<<gsz(CH4*CCH),256>>>(c1_qw, qw1_h, qw1_l, CH4*CCH);
  split_nat_kernel<<<gsz(CH4*CCH),256>>>(c2_qw, qw2_h, qw2_l, CH4*CCH);
  split_nat_kernel<<<gsz(CCH*CH4),256>>>(c1_ew, ew1_h, ew1_l, CCH*CH4);
  split_nat_kernel<<<gsz(CCH*CH4),256>>>(c2_ew, ew2_h, ew2_l, CCH*CH4);
  split_nat_kernel<<<gsz((long)NB*sX),256>>>(x, x_h, x_l, (long)NB*sX);

  // ---- Q (transposed split), K, V ----
  rg<0,6>(wq_h, wq_l, 0, x_h, x_l, sX, nullptr,0, qT_h, qT_l, sQT,
          CR, NPIX, CCH, bq, nullptr, nullptr,0, nullptr, CR);
  rg<0,5>(wk_h, wk_l, 0, x_h, x_l, sX, nullptr,0, k_h, k_l, sK,
          CR, NPIX, CCH, bk, nullptr, nullptr,0, nullptr, 0);
  rg<0,5>(wv_h, wv_l, 0, x_h, x_l, sX, nullptr,0, v_h, v_l, sX,
          CCH, NPIX, CCH, bv0, nullptr, nullptr,0, nullptr, 0);

  // ---- energy = qT * k ----
  rg<0,0>(qT_h, qT_l, sQT, k_h, k_l, sK, E, sE, nullptr,nullptr,0,
          NPIX, NPIX, CR, nullptr, nullptr, nullptr,0, nullptr, 0);

  softmax_stats_kernel<<<R, 256>>>(E, mask1, mask2, st);

  // ---- pass 0 ----
  attn_mat_kernel<<<amg, 256>>>(E, nullptr, st, at_h, at_l, total4);
  rg<2,2>(v_h, v_l, sX, at_h, at_l, sE, buf1, sX, nullptr,nullptr,0,
          CCH, NPIX, NPIX, nullptr, nullptr, (const float*)x, sX, gamma, 0);
  im2col_kernel<<<gsz((long)NB*KCONV*(NPIX/2)), 256>>>(buf1, ci_h, ci_l);
  rg<0,3>(cw1_h, cw1_l, 0, ci_h, ci_l, sCI, buf0, sX, b0_h, b0_l, sX,
          CCH, NPIX, KCONV, conv1_s, conv1_b, nullptr,0, nullptr, 0);

  // chl #1
  rg<0,4>(qw1_h, qw1_l, 0, b0_h, b0_l, sX, nullptr,0, qc_h, qc_l, sQC,
          CH4, NPIX, CCH, c1_qs, c1_qb, nullptr,0, nullptr, 0);
  rg<2,5>(qc_h, qc_l, sQC, b0_h, b0_l, sX, nullptr,0, e2_h, e2_l, sE2,
          CH4, CCH, NPIX, nullptr, nullptr, nullptr,0, nullptr, 0);
  rg<0,0>(ew1_h, ew1_l, 0, e2_h, e2_l, sE2, expd, sCC, nullptr,nullptr,0,
          CCH, CCH, CH4, c1_eb, nullptr, nullptr,0, nullptr, 0);
  chl_softmax_kernel<<<NB*CCH, 256>>>(expd, ac_h, ac_l);
  rg<0,5>(ac_h, ac_l, sCC, b0_h, b0_l, sX, nullptr,0, vc_h, vc_l, sX,
          CCH, NPIX, CCH, nullptr, nullptr, nullptr,0, nullptr, 0);

  // ---- pass 1 ----
  attn_mat_kernel<<<amg, 256>>>(E, mask1, st + 2*R, at_h, at_l, total4);
  rg<2,2>(vc_h, vc_l, sX, at_h, at_l, sE, buf1, sX, nullptr,nullptr,0,
          CCH, NPIX, NPIX, nullptr, nullptr, buf0, sX, gamma1, 0);
  im2col_kernel<<<gsz((long)NB*KCONV*(NPIX/2)), 256>>>(buf1, ci_h, ci_l);
  rg<0,3>(cw2_h, cw2_l, 0, ci_h, ci_l, sCI, out1, sX, o1_h, o1_l, sX,
          CCH, NPIX, KCONV, conv2_s, conv2_b, nullptr,0, nullptr, 0);

  // chl #2
  rg<0,4>(qw2_h, qw2_l, 0, o1_h, o1_l, sX, nullptr,0, qc_h, qc_l, sQC,
          CH4, NPIX, CCH, c2_qs, c2_qb, nullptr,0, nullptr, 0);
  rg<2,5>(qc_h, qc_l, sQC, o1_h, o1_l, sX, nullptr,0, e2_h, e2_l, sE2,
          CH4, CCH, NPIX, nullptr, nullptr, nullptr,0, nullptr, 0);
  rg<0,0>(ew2_h, ew2_l, 0, e2_h, e2_l, sE2, expd, sCC, nullptr,nullptr,0,
          CCH, CCH, CH4, c2_eb, nullptr, nullptr,0, nullptr, 0);
  chl_softmax_kernel<<<NB*CCH, 256>>>(expd, ac_h, ac_l);
  rg<0,5>(ac_h, ac_l, sCC, o1_h, o1_l, sX, nullptr,0, vc_h, vc_l, sX,
          CCH, NPIX, CCH, nullptr, nullptr, nullptr,0, nullptr, 0);

  // ---- pass 2 -> out ----
  attn_mat_kernel<<<amg, 256>>>(E, mask2, st + 4*R, at_h, at_l, total4);
  rg<2,2>(vc_h, vc_l, sX, at_h, at_l, sE, out, sX, nullptr,nullptr,0,
          CCH, NPIX, NPIX, nullptr, nullptr, out1, sX, gamma2, 0);

  (void)in_sizes; (void)n_in; (void)out_size;
}

// round 10
// speedup vs baseline: 1.1443x; 1.0441x over previous
#include <cuda_runtime.h>
#include <cuda_bf16.h>
#include <cstdint>

#define NB   4
#define CCH  512
#define NPIX 2304
#define CR   64
#define CH4  128
#define HW   48
#define KCONV 4608

// ---------------- fp32 scratch ----------------
__device__ float g_E[(size_t)NB*NPIX*NPIX];
__device__ float g_stats[6*NB*NPIX];
__device__ float g_buf0[NB*CCH*NPIX];
__device__ float g_buf1[NB*CCH*NPIX];
__device__ float g_out1[NB*CCH*NPIX];
__device__ float g_expd[NB*CCH*CCH];

// ---------------- bf16 split scratch ----------------
__device__ __nv_bfloat16 g_wq_h[CR*CCH],  g_wq_l[CR*CCH];
__device__ __nv_bfloat16 g_wk_h[CR*CCH],  g_wk_l[CR*CCH];
__device__ __nv_bfloat16 g_wv_h[CCH*CCH], g_wv_l[CCH*CCH];
__device__ __nv_bfloat16 g_cw1_h[CCH*KCONV], g_cw1_l[CCH*KCONV];
__device__ __nv_bfloat16 g_cw2_h[CCH*KCONV], g_cw2_l[CCH*KCONV];
__device__ __nv_bfloat16 g_qw1_h[CH4*CCH], g_qw1_l[CH4*CCH];
__device__ __nv_bfloat16 g_qw2_h[CH4*CCH], g_qw2_l[CH4*CCH];
__device__ __nv_bfloat16 g_ew1_h[CCH*CH4], g_ew1_l[CCH*CH4];
__device__ __nv_bfloat16 g_ew2_h[CCH*CH4], g_ew2_l[CCH*CH4];
__device__ __nv_bfloat16 g_x_h[(size_t)NB*CCH*NPIX], g_x_l[(size_t)NB*CCH*NPIX];
__device__ __nv_bfloat16 g_qT_h[NB*NPIX*CR], g_qT_l[NB*NPIX*CR];
__device__ __nv_bfloat16 g_k_h[NB*CR*NPIX],  g_k_l[NB*CR*NPIX];
__device__ __nv_bfloat16 g_v_h[NB*CCH*NPIX], g_v_l[NB*CCH*NPIX];
__device__ __nv_bfloat16 g_at_h[(size_t)NB*NPIX*NPIX], g_at_l[(size_t)NB*NPIX*NPIX];
__device__ __nv_bfloat16 g_ci_h[(size_t)NB*KCONV*NPIX], g_ci_l[(size_t)NB*KCONV*NPIX];
__device__ __nv_bfloat16 g_b0_h[NB*CCH*NPIX], g_b0_l[NB*CCH*NPIX];
__device__ __nv_bfloat16 g_o1_h[NB*CCH*NPIX], g_o1_l[NB*CCH*NPIX];
__device__ __nv_bfloat16 g_qc_h[NB*CH4*NPIX], g_qc_l[NB*CH4*NPIX];
__device__ __nv_bfloat16 g_e2_h[NB*CH4*CCH],  g_e2_l[NB*CH4*CCH];
__device__ __nv_bfloat16 g_ac_h[NB*CCH*CCH],  g_ac_l[NB*CCH*CCH];
__device__ __nv_bfloat16 g_vc_h[NB*CCH*NPIX], g_vc_l[NB*CCH*NPIX];

// ---------------- reductions ----------------
__device__ __forceinline__ float warpMax(float v){
  #pragma unroll
  for (int o=16;o;o>>=1) v = fmaxf(v, __shfl_xor_sync(0xffffffffu, v, o));
  return v;
}
__device__ __forceinline__ float warpMin(float v){
  #pragma unroll
  for (int o=16;o;o>>=1) v = fminf(v, __shfl_xor_sync(0xffffffffu, v, o));
  return v;
}
__device__ __forceinline__ float warpSum(float v){
  #pragma unroll
  for (int o=16;o;o>>=1) v += __shfl_xor_sync(0xffffffffu, v, o);
  return v;
}
__device__ float blockMax(float v, float* sh){
  v = warpMax(v);
  if ((threadIdx.x & 31) == 0) sh[threadIdx.x >> 5] = v;
  __syncthreads();
  if (threadIdx.x < 32){
    float t = (threadIdx.x < (blockDim.x>>5)) ? sh[threadIdx.x] : -3.4e38f;
    t = warpMax(t);
    if (threadIdx.x == 0) sh[0] = t;
  }
  __syncthreads();
  float r = sh[0]; __syncthreads(); return r;
}
__device__ float blockMin(float v, float* sh){
  v = warpMin(v);
  if ((threadIdx.x & 31) == 0) sh[threadIdx.x >> 5] = v;
  __syncthreads();
  if (threadIdx.x < 32){
    float t = (threadIdx.x < (blockDim.x>>5)) ? sh[threadIdx.x] : 3.4e38f;
    t = warpMin(t);
    if (threadIdx.x == 0) sh[0] = t;
  }
  __syncthreads();
  float r = sh[0]; __syncthreads(); return r;
}
__device__ float blockSum(float v, float* sh){
  v = warpSum(v);
  if ((threadIdx.x & 31) == 0) sh[threadIdx.x >> 5] = v;
  __syncthreads();
  if (threadIdx.x < 32){
    float t = (threadIdx.x < (blockDim.x>>5)) ? sh[threadIdx.x] : 0.f;
    t = warpSum(t);
    if (threadIdx.x == 0) sh[0] = t;
  }
  __syncthreads();
  float r = sh[0]; __syncthreads(); return r;
}

// ---------------- helpers ----------------
__device__ __forceinline__ void mma_bf16(float* c, const uint32_t* a, const uint32_t* b){
  asm volatile("mma.sync.aligned.m16n8k16.row.col.f32.bf16.bf16.f32 "
    "{%0,%1,%2,%3}, {%4,%5,%6,%7}, {%8,%9}, {%0,%1,%2,%3};\n"
    : "+f"(c[0]), "+f"(c[1]), "+f"(c[2]), "+f"(c[3])
    : "r"(a[0]), "r"(a[1]), "r"(a[2]), "r"(a[3]), "r"(b[0]), "r"(b[1]));
}
__device__ __forceinline__ void ldsm_x4(uint32_t* r, uint32_t saddr){
  asm volatile("ldmatrix.sync.aligned.m8n8.x4.shared.b16 {%0,%1,%2,%3}, [%4];"
    : "=r"(r[0]), "=r"(r[1]), "=r"(r[2]), "=r"(r[3]) : "r"(saddr));
}
__device__ __forceinline__ void ldsm_x4t(uint32_t* r, uint32_t saddr){
  asm volatile("ldmatrix.sync.aligned.m8n8.x4.trans.shared.b16 {%0,%1,%2,%3}, [%4];"
    : "=r"(r[0]), "=r"(r[1]), "=r"(r[2]), "=r"(r[3]) : "r"(saddr));
}
__device__ __forceinline__ void cpasync16(void* dst, const void* src, int szbytes){
  uint32_t d = (uint32_t)__cvta_generic_to_shared(dst);
  asm volatile("cp.async.cg.shared.global [%0], [%1], 16, %2;\n"
               :: "r"(d), "l"(src), "r"(szbytes));
}
__device__ __forceinline__ void cp_commit(){ asm volatile("cp.async.commit_group;\n"); }
__device__ __forceinline__ void cp_wait0(){ asm volatile("cp.async.wait_group 0;\n"); }
__device__ __forceinline__ void cp_wait1(){ asm volatile("cp.async.wait_group 1;\n"); }

__device__ __forceinline__ void bsplit(float v, __nv_bfloat16& h, __nv_bfloat16& l){
  h = __float2bfloat16(v);
  l = __float2bfloat16(v - __bfloat162float(h));
}
__device__ __forceinline__ uint32_t bpack(__nv_bfloat16 a, __nv_bfloat16 b){
  return (uint32_t)__bfloat16_as_ushort(a) | ((uint32_t)__bfloat16_as_ushort(b) << 16);
}

// ---------------- BF16x3 tensor-core GEMM (ldmatrix, K-tile 32, 2-stage) ----------------
// A bf16 [M][K] row-major (hi/lo). BI: 0 = B bf16 [K][N] k-major; 2 = B bf16 [N][K] (NT).
// EPI: 0 fp32(+opt bias p0); 2 fp32 gamma*acc+res; 3 relu(acc*p0+p1)->fp32+split;
//      4 relu->split; 5 (+opt bias)->split; 6 (+bias)->transposed split (ldT).
// Block tile 128x128x32; N%128==0, K%32==0.
template<int BI, int EPI>
__global__ void __launch_bounds__(256,2) gemm3_kernel(
    const __nv_bfloat16* __restrict__ Ah, const __nv_bfloat16* __restrict__ Al, long sA,
    const __nv_bfloat16* __restrict__ Bh, const __nv_bfloat16* __restrict__ Bl, long sB,
    float* __restrict__ Cm, long sC,
    __nv_bfloat16* __restrict__ Dh, __nv_bfloat16* __restrict__ Dl, long sD,
    int M, int N, int K,
    const float* __restrict__ p0, const float* __restrict__ p1,
    const float* __restrict__ res, long sRes,
    const float* __restrict__ gamma, int ldT)
{
  constexpr int AROW = 40;          // bf16 stride (32 data + 8 pad)
  constexpr int ABF  = 128*AROW;    // bf16 per A array per stage
  constexpr int ABYTES = 2*ABF*2;   // hi+lo
  constexpr int BBF  = (BI==2) ? ABF : 32*136;
  constexpr int BBYTES = 2*BBF*2;
  constexpr int STAGEB = ABYTES + BBYTES;

  extern __shared__ char smc[];
  const uint32_t smem0 = (uint32_t)__cvta_generic_to_shared(smc);

  const int bz = blockIdx.z;
  Ah += (long)bz * sA;  Al += (long)bz * sA;
  Bh += (long)bz * sB;  Bl += (long)bz * sB;
  if (Cm) Cm += (long)bz * sC;
  if (EPI >= 3){ Dh += (long)bz * sD; Dl += (long)bz * sD; }
  if (EPI == 2) res += (long)bz * sRes;

  const int tid  = threadIdx.x;
  const int warp = tid >> 5;
  const int lane = tid & 31;
  const int g    = lane >> 2;
  const int ct   = lane & 3;
  const int warpM = warp >> 2;
  const int warpN = warp & 3;
  const int m0 = blockIdx.y * 128;
  const int n0 = blockIdx.x * 128;

  // ldmatrix per-lane byte offsets (h = k16 half handled via +h*16 cols)
  const int lo8 = lane & 7, b3 = (lane>>3)&1, b4 = (lane>>4)&1;
  const uint32_t aoff  = ((warpM*64 + lo8 + b3*8)*AROW + b4*8)*2;
  const uint32_t boff2 = ((warpN*32 + lo8 + b4*8)*AROW + b3*8)*2;          // BI2
  const uint32_t boff0 = ((lo8 + b3*8)*136 + warpN*32 + b4*8)*2;           // BI0

  float acc[4][4][4];
  #pragma unroll
  for (int i=0;i<4;i++)
    #pragma unroll
    for (int j=0;j<4;j++)
      #pragma unroll
      for (int c=0;c<4;c++) acc[i][j][c]=0.f;

  auto loadT = [&](int s, int k0){
    char* st = smc + s*STAGEB;
    __nv_bfloat16* Ahs = (__nv_bfloat16*)st;
    #pragma unroll
    for (int c = tid; c < 1024; c += 256){
      const __nv_bfloat16* base = (c < 512) ? Ah : Al;
      __nv_bfloat16* dst = Ahs + ((c < 512) ? 0 : ABF);
      int e = c & 511, row = e >> 2, q = e & 3;
      int gm = m0 + row;
      int sz = (gm < M) ? 16 : 0; if (gm >= M) gm = 0;
      cpasync16(dst + row*AROW + q*8, base + (long)gm*K + k0 + q*8, sz);
    }
    __nv_bfloat16* Bs = (__nv_bfloat16*)(st + ABYTES);
    if (BI == 2){
      #pragma unroll
      for (int c = tid; c < 1024; c += 256){
        const __nv_bfloat16* base = (c < 512) ? Bh : Bl;
        __nv_bfloat16* dst = Bs + ((c < 512) ? 0 : ABF);
        int e = c & 511, row = e >> 2, q = e & 3;
        cpasync16(dst + row*AROW + q*8, base + (long)(n0+row)*K + k0 + q*8, 16);
      }
    } else {
      #pragma unroll
      for (int c = tid; c < 1024; c += 256){
        const __nv_bfloat16* base = (c < 512) ? Bh : Bl;
        __nv_bfloat16* dst = Bs + ((c < 512) ? 0 : 32*136);
        int e = c & 511, row = e >> 4, ch = e & 15;
        cpasync16(dst + row*136 + ch*8, base + (long)(k0+row)*N + n0 + ch*8, 16);
      }
    }
  };

  const int T = K/32;
  loadT(0, 0); cp_commit();

  for (int i = 0; i < T; i++){
    if (i + 1 < T){ loadT((i+1)&1, (i+1)*32); cp_commit(); cp_wait1(); }
    else          { cp_wait0(); }
    __syncthreads();

    const uint32_t stb = smem0 + (uint32_t)((i&1)*STAGEB);
    const uint32_t bb  = stb + ABYTES;

    #pragma unroll
    for (int h = 0; h < 2; h++){
      const uint32_t aH = stb + aoff + h*32;            // +16 cols = +32B
      const uint32_t aL = stb + ABF*2 + aoff + h*32;
      uint32_t ah[4][4], al[4][4], bhf[8], blf[8];
      #pragma unroll
      for (int mi=0; mi<4; mi++){
        ldsm_x4(ah[mi], aH + mi*(16*AROW*2));
        ldsm_x4(al[mi], aL + mi*(16*AROW*2));
      }
      if (BI == 2){
        const uint32_t bH = bb + boff2 + h*32;
        const uint32_t bL = bb + ABF*2 + boff2 + h*32;
        ldsm_x4(bhf,   bH);
        ldsm_x4(bhf+4, bH + 16*AROW*2);
        ldsm_x4(blf,   bL);
        ldsm_x4(blf+4, bL + 16*AROW*2);
      } else {
        const uint32_t bH = bb + boff0 + h*(16*136*2);
        const uint32_t bL = bb + 32*136*2 + boff0 + h*(16*136*2);
        ldsm_x4t(bhf,   bH);
        ldsm_x4t(bhf+4, bH + 16*2);
        ldsm_x4t(blf,   bL);
        ldsm_x4t(blf+4, bL + 16*2);
      }
      #pragma unroll
      for (int mi=0; mi<4; mi++)
        #pragma unroll
        for (int nj=0; nj<4; nj++){
          mma_bf16(acc[mi][nj], ah[mi], bhf + nj*2);
          mma_bf16(acc[mi][nj], ah[mi], blf + nj*2);
          mma_bf16(acc[mi][nj], al[mi], bhf + nj*2);
        }
    }
    __syncthreads();
  }

  // ---- epilogue
  #pragma unroll
  for (int mi=0; mi<4; mi++){
    int rr[2] = { m0 + warpM*64 + mi*16 + g, m0 + warpM*64 + mi*16 + g + 8 };
    float sc[2] = {0.f,0.f}, of[2] = {0.f,0.f};
    #pragma unroll
    for (int h=0; h<2; h++){
      if (rr[h] < M){
        if (EPI == 3 || EPI == 4){ sc[h] = p0[rr[h]]; of[h] = p1[rr[h]]; }
        else if (EPI == 0 || EPI == 5 || EPI == 6){ if (p0) of[h] = p0[rr[h]]; }
      }
    }
    #pragma unroll
    for (int nj=0; nj<4; nj++){
      int n = n0 + warpN*32 + nj*8 + 2*ct;
      #pragma unroll
      for (int h=0; h<2; h++){
        int r = rr[h];
        if (r >= M) continue;
        float wx = acc[mi][nj][2*h], wy = acc[mi][nj][2*h+1];
        if (EPI == 0){ wx += of[h]; wy += of[h]; }
        else if (EPI == 2){
          float2 rv = *(const float2*)&res[(long)r*N + n];
          wx = gamma[0]*wx + rv.x; wy = gamma[0]*wy + rv.y;
        } else if (EPI == 3 || EPI == 4){
          wx = fmaxf(wx*sc[h] + of[h], 0.f);
          wy = fmaxf(wy*sc[h] + of[h], 0.f);
        } else { wx += of[h]; wy += of[h]; }
        if (EPI == 0 || EPI == 2 || EPI == 3){
          float2 w; w.x = wx; w.y = wy;
          *(float2*)&Cm[(long)r*N + n] = w;
        }
        if (EPI >= 3){
          __nv_bfloat16 hx, lx, hy, ly;
          bsplit(wx, hx, lx); bsplit(wy, hy, ly);
          if (EPI == 6){
            Dh[(long)n*ldT + r] = hx;       Dl[(long)n*ldT + r] = lx;
            Dh[(long)(n+1)*ldT + r] = hy;   Dl[(long)(n+1)*ldT + r] = ly;
          } else {
            *(uint32_t*)&Dh[(long)r*N + n] = bpack(hx, hy);
            *(uint32_t*)&Dl[(long)r*N + n] = bpack(lx, ly);
          }
        }
      }
    }
  }
}

// ---------------- softmax row stats ----------------
__global__ __launch_bounds__(256) void softmax_stats_kernel(
    const float* __restrict__ E, const float* __restrict__ M1,
    const float* __restrict__ M2, float* __restrict__ st)
{
  __shared__ float sh[32];
  const int R = NB*NPIX;
  int row = blockIdx.x;
  int mr  = row % NPIX;
  const float* e  = E  + (long)row * NPIX;
  const float* m1 = M1 + (long)mr  * NPIX;
  const float* m2 = M2 + (long)mr  * NPIX;
  int tid = threadIdx.x;
  float ev[9], w1[9], w2[9];
  float mx0=-3.4e38f, mx1=-3.4e38f, mx2=-3.4e38f;
  #pragma unroll
  for (int i=0;i<9;i++){
    int n = tid + i*256;
    ev[i]=e[n]; w1[i]=m1[n]; w2[i]=m2[n];
    mx0 = fmaxf(mx0, ev[i]);
    if (w1[i] > 0.f) mx1 = fmaxf(mx1, ev[i]);
    if (w2[i] > 0.f) mx2 = fmaxf(mx2, ev[i]);
  }
  mx0 = blockMax(mx0, sh); mx1 = blockMax(mx1, sh); mx2 = blockMax(mx2, sh);
  float s0=0.f, s1=0.f, s2=0.f;
  #pragma unroll
  for (int i=0;i<9;i++){
    s0 += __expf(ev[i]-mx0);
    s1 += (w1[i] > 0.f) ? __expf(ev[i]-mx1) : 0.f;
    s2 += (w2[i] > 0.f) ? __expf(ev[i]-mx2) : 0.f;
  }
  s0 = blockSum(s0, sh); s1 = blockSum(s1, sh); s2 = blockSum(s2, sh);
  if (tid == 0){
    st[row]       = mx0;  st[R   + row] = 1.f/s0;
    st[2*R + row] = mx1;  st[3*R + row] = 1.f/s1;
    st[4*R + row] = mx2;  st[5*R + row] = 1.f/s2;
  }
}

// ---------------- attention matrix -> bf16 split ----------------
__global__ __launch_bounds__(256) void attn_mat_kernel(
    const float* __restrict__ E, const float* __restrict__ mask,
    const float* __restrict__ st, __nv_bfloat16* __restrict__ Ahd,
    __nv_bfloat16* __restrict__ Ald, long total4)
{
  const long NN2 = (long)NPIX*NPIX;
  long i4 = (long)blockIdx.x * 256 + threadIdx.x;
  if (i4 >= total4) return;
  long idx = i4 * 4;
  int  b   = (int)(idx / NN2);
  long rem = idx - (long)b * NN2;
  int  mr  = (int)(rem / NPIX);
  float mx   = st[b*NPIX + mr];
  float rinv = st[NB*NPIX + b*NPIX + mr];
  float4 e = *(const float4*)&E[idx];
  float4 a;
  a.x = __expf(e.x-mx)*rinv; a.y = __expf(e.y-mx)*rinv;
  a.z = __expf(e.z-mx)*rinv; a.w = __expf(e.w-mx)*rinv;
  if (mask){
    float4 mk = *(const float4*)&mask[rem];
    if (mk.x <= 0.f) a.x = 0.f;
    if (mk.y <= 0.f) a.y = 0.f;
    if (mk.z <= 0.f) a.z = 0.f;
    if (mk.w <= 0.f) a.w = 0.f;
  }
  __nv_bfloat16 h0,l0,h1,l1,h2,l2,h3,l3;
  bsplit(a.x,h0,l0); bsplit(a.y,h1,l1); bsplit(a.z,h2,l2); bsplit(a.w,h3,l3);
  *(uint32_t*)&Ahd[idx]   = bpack(h0,h1);
  *(uint32_t*)&Ahd[idx+2] = bpack(h2,h3);
  *(uint32_t*)&Ald[idx]   = bpack(l0,l1);
  *(uint32_t*)&Ald[idx+2] = bpack(l2,l3);
}

// ---------------- chl softmax -> bf16 split ----------------
__global__ __launch_bounds__(256) void chl_softmax_kernel(
    const float* __restrict__ E, __nv_bfloat16* __restrict__ Ahd,
    __nv_bfloat16* __restrict__ Ald)
{
  __shared__ float sh[32];
  long row = blockIdx.x;
  const float* e = E + row * CCH;
  int tid = threadIdx.x;
  float v0 = e[tid], v1 = e[tid+256];
  float mn = blockMin(fminf(v0, v1), sh);
  float t0 = __expf(mn - v0), t1 = __expf(mn - v1);
  float s = blockSum(t0 + t1, sh);
  float rinv = 1.f/s;
  __nv_bfloat16 h,l;
  bsplit(t0*rinv, h, l); Ahd[row*CCH + tid]     = h; Ald[row*CCH + tid]     = l;
  bsplit(t1*rinv, h, l); Ahd[row*CCH + tid+256] = h; Ald[row*CCH + tid+256] = l;
}

// ---------------- im2col -> k-major bf16 split [KCONV][NPIX] ----------------
__global__ __launch_bounds__(256) void im2col_kernel(const float* __restrict__ X,
    __nv_bfloat16* __restrict__ Ch, __nv_bfloat16* __restrict__ Cl)
{
  const long total = (long)NB*KCONV*(NPIX/2);
  long w = (long)blockIdx.x * 256 + threadIdx.x;
  if (w >= total) return;
  int n2 = (int)(w % (NPIX/2));
  long t = w / (NPIX/2);
  int k  = (int)(t % KCONV);
  int b  = (int)(t / KCONV);
  int ic = k/9, kk = k - ic*9;
  int ky = kk/3, kx = kk - ky*3;
  const float* xs = X + ((long)(b*CCH + ic))*NPIX;
  float v[2];
  #pragma unroll
  for (int u=0; u<2; u++){
    int n = 2*n2 + u;
    int y = n/HW + ky - 1, x = n - (n/HW)*HW + kx - 1;
    v[u] = (y >= 0 && y < HW && x >= 0 && x < HW) ? xs[y*HW + x] : 0.f;
  }
  __nv_bfloat16 h0,l0,h1,l1;
  bsplit(v[0],h0,l0); bsplit(v[1],h1,l1);
  long o = ((long)(b*KCONV + k))*NPIX + 2*n2;
  *(uint32_t*)&Ch[o] = bpack(h0,h1);
  *(uint32_t*)&Cl[o] = bpack(l0,l1);
}

// ---------------- prepass: plain split ----------------
__global__ __launch_bounds__(256) void split_nat_kernel(const float* __restrict__ X,
    __nv_bfloat16* __restrict__ H, __nv_bfloat16* __restrict__ L, long total)
{
  for (long i = (long)blockIdx.x*256 + threadIdx.x; i < total; i += (long)gridDim.x*256){
    __nv_bfloat16 h,l; bsplit(X[i], h, l); H[i] = h; L[i] = l;
  }
}

// ---------------- host ----------------
template<int BI, int EPI>
static void rg(const __nv_bfloat16* Ah, const __nv_bfloat16* Al, long sA,
               const __nv_bfloat16* Bh, const __nv_bfloat16* Bl, long sB,
               float* C, long sC,
               __nv_bfloat16* Dh, __nv_bfloat16* Dl, long sD,
               int M, int N, int K,
               const float* p0, const float* p1,
               const float* res, long sRes, const float* gamma, int ldT)
{
  constexpr int ABYTES = 2*128*40*2;
  constexpr int BBYTES = (BI==2) ? ABYTES : 2*32*136*2;
  constexpr int SMEM = 2*(ABYTES + BBYTES);
  cudaFuncSetAttribute(gemm3_kernel<BI,EPI>,
                       cudaFuncAttributeMaxDynamicSharedMemorySize, SMEM);
  dim3 grid(N/128, (M+127)/128, NB);
  gemm3_kernel<BI,EPI><<<grid, 256, SMEM>>>(Ah, Al, sA, Bh, Bl, sB, C, sC,
                                            Dh, Dl, sD, M, N, K, p0, p1, res, sRes, gamma, ldT);
}

template<typename T>
static T* sym(const void* s){ void* p = nullptr; cudaGetSymbolAddress(&p, s); return (T*)p; }

extern "C" void kernel_launch(void* const* d_in, const int* in_sizes, int n_in,
                              void* d_out, int out_size)
{
  const float* x       = (const float*)d_in[0];
  const float* wq      = (const float*)d_in[1];
  const float* bq      = (const float*)d_in[2];
  const float* wk      = (const float*)d_in[3];
  const float* bk      = (const float*)d_in[4];
  const float* wv0     = (const float*)d_in[5];
  const float* bv0     = (const float*)d_in[6];
  const float* conv1_w = (const float*)d_in[7];
  const float* conv1_s = (const float*)d_in[8];
  const float* conv1_b = (const float*)d_in[9];
  const float* conv2_w = (const float*)d_in[10];
  const float* conv2_s = (const float*)d_in[11];
  const float* conv2_b = (const float*)d_in[12];
  const float* gamma   = (const float*)d_in[13];
  const float* gamma1  = (const float*)d_in[14];
  const float* gamma2  = (const float*)d_in[15];
  const float* c1_qw   = (const float*)d_in[16];
  const float* c1_qs   = (const float*)d_in[17];
  const float* c1_qb   = (const float*)d_in[18];
  const float* c1_ew   = (const float*)d_in[19];
  const float* c1_eb   = (const float*)d_in[20];
  const float* c2_qw   = (const float*)d_in[21];
  const float* c2_qs   = (const float*)d_in[22];
  const float* c2_qb   = (const float*)d_in[23];
  const float* c2_ew   = (const float*)d_in[24];
  const float* c2_eb   = (const float*)d_in[25];
  const float* mask1   = (const float*)d_in[26];
  const float* mask2   = (const float*)d_in[27];

  typedef __nv_bfloat16 bf;
  float* E    = sym<float>(g_E);    float* st   = sym<float>(g_stats);
  float* buf0 = sym<float>(g_buf0); float* buf1 = sym<float>(g_buf1);
  float* out1 = sym<float>(g_out1); float* expd = sym<float>(g_expd);
  bf *wq_h = sym<bf>(g_wq_h), *wq_l = sym<bf>(g_wq_l);
  bf *wk_h = sym<bf>(g_wk_h), *wk_l = sym<bf>(g_wk_l);
  bf *wv_h = sym<bf>(g_wv_h), *wv_l = sym<bf>(g_wv_l);
  bf *cw1_h = sym<bf>(g_cw1_h), *cw1_l = sym<bf>(g_cw1_l);
  bf *cw2_h = sym<bf>(g_cw2_h), *cw2_l = sym<bf>(g_cw2_l);
  bf *qw1_h = sym<bf>(g_qw1_h), *qw1_l = sym<bf>(g_qw1_l);
  bf *qw2_h = sym<bf>(g_qw2_h), *qw2_l = sym<bf>(g_qw2_l);
  bf *ew1_h = sym<bf>(g_ew1_h), *ew1_l = sym<bf>(g_ew1_l);
  bf *ew2_h = sym<bf>(g_ew2_h), *ew2_l = sym<bf>(g_ew2_l);
  bf *x_h = sym<bf>(g_x_h), *x_l = sym<bf>(g_x_l);
  bf *qT_h = sym<bf>(g_qT_h), *qT_l = sym<bf>(g_qT_l);
  bf *k_h  = sym<bf>(g_k_h),  *k_l  = sym<bf>(g_k_l);
  bf *v_h  = sym<bf>(g_v_h),  *v_l  = sym<bf>(g_v_l);
  bf *at_h = sym<bf>(g_at_h), *at_l = sym<bf>(g_at_l);
  bf *ci_h = sym<bf>(g_ci_h), *ci_l = sym<bf>(g_ci_l);
  bf *b0_h = sym<bf>(g_b0_h), *b0_l = sym<bf>(g_b0_l);
  bf *o1_h = sym<bf>(g_o1_h), *o1_l = sym<bf>(g_o1_l);
  bf *qc_h = sym<bf>(g_qc_h), *qc_l = sym<bf>(g_qc_l);
  bf *e2_h = sym<bf>(g_e2_h), *e2_l = sym<bf>(g_e2_l);
  bf *ac_h = sym<bf>(g_ac_h), *ac_l = sym<bf>(g_ac_l);
  bf *vc_h = sym<bf>(g_vc_h), *vc_l = sym<bf>(g_vc_l);
  float* out = (float*)d_out;

  const long sX  = (long)CCH*NPIX;
  const long sE  = (long)NPIX*NPIX;
  const long sCI = (long)KCONV*NPIX;
  const long sQT = (long)NPIX*CR;
  const long sK  = (long)CR*NPIX;
  const long sQC = (long)CH4*NPIX;
  const long sE2 = (long)CH4*CCH;
  const long sCC = (long)CCH*CCH;
  const int  R   = NB*NPIX;
  const long total4 = (long)NB*NPIX*NPIX/4;
  const int  amg = (int)((total4 + 255)/256);
  auto gsz = [](long t){ return (int)((t + 255)/256); };

  // ---- prepass splits ----
  split_nat_kernel<<<gsz(CR*CCH),256>>>(wq, wq_h, wq_l, CR*CCH);
  split_nat_kernel<<<gsz(CR*CCH),256>>>(wk, wk_h, wk_l, CR*CCH);
  split_nat_kernel<<<gsz(CCH*CCH),256>>>(wv0, wv_h, wv_l, CCH*CCH);
  split_nat_kernel<<<gsz((long)CCH*KCONV),256>>>(conv1_w, cw1_h, cw1_l, (long)CCH*KCONV);
  split_nat_kernel<<<gsz((long)CCH*KCONV),256>>>(conv2_w, cw2_h, cw2_l, (long)CCH*KCONV);
  split_nat_kernel<<<gsz(CH4*CCH),256>>>(c1_qw, qw1_h, qw1_l, CH4*CCH);
  split_nat_kernel<<<gsz(CH4*CCH),256>>>(c2_qw, qw2_h, qw2_l, CH4*CCH);
  split_nat_kernel<<<gsz(CCH*CH4),256>>>(c1_ew, ew1_h, ew1_l, CCH*CH4);
  split_nat_kernel<<<gsz(CCH*CH4),256>>>(c2_ew, ew2_h, ew2_l, CCH*CH4);
  split_nat_kernel<<<gsz((long)NB*sX),256>>>(x, x_h, x_l, (long)NB*sX);

  // ---- Q (transposed split), K, V ----
  rg<0,6>(wq_h, wq_l, 0, x_h, x_l, sX, nullptr,0, qT_h, qT_l, sQT,
          CR, NPIX, CCH, bq, nullptr, nullptr,0, nullptr, CR);
  rg<0,5>(wk_h, wk_l, 0, x_h, x_l, sX, nullptr,0, k_h, k_l, sK,
          CR, NPIX, CCH, bk, nullptr, nullptr,0, nullptr, 0);
  rg<0,5>(wv_h, wv_l, 0, x_h, x_l, sX, nullptr,0, v_h, v_l, sX,
          CCH, NPIX, CCH, bv0, nullptr, nullptr,0, nullptr, 0);

  // ---- energy = qT * k ----
  rg<0,0>(qT_h, qT_l, sQT, k_h, k_l, sK, E, sE, nullptr,nullptr,0,
          NPIX, NPIX, CR, nullptr, nullptr, nullptr,0, nullptr, 0);

  softmax_stats_kernel<<<R, 256>>>(E, mask1, mask2, st);

  // ---- pass 0 ----
  attn_mat_kernel<<<amg, 256>>>(E, nullptr, st, at_h, at_l, total4);
  rg<2,2>(v_h, v_l, sX, at_h, at_l, sE, buf1, sX, nullptr,nullptr,0,
          CCH, NPIX, NPIX, nullptr, nullptr, (const float*)x, sX, gamma, 0);
  im2col_kernel<<<gsz((long)NB*KCONV*(NPIX/2)), 256>>>(buf1, ci_h, ci_l);
  rg<0,3>(cw1_h, cw1_l, 0, ci_h, ci_l, sCI, buf0, sX, b0_h, b0_l, sX,
          CCH, NPIX, KCONV, conv1_s, conv1_b, nullptr,0, nullptr, 0);

  // chl #1
  rg<0,4>(qw1_h, qw1_l, 0, b0_h, b0_l, sX, nullptr,0, qc_h, qc_l, sQC,
          CH4, NPIX, CCH, c1_qs, c1_qb, nullptr,0, nullptr, 0);
  rg<2,5>(qc_h, qc_l, sQC, b0_h, b0_l, sX, nullptr,0, e2_h, e2_l, sE2,
          CH4, CCH, NPIX, nullptr, nullptr, nullptr,0, nullptr, 0);
  rg<0,0>(ew1_h, ew1_l, 0, e2_h, e2_l, sE2, expd, sCC, nullptr,nullptr,0,
          CCH, CCH, CH4, c1_eb, nullptr, nullptr,0, nullptr, 0);
  chl_softmax_kernel<<<NB*CCH, 256>>>(expd, ac_h, ac_l);
  rg<0,5>(ac_h, ac_l, sCC, b0_h, b0_l, sX, nullptr,0, vc_h, vc_l, sX,
          CCH, NPIX, CCH, nullptr, nullptr, nullptr,0, nullptr, 0);

  // ---- pass 1 ----
  attn_mat_kernel<<<amg, 256>>>(E, mask1, st + 2*R, at_h, at_l, total4);
  rg<2,2>(vc_h, vc_l, sX, at_h, at_l, sE, buf1, sX, nullptr,nullptr,0,
          CCH, NPIX, NPIX, nullptr, nullptr, buf0, sX, gamma1, 0);
  im2col_kernel<<<gsz((long)NB*KCONV*(NPIX/2)), 256>>>(buf1, ci_h, ci_l);
  rg<0,3>(cw2_h, cw2_l, 0, ci_h, ci_l, sCI, out1, sX, o1_h, o1_l, sX,
          CCH, NPIX, KCONV, conv2_s, conv2_b, nullptr,0, nullptr, 0);

  // chl #2
  rg<0,4>(qw2_h, qw2_l, 0, o1_h, o1_l, sX, nullptr,0, qc_h, qc_l, sQC,
          CH4, NPIX, CCH, c2_qs, c2_qb, nullptr,0, nullptr, 0);
  rg<2,5>(qc_h, qc_l, sQC, o1_h, o1_l, sX, nullptr,0, e2_h, e2_l, sE2,
          CH4, CCH, NPIX, nullptr, nullptr, nullptr,0, nullptr, 0);
  rg<0,0>(ew2_h, ew2_l, 0, e2_h, e2_l, sE2, expd, sCC, nullptr,nullptr,0,
          CCH, CCH, CH4, c2_eb, nullptr, nullptr,0, nullptr, 0);
  chl_softmax_kernel<<<NB*CCH, 256>>>(expd, ac_h, ac_l);
  rg<0,5>(ac_h, ac_l, sCC, o1_h, o1_l, sX, nullptr,0, vc_h, vc_l, sX,
          CCH, NPIX, CCH, nullptr, nullptr, nullptr,0, nullptr, 0);

  // ---- pass 2 -> out ----
  attn_mat_kernel<<<amg, 256>>>(E, mask2, st + 4*R, at_h, at_l, total4);
  rg<2,2>(vc_h, vc_l, sX, at_h, at_l, sE, out, sX, nullptr,nullptr,0,
          CCH, NPIX, NPIX, nullptr, nullptr, out1, sX, gamma2, 0);

  (void)in_sizes; (void)n_in; (void)out_size;
}

// round 11
// speedup vs baseline: 1.1855x; 1.0360x over previous
#include <cuda_runtime.h>
#include <cuda_bf16.h>
#include <cstdint>

#define NB   4
#define CCH  512
#define NPIX 2304
#define CR   64
#define CH4  128
#define HW   48
#define KCONV 4608

// ---------------- fp32 scratch ----------------
__device__ float g_E[(size_t)NB*NPIX*NPIX];
__device__ float g_buf0[NB*CCH*NPIX];
__device__ float g_buf1[NB*CCH*NPIX];
__device__ float g_out1[NB*CCH*NPIX];
__device__ float g_expd[NB*CCH*CCH];

// ---------------- bf16 split scratch ----------------
__device__ __nv_bfloat16 g_wq_h[CR*CCH],  g_wq_l[CR*CCH];
__device__ __nv_bfloat16 g_wk_h[CR*CCH],  g_wk_l[CR*CCH];
__device__ __nv_bfloat16 g_wv_h[CCH*CCH], g_wv_l[CCH*CCH];
__device__ __nv_bfloat16 g_cw1_h[CCH*KCONV], g_cw1_l[CCH*KCONV];
__device__ __nv_bfloat16 g_cw2_h[CCH*KCONV], g_cw2_l[CCH*KCONV];
__device__ __nv_bfloat16 g_qw1_h[CH4*CCH], g_qw1_l[CH4*CCH];
__device__ __nv_bfloat16 g_qw2_h[CH4*CCH], g_qw2_l[CH4*CCH];
__device__ __nv_bfloat16 g_ew1_h[CCH*CH4], g_ew1_l[CCH*CH4];
__device__ __nv_bfloat16 g_ew2_h[CCH*CH4], g_ew2_l[CCH*CH4];
__device__ __nv_bfloat16 g_x_h[(size_t)NB*CCH*NPIX], g_x_l[(size_t)NB*CCH*NPIX];
__device__ __nv_bfloat16 g_qT_h[NB*NPIX*CR], g_qT_l[NB*NPIX*CR];
__device__ __nv_bfloat16 g_k_h[NB*CR*NPIX],  g_k_l[NB*CR*NPIX];
__device__ __nv_bfloat16 g_v_h[NB*CCH*NPIX], g_v_l[NB*CCH*NPIX];
__device__ __nv_bfloat16 g_at0_h[(size_t)NB*NPIX*NPIX], g_at0_l[(size_t)NB*NPIX*NPIX];
__device__ __nv_bfloat16 g_at1_h[(size_t)NB*NPIX*NPIX], g_at1_l[(size_t)NB*NPIX*NPIX];
__device__ __nv_bfloat16 g_at2_h[(size_t)NB*NPIX*NPIX], g_at2_l[(size_t)NB*NPIX*NPIX];
__device__ __nv_bfloat16 g_ci_h[(size_t)NB*KCONV*NPIX], g_ci_l[(size_t)NB*KCONV*NPIX];
__device__ __nv_bfloat16 g_b0_h[NB*CCH*NPIX], g_b0_l[NB*CCH*NPIX];
__device__ __nv_bfloat16 g_o1_h[NB*CCH*NPIX], g_o1_l[NB*CCH*NPIX];
__device__ __nv_bfloat16 g_qc_h[NB*CH4*NPIX], g_qc_l[NB*CH4*NPIX];
__device__ __nv_bfloat16 g_e2_h[NB*CH4*CCH],  g_e2_l[NB*CH4*CCH];
__device__ __nv_bfloat16 g_ac_h[NB*CCH*CCH],  g_ac_l[NB*CCH*CCH];
__device__ __nv_bfloat16 g_vc_h[NB*CCH*NPIX], g_vc_l[NB*CCH*NPIX];

// ---------------- reductions ----------------
__device__ __forceinline__ float warpMax(float v){
  #pragma unroll
  for (int o=16;o;o>>=1) v = fmaxf(v, __shfl_xor_sync(0xffffffffu, v, o));
  return v;
}
__device__ __forceinline__ float warpMin(float v){
  #pragma unroll
  for (int o=16;o;o>>=1) v = fminf(v, __shfl_xor_sync(0xffffffffu, v, o));
  return v;
}
__device__ __forceinline__ float warpSum(float v){
  #pragma unroll
  for (int o=16;o;o>>=1) v += __shfl_xor_sync(0xffffffffu, v, o);
  return v;
}
__device__ float blockMax(float v, float* sh){
  v = warpMax(v);
  if ((threadIdx.x & 31) == 0) sh[threadIdx.x >> 5] = v;
  __syncthreads();
  if (threadIdx.x < 32){
    float t = (threadIdx.x < (blockDim.x>>5)) ? sh[threadIdx.x] : -3.4e38f;
    t = warpMax(t);
    if (threadIdx.x == 0) sh[0] = t;
  }
  __syncthreads();
  float r = sh[0]; __syncthreads(); return r;
}
__device__ float blockMin(float v, float* sh){
  v = warpMin(v);
  if ((threadIdx.x & 31) == 0) sh[threadIdx.x >> 5] = v;
  __syncthreads();
  if (threadIdx.x < 32){
    float t = (threadIdx.x < (blockDim.x>>5)) ? sh[threadIdx.x] : 3.4e38f;
    t = warpMin(t);
    if (threadIdx.x == 0) sh[0] = t;
  }
  __syncthreads();
  float r = sh[0]; __syncthreads(); return r;
}
__device__ float blockSum(float v, float* sh){
  v = warpSum(v);
  if ((threadIdx.x & 31) == 0) sh[threadIdx.x >> 5] = v;
  __syncthreads();
  if (threadIdx.x < 32){
    float t = (threadIdx.x < (blockDim.x>>5)) ? sh[threadIdx.x] : 0.f;
    t = warpSum(t);
    if (threadIdx.x == 0) sh[0] = t;
  }
  __syncthreads();
  float r = sh[0]; __syncthreads(); return r;
}

// ---------------- helpers ----------------
__device__ __forceinline__ void mma_bf16(float* c, const uint32_t* a, const uint32_t* b){
  asm volatile("mma.sync.aligned.m16n8k16.row.col.f32.bf16.bf16.f32 "
    "{%0,%1,%2,%3}, {%4,%5,%6,%7}, {%8,%9}, {%0,%1,%2,%3};\n"
    : "+f"(c[0]), "+f"(c[1]), "+f"(c[2]), "+f"(c[3])
    : "r"(a[0]), "r"(a[1]), "r"(a[2]), "r"(a[3]), "r"(b[0]), "r"(b[1]));
}
__device__ __forceinline__ void ldsm_x4(uint32_t* r, uint32_t saddr){
  asm volatile("ldmatrix.sync.aligned.m8n8.x4.shared.b16 {%0,%1,%2,%3}, [%4];"
    : "=r"(r[0]), "=r"(r[1]), "=r"(r[2]), "=r"(r[3]) : "r"(saddr));
}
__device__ __forceinline__ void ldsm_x4t(uint32_t* r, uint32_t saddr){
  asm volatile("ldmatrix.sync.aligned.m8n8.x4.trans.shared.b16 {%0,%1,%2,%3}, [%4];"
    : "=r"(r[0]), "=r"(r[1]), "=r"(r[2]), "=r"(r[3]) : "r"(saddr));
}
__device__ __forceinline__ void cpasync16(void* dst, const void* src, int szbytes){
  uint32_t d = (uint32_t)__cvta_generic_to_shared(dst);
  asm volatile("cp.async.cg.shared.global [%0], [%1], 16, %2;\n"
               :: "r"(d), "l"(src), "r"(szbytes));
}
__device__ __forceinline__ void cp_commit(){ asm volatile("cp.async.commit_group;\n"); }
__device__ __forceinline__ void cp_wait0(){ asm volatile("cp.async.wait_group 0;\n"); }
__device__ __forceinline__ void cp_wait1(){ asm volatile("cp.async.wait_group 1;\n"); }

__device__ __forceinline__ void bsplit(float v, __nv_bfloat16& h, __nv_bfloat16& l){
  h = __float2bfloat16(v);
  l = __float2bfloat16(v - __bfloat162float(h));
}
__device__ __forceinline__ uint32_t bpack(__nv_bfloat16 a, __nv_bfloat16 b){
  return (uint32_t)__bfloat16_as_ushort(a) | ((uint32_t)__bfloat16_as_ushort(b) << 16);
}

// ---------------- BF16x3 tensor-core GEMM (ldmatrix, K-tile 32, 2-stage) ----------------
// A bf16 [M][K] row-major (hi/lo). BI: 0 = B bf16 [K][N] k-major; 2 = B bf16 [N][K] (NT).
// EPI: 0 fp32(+opt bias p0); 2 fp32 gamma*acc+res; 3 relu(acc*p0+p1)->fp32+split;
//      4 relu->split; 5 (+opt bias)->split; 6 (+bias)->transposed split (ldT).
// Block tile 128x128x32; N%128==0, K%32==0.
template<int BI, int EPI>
__global__ void __launch_bounds__(256,2) gemm3_kernel(
    const __nv_bfloat16* __restrict__ Ah, const __nv_bfloat16* __restrict__ Al, long sA,
    const __nv_bfloat16* __restrict__ Bh, const __nv_bfloat16* __restrict__ Bl, long sB,
    float* __restrict__ Cm, long sC,
    __nv_bfloat16* __restrict__ Dh, __nv_bfloat16* __restrict__ Dl, long sD,
    int M, int N, int K,
    const float* __restrict__ p0, const float* __restrict__ p1,
    const float* __restrict__ res, long sRes,
    const float* __restrict__ gamma, int ldT)
{
  constexpr int AROW = 40;          // bf16 stride (32 data + 8 pad)
  constexpr int ABF  = 128*AROW;    // bf16 per A array per stage
  constexpr int ABYTES = 2*ABF*2;   // hi+lo
  constexpr int BBF  = (BI==2) ? ABF : 32*136;
  constexpr int BBYTES = 2*BBF*2;
  constexpr int STAGEB = ABYTES + BBYTES;

  extern __shared__ char smc[];
  const uint32_t smem0 = (uint32_t)__cvta_generic_to_shared(smc);

  const int bz = blockIdx.z;
  Ah += (long)bz * sA;  Al += (long)bz * sA;
  Bh += (long)bz * sB;  Bl += (long)bz * sB;
  if (Cm) Cm += (long)bz * sC;
  if (EPI >= 3){ Dh += (long)bz * sD; Dl += (long)bz * sD; }
  if (EPI == 2) res += (long)bz * sRes;

  const int tid  = threadIdx.x;
  const int warp = tid >> 5;
  const int lane = tid & 31;
  const int g    = lane >> 2;
  const int ct   = lane & 3;
  const int warpM = warp >> 2;
  const int warpN = warp & 3;
  const int m0 = blockIdx.y * 128;
  const int n0 = blockIdx.x * 128;

  const int lo8 = lane & 7, b3 = (lane>>3)&1, b4 = (lane>>4)&1;
  const uint32_t aoff  = ((warpM*64 + lo8 + b3*8)*AROW + b4*8)*2;
  const uint32_t boff2 = ((warpN*32 + lo8 + b4*8)*AROW + b3*8)*2;          // BI2
  const uint32_t boff0 = ((lo8 + b3*8)*136 + warpN*32 + b4*8)*2;           // BI0

  float acc[4][4][4];
  #pragma unroll
  for (int i=0;i<4;i++)
    #pragma unroll
    for (int j=0;j<4;j++)
      #pragma unroll
      for (int c=0;c<4;c++) acc[i][j][c]=0.f;

  auto loadT = [&](int s, int k0){
    char* st = smc + s*STAGEB;
    __nv_bfloat16* Ahs = (__nv_bfloat16*)st;
    #pragma unroll
    for (int c = tid; c < 1024; c += 256){
      const __nv_bfloat16* base = (c < 512) ? Ah : Al;
      __nv_bfloat16* dst = Ahs + ((c < 512) ? 0 : ABF);
      int e = c & 511, row = e >> 2, q = e & 3;
      int gm = m0 + row;
      int sz = (gm < M) ? 16 : 0; if (gm >= M) gm = 0;
      cpasync16(dst + row*AROW + q*8, base + (long)gm*K + k0 + q*8, sz);
    }
    __nv_bfloat16* Bs = (__nv_bfloat16*)(st + ABYTES);
    if (BI == 2){
      #pragma unroll
      for (int c = tid; c < 1024; c += 256){
        const __nv_bfloat16* base = (c < 512) ? Bh : Bl;
        __nv_bfloat16* dst = Bs + ((c < 512) ? 0 : ABF);
        int e = c & 511, row = e >> 2, q = e & 3;
        cpasync16(dst + row*AROW + q*8, base + (long)(n0+row)*K + k0 + q*8, 16);
      }
    } else {
      #pragma unroll
      for (int c = tid; c < 1024; c += 256){
        const __nv_bfloat16* base = (c < 512) ? Bh : Bl;
        __nv_bfloat16* dst = Bs + ((c < 512) ? 0 : 32*136);
        int e = c & 511, row = e >> 4, ch = e & 15;
        cpasync16(dst + row*136 + ch*8, base + (long)(k0+row)*N + n0 + ch*8, 16);
      }
    }
  };

  const int T = K/32;
  loadT(0, 0); cp_commit();

  for (int i = 0; i < T; i++){
    if (i + 1 < T){ loadT((i+1)&1, (i+1)*32); cp_commit(); cp_wait1(); }
    else          { cp_wait0(); }
    __syncthreads();

    const uint32_t stb = smem0 + (uint32_t)((i&1)*STAGEB);
    const uint32_t bb  = stb + ABYTES;

    #pragma unroll
    for (int h = 0; h < 2; h++){
      const uint32_t aH = stb + aoff + h*32;
      const uint32_t aL = stb + ABF*2 + aoff + h*32;
      uint32_t ah[4][4], al[4][4], bhf[8], blf[8];
      #pragma unroll
      for (int mi=0; mi<4; mi++){
        ldsm_x4(ah[mi], aH + mi*(16*AROW*2));
        ldsm_x4(al[mi], aL + mi*(16*AROW*2));
      }
      if (BI == 2){
        const uint32_t bH = bb + boff2 + h*32;
        const uint32_t bL = bb + ABF*2 + boff2 + h*32;
        ldsm_x4(bhf,   bH);
        ldsm_x4(bhf+4, bH + 16*AROW*2);
        ldsm_x4(blf,   bL);
        ldsm_x4(blf+4, bL + 16*AROW*2);
      } else {
        const uint32_t bH = bb + boff0 + h*(16*136*2);
        const uint32_t bL = bb + 32*136*2 + boff0 + h*(16*136*2);
        ldsm_x4t(bhf,   bH);
        ldsm_x4t(bhf+4, bH + 16*2);
        ldsm_x4t(blf,   bL);
        ldsm_x4t(blf+4, bL + 16*2);
      }
      #pragma unroll
      for (int mi=0; mi<4; mi++)
        #pragma unroll
        for (int nj=0; nj<4; nj++){
          mma_bf16(acc[mi][nj], ah[mi], bhf + nj*2);
          mma_bf16(acc[mi][nj], ah[mi], blf + nj*2);
          mma_bf16(acc[mi][nj], al[mi], bhf + nj*2);
        }
    }
    __syncthreads();
  }

  // ---- epilogue
  #pragma unroll
  for (int mi=0; mi<4; mi++){
    int rr[2] = { m0 + warpM*64 + mi*16 + g, m0 + warpM*64 + mi*16 + g + 8 };
    float sc[2] = {0.f,0.f}, of[2] = {0.f,0.f};
    #pragma unroll
    for (int h=0; h<2; h++){
      if (rr[h] < M){
        if (EPI == 3 || EPI == 4){ sc[h] = p0[rr[h]]; of[h] = p1[rr[h]]; }
        else if (EPI == 0 || EPI == 5 || EPI == 6){ if (p0) of[h] = p0[rr[h]]; }
      }
    }
    #pragma unroll
    for (int nj=0; nj<4; nj++){
      int n = n0 + warpN*32 + nj*8 + 2*ct;
      #pragma unroll
      for (int h=0; h<2; h++){
        int r = rr[h];
        if (r >= M) continue;
        float wx = acc[mi][nj][2*h], wy = acc[mi][nj][2*h+1];
        if (EPI == 0){ wx += of[h]; wy += of[h]; }
        else if (EPI == 2){
          float2 rv = *(const float2*)&res[(long)r*N + n];
          wx = gamma[0]*wx + rv.x; wy = gamma[0]*wy + rv.y;
        } else if (EPI == 3 || EPI == 4){
          wx = fmaxf(wx*sc[h] + of[h], 0.f);
          wy = fmaxf(wy*sc[h] + of[h], 0.f);
        } else { wx += of[h]; wy += of[h]; }
        if (EPI == 0 || EPI == 2 || EPI == 3){
          float2 w; w.x = wx; w.y = wy;
          *(float2*)&Cm[(long)r*N + n] = w;
        }
        if (EPI >= 3){
          __nv_bfloat16 hx, lx, hy, ly;
          bsplit(wx, hx, lx); bsplit(wy, hy, ly);
          if (EPI == 6){
            Dh[(long)n*ldT + r] = hx;       Dl[(long)n*ldT + r] = lx;
            Dh[(long)(n+1)*ldT + r] = hy;   Dl[(long)(n+1)*ldT + r] = ly;
          } else {
            *(uint32_t*)&Dh[(long)r*N + n] = bpack(hx, hy);
            *(uint32_t*)&Dl[(long)r*N + n] = bpack(lx, ly);
          }
        }
      }
    }
  }
}

// ---------------- fused softmax: one exp per element, all 3 variants ----------------
// masked softmax == exp0*mask / sum(exp0*mask) with exp0 = exp(e - rowmax_global).
__global__ __launch_bounds__(288) void softmax_all_kernel(
    const float* __restrict__ E,
    const float* __restrict__ M1, const float* __restrict__ M2,
    __nv_bfloat16* __restrict__ a0h, __nv_bfloat16* __restrict__ a0l,
    __nv_bfloat16* __restrict__ a1h, __nv_bfloat16* __restrict__ a1l,
    __nv_bfloat16* __restrict__ a2h, __nv_bfloat16* __restrict__ a2l)
{
  __shared__ float sh[32];
  long row = blockIdx.x;                 // b*NPIX + m
  int  mr  = (int)(row % NPIX);
  const float* e  = E  + row * NPIX;
  const float* m1 = M1 + (long)mr * NPIX;
  const float* m2 = M2 + (long)mr * NPIX;
  int tid = threadIdx.x;

  float ev[8], w1[8], w2[8];
  float mx = -3.4e38f;
  #pragma unroll
  for (int j = 0; j < 4; j++){
    int n = 2*(tid + j*288);
    float2 e2 = *(const float2*)&e[n];
    float2 u1 = *(const float2*)&m1[n];
    float2 u2 = *(const float2*)&m2[n];
    ev[2*j]=e2.x; ev[2*j+1]=e2.y;
    w1[2*j]=u1.x; w1[2*j+1]=u1.y;
    w2[2*j]=u2.x; w2[2*j+1]=u2.y;
    mx = fmaxf(mx, fmaxf(e2.x, e2.y));
  }
  mx = blockMax(mx, sh);

  float x0[8];
  float s0 = 0.f, s1 = 0.f, s2 = 0.f;
  #pragma unroll
  for (int i = 0; i < 8; i++){
    x0[i] = __expf(ev[i] - mx);
    s0 += x0[i];
    if (w1[i] > 0.f) s1 += x0[i];
    if (w2[i] > 0.f) s2 += x0[i];
  }
  s0 = blockSum(s0, sh);
  s1 = blockSum(s1, sh);
  s2 = blockSum(s2, sh);
  float r0 = 1.f/s0, r1 = 1.f/s1, r2 = 1.f/s2;

  #pragma unroll
  for (int j = 0; j < 4; j++){
    int n = 2*(tid + j*288);
    long o = row * NPIX + n;
    float px = x0[2*j], py = x0[2*j+1];
    __nv_bfloat16 hx, lx, hy, ly;
    // variant 0 (unmasked)
    bsplit(px*r0, hx, lx); bsplit(py*r0, hy, ly);
    *(uint32_t*)&a0h[o] = bpack(hx, hy);
    *(uint32_t*)&a0l[o] = bpack(lx, ly);
    // variant 1 (mask1)
    float ax = (w1[2*j]   > 0.f) ? px*r1 : 0.f;
    float ay = (w1[2*j+1] > 0.f) ? py*r1 : 0.f;
    bsplit(ax, hx, lx); bsplit(ay, hy, ly);
    *(uint32_t*)&a1h[o] = bpack(hx, hy);
    *(uint32_t*)&a1l[o] = bpack(lx, ly);
    // variant 2 (mask2)
    ax = (w2[2*j]   > 0.f) ? px*r2 : 0.f;
    ay = (w2[2*j+1] > 0.f) ? py*r2 : 0.f;
    bsplit(ax, hx, lx); bsplit(ay, hy, ly);
    *(uint32_t*)&a2h[o] = bpack(hx, hy);
    *(uint32_t*)&a2l[o] = bpack(lx, ly);
  }
}

// ---------------- chl softmax -> bf16 split ----------------
__global__ __launch_bounds__(256) void chl_softmax_kernel(
    const float* __restrict__ E, __nv_bfloat16* __restrict__ Ahd,
    __nv_bfloat16* __restrict__ Ald)
{
  __shared__ float sh[32];
  long row = blockIdx.x;
  const float* e = E + row * CCH;
  int tid = threadIdx.x;
  float v0 = e[tid], v1 = e[tid+256];
  float mn = blockMin(fminf(v0, v1), sh);
  float t0 = __expf(mn - v0), t1 = __expf(mn - v1);
  float s = blockSum(t0 + t1, sh);
  float rinv = 1.f/s;
  __nv_bfloat16 h,l;
  bsplit(t0*rinv, h, l); Ahd[row*CCH + tid]     = h; Ald[row*CCH + tid]     = l;
  bsplit(t1*rinv, h, l); Ahd[row*CCH + tid+256] = h; Ald[row*CCH + tid+256] = l;
}

// ---------------- im2col -> k-major bf16 split [KCONV][NPIX] ----------------
__global__ __launch_bounds__(256) void im2col_kernel(const float* __restrict__ X,
    __nv_bfloat16* __restrict__ Ch, __nv_bfloat16* __restrict__ Cl)
{
  const long total = (long)NB*KCONV*(NPIX/2);
  long w = (long)blockIdx.x * 256 + threadIdx.x;
  if (w >= total) return;
  int n2 = (int)(w % (NPIX/2));
  long t = w / (NPIX/2);
  int k  = (int)(t % KCONV);
  int b  = (int)(t / KCONV);
  int ic = k/9, kk = k - ic*9;
  int ky = kk/3, kx = kk - ky*3;
  const float* xs = X + ((long)(b*CCH + ic))*NPIX;
  float v[2];
  #pragma unroll
  for (int u=0; u<2; u++){
    int n = 2*n2 + u;
    int y = n/HW + ky - 1, x = n - (n/HW)*HW + kx - 1;
    v[u] = (y >= 0 && y < HW && x >= 0 && x < HW) ? xs[y*HW + x] : 0.f;
  }
  __nv_bfloat16 h0,l0,h1,l1;
  bsplit(v[0],h0,l0); bsplit(v[1],h1,l1);
  long o = ((long)(b*KCONV + k))*NPIX + 2*n2;
  *(uint32_t*)&Ch[o] = bpack(h0,h1);
  *(uint32_t*)&Cl[o] = bpack(l0,l1);
}

// ---------------- prepass: plain split ----------------
__global__ __launch_bounds__(256) void split_nat_kernel(const float* __restrict__ X,
    __nv_bfloat16* __restrict__ H, __nv_bfloat16* __restrict__ L, long total)
{
  for (long i = (long)blockIdx.x*256 + threadIdx.x; i < total; i += (long)gridDim.x*256){
    __nv_bfloat16 h,l; bsplit(X[i], h, l); H[i] = h; L[i] = l;
  }
}

// ---------------- host ----------------
template<int BI, int EPI>
static void rg(const __nv_bfloat16* Ah, const __nv_bfloat16* Al, long sA,
               const __nv_bfloat16* Bh, const __nv_bfloat16* Bl, long sB,
               float* C, long sC,
               __nv_bfloat16* Dh, __nv_bfloat16* Dl, long sD,
               int M, int N, int K,
               const float* p0, const float* p1,
               const float* res, long sRes, const float* gamma, int ldT)
{
  constexpr int ABYTES = 2*128*40*2;
  constexpr int BBYTES = (BI==2) ? ABYTES : 2*32*136*2;
  constexpr int SMEM = 2*(ABYTES + BBYTES);
  cudaFuncSetAttribute(gemm3_kernel<BI,EPI>,
                       cudaFuncAttributeMaxDynamicSharedMemorySize, SMEM);
  dim3 grid(N/128, (M+127)/128, NB);
  gemm3_kernel<BI,EPI><<<grid, 256, SMEM>>>(Ah, Al, sA, Bh, Bl, sB, C, sC,
                                            Dh, Dl, sD, M, N, K, p0, p1, res, sRes, gamma, ldT);
}

template<typename T>
static T* sym(const void* s){ void* p = nullptr; cudaGetSymbolAddress(&p, s); return (T*)p; }

extern "C" void kernel_launch(void* const* d_in, const int* in_sizes, int n_in,
                              void* d_out, int out_size)
{
  const float* x       = (const float*)d_in[0];
  const float* wq      = (const float*)d_in[1];
  const float* bq      = (const float*)d_in[2];
  const float* wk      = (const float*)d_in[3];
  const float* bk      = (const float*)d_in[4];
  const float* wv0     = (const float*)d_in[5];
  const float* bv0     = (const float*)d_in[6];
  const float* conv1_w = (const float*)d_in[7];
  const float* conv1_s = (const float*)d_in[8];
  const float* conv1_b = (const float*)d_in[9];
  const float* conv2_w = (const float*)d_in[10];
  const float* conv2_s = (const float*)d_in[11];
  const float* conv2_b = (const float*)d_in[12];
  const float* gamma   = (const float*)d_in[13];
  const float* gamma1  = (const float*)d_in[14];
  const float* gamma2  = (const float*)d_in[15];
  const float* c1_qw   = (const float*)d_in[16];
  const float* c1_qs   = (const float*)d_in[17];
  const float* c1_qb   = (const float*)d_in[18];
  const float* c1_ew   = (const float*)d_in[19];
  const float* c1_eb   = (const float*)d_in[20];
  const float* c2_qw   = (const float*)d_in[21];
  const float* c2_qs   = (const float*)d_in[22];
  const float* c2_qb   = (const float*)d_in[23];
  const float* c2_ew   = (const float*)d_in[24];
  const float* c2_eb   = (const float*)d_in[25];
  const float* mask1   = (const float*)d_in[26];
  const float* mask2   = (const float*)d_in[27];

  typedef __nv_bfloat16 bf;
  float* E    = sym<float>(g_E);
  float* buf0 = sym<float>(g_buf0); float* buf1 = sym<float>(g_buf1);
  float* out1 = sym<float>(g_out1); float* expd = sym<float>(g_expd);
  bf *wq_h = sym<bf>(g_wq_h), *wq_l = sym<bf>(g_wq_l);
  bf *wk_h = sym<bf>(g_wk_h), *wk_l = sym<bf>(g_wk_l);
  bf *wv_h = sym<bf>(g_wv_h), *wv_l = sym<bf>(g_wv_l);
  bf *cw1_h = sym<bf>(g_cw1_h), *cw1_l = sym<bf>(g_cw1_l);
  bf *cw2_h = sym<bf>(g_cw2_h), *cw2_l = sym<bf>(g_cw2_l);
  bf *qw1_h = sym<bf>(g_qw1_h), *qw1_l = sym<bf>(g_qw1_l);
  bf *qw2_h = sym<bf>(g_qw2_h), *qw2_l = sym<bf>(g_qw2_l);
  bf *ew1_h = sym<bf>(g_ew1_h), *ew1_l = sym<bf>(g_ew1_l);
  bf *ew2_h = sym<bf>(g_ew2_h), *ew2_l = sym<bf>(g_ew2_l);
  bf *x_h = sym<bf>(g_x_h), *x_l = sym<bf>(g_x_l);
  bf *qT_h = sym<bf>(g_qT_h), *qT_l = sym<bf>(g_qT_l);
  bf *k_h  = sym<bf>(g_k_h),  *k_l  = sym<bf>(g_k_l);
  bf *v_h  = sym<bf>(g_v_h),  *v_l  = sym<bf>(g_v_l);
  bf *at0_h = sym<bf>(g_at0_h), *at0_l = sym<bf>(g_at0_l);
  bf *at1_h = sym<bf>(g_at1_h), *at1_l = sym<bf>(g_at1_l);
  bf *at2_h = sym<bf>(g_at2_h), *at2_l = sym<bf>(g_at2_l);
  bf *ci_h = sym<bf>(g_ci_h), *ci_l = sym<bf>(g_ci_l);
  bf *b0_h = sym<bf>(g_b0_h), *b0_l = sym<bf>(g_b0_l);
  bf *o1_h = sym<bf>(g_o1_h), *o1_l = sym<bf>(g_o1_l);
  bf *qc_h = sym<bf>(g_qc_h), *qc_l = sym<bf>(g_qc_l);
  bf *e2_h = sym<bf>(g_e2_h), *e2_l = sym<bf>(g_e2_l);
  bf *ac_h = sym<bf>(g_ac_h), *ac_l = sym<bf>(g_ac_l);
  bf *vc_h = sym<bf>(g_vc_h), *vc_l = sym<bf>(g_vc_l);
  float* out = (float*)d_out;

  const long sX  = (long)CCH*NPIX;
  const long sE  = (long)NPIX*NPIX;
  const long sCI = (long)KCONV*NPIX;
  const long sQT = (long)NPIX*CR;
  const long sK  = (long)CR*NPIX;
  const long sQC = (long)CH4*NPIX;
  const long sE2 = (long)CH4*CCH;
  const long sCC = (long)CCH*CCH;
  const int  R   = NB*NPIX;
  auto gsz = [](long t){ return (int)((t + 255)/256); };

  // ---- prepass splits needed for QKV (launches 1-4) ----
  split_nat_kernel<<<gsz(CR*CCH),256>>>(wq, wq_h, wq_l, CR*CCH);
  split_nat_kernel<<<gsz(CR*CCH),256>>>(wk, wk_h, wk_l, CR*CCH);
  split_nat_kernel<<<gsz(CCH*CCH),256>>>(wv0, wv_h, wv_l, CCH*CCH);
  split_nat_kernel<<<gsz((long)NB*sX),256>>>(x, x_h, x_l, (long)NB*sX);

  // ---- Q (#5), V (#6 -> ncu capture target), K (#7) ----
  rg<0,6>(wq_h, wq_l, 0, x_h, x_l, sX, nullptr,0, qT_h, qT_l, sQT,
          CR, NPIX, CCH, bq, nullptr, nullptr,0, nullptr, CR);
  rg<0,5>(wv_h, wv_l, 0, x_h, x_l, sX, nullptr,0, v_h, v_l, sX,
          CCH, NPIX, CCH, bv0, nullptr, nullptr,0, nullptr, 0);
  rg<0,5>(wk_h, wk_l, 0, x_h, x_l, sX, nullptr,0, k_h, k_l, sK,
          CR, NPIX, CCH, bk, nullptr, nullptr,0, nullptr, 0);

  // ---- energy = qT * k (#8) ----
  rg<0,0>(qT_h, qT_l, sQT, k_h, k_l, sK, E, sE, nullptr,nullptr,0,
          NPIX, NPIX, CR, nullptr, nullptr, nullptr,0, nullptr, 0);

  // ---- remaining weight splits (independent; scheduled here) ----
  split_nat_kernel<<<gsz((long)CCH*KCONV),256>>>(conv1_w, cw1_h, cw1_l, (long)CCH*KCONV);
  split_nat_kernel<<<gsz((long)CCH*KCONV),256>>>(conv2_w, cw2_h, cw2_l, (long)CCH*KCONV);
  split_nat_kernel<<<gsz(CH4*CCH),256>>>(c1_qw, qw1_h, qw1_l, CH4*CCH);
  split_nat_kernel<<<gsz(CH4*CCH),256>>>(c2_qw, qw2_h, qw2_l, CH4*CCH);
  split_nat_kernel<<<gsz(CCH*CH4),256>>>(c1_ew, ew1_h, ew1_l, CCH*CH4);
  split_nat_kernel<<<gsz(CCH*CH4),256>>>(c2_ew, ew2_h, ew2_l, CCH*CH4);

  // ---- fused softmax: stats + all 3 attention matrices, one exp/elem ----
  softmax_all_kernel<<<R, 288>>>(E, mask1, mask2,
                                 at0_h, at0_l, at1_h, at1_l, at2_h, at2_l);

  // ---- pass 0 ----
  rg<2,2>(v_h, v_l, sX, at0_h, at0_l, sE, buf1, sX, nullptr,nullptr,0,
          CCH, NPIX, NPIX, nullptr, nullptr, (const float*)x, sX, gamma, 0);
  im2col_kernel<<<gsz((long)NB*KCONV*(NPIX/2)), 256>>>(buf1, ci_h, ci_l);
  rg<0,3>(cw1_h, cw1_l, 0, ci_h, ci_l, sCI, buf0, sX, b0_h, b0_l, sX,
          CCH, NPIX, KCONV, conv1_s, conv1_b, nullptr,0, nullptr, 0);

  // chl #1
  rg<0,4>(qw1_h, qw1_l, 0, b0_h, b0_l, sX, nullptr,0, qc_h, qc_l, sQC,
          CH4, NPIX, CCH, c1_qs, c1_qb, nullptr,0, nullptr, 0);
  rg<2,5>(qc_h, qc_l, sQC, b0_h, b0_l, sX, nullptr,0, e2_h, e2_l, sE2,
          CH4, CCH, NPIX, nullptr, nullptr, nullptr,0, nullptr, 0);
  rg<0,0>(ew1_h, ew1_l, 0, e2_h, e2_l, sE2, expd, sCC, nullptr,nullptr,0,
          CCH, CCH, CH4, c1_eb, nullptr, nullptr,0, nullptr, 0);
  chl_softmax_kernel<<<NB*CCH, 256>>>(expd, ac_h, ac_l);
  rg<0,5>(ac_h, ac_l, sCC, b0_h, b0_l, sX, nullptr,0, vc_h, vc_l, sX,
          CCH, NPIX, CCH, nullptr, nullptr, nullptr,0, nullptr, 0);

  // ---- pass 1 ----
  rg<2,2>(vc_h, vc_l, sX, at1_h, at1_l, sE, buf1, sX, nullptr,nullptr,0,
          CCH, NPIX, NPIX, nullptr, nullptr, buf0, sX, gamma1, 0);
  im2col_kernel<<<gsz((long)NB*KCONV*(NPIX/2)), 256>>>(buf1, ci_h, ci_l);
  rg<0,3>(cw2_h, cw2_l, 0, ci_h, ci_l, sCI, out1, sX, o1_h, o1_l, sX,
          CCH, NPIX, KCONV, conv2_s, conv2_b, nullptr,0, nullptr, 0);

  // chl #2
  rg<0,4>(qw2_h, qw2_l, 0, o1_h, o1_l, sX, nullptr,0, qc_h, qc_l, sQC,
          CH4, NPIX, CCH, c2_qs, c2_qb, nullptr,0, nullptr, 0);
  rg<2,5>(qc_h, qc_l, sQC, o1_h, o1_l, sX, nullptr,0, e2_h, e2_l, sE2,
          CH4, CCH, NPIX, nullptr, nullptr, nullptr,0, nullptr, 0);
  rg<0,0>(ew2_h, ew2_l, 0, e2_h, e2_l, sE2, expd, sCC, nullptr,nullptr,0,
          CCH, CCH, CH4, c2_eb, nullptr, nullptr,0, nullptr, 0);
  chl_softmax_kernel<<<NB*CCH, 256>>>(expd, ac_h, ac_l);
  rg<0,5>(ac_h, ac_l, sCC, o1_h, o1_l, sX, nullptr,0, vc_h, vc_l, sX,
          CCH, NPIX, CCH, nullptr, nullptr, nullptr,0, nullptr, 0);

  // ---- pass 2 -> out ----
  rg<2,2>(vc_h, vc_l, sX, at2_h, at2_l, sE, out, sX, nullptr,nullptr,0,
          CCH, NPIX, NPIX, nullptr, nullptr, out1, sX, gamma2, 0);

  (void)in_sizes; (void)n_in; (void)out_size;
}

// round 12
// speedup vs baseline: 1.3000x; 1.0966x over previous
#include <cuda_runtime.h>
#include <cuda_bf16.h>
#include <cstdint>

#define NB   4
#define CCH  512
#define NPIX 2304
#define CR   64
#define CH4  128
#define HW   48
#define KCONV 4608

// ---------------- fp32 scratch ----------------
__device__ float g_E[(size_t)NB*NPIX*NPIX];
__device__ float g_buf0[NB*CCH*NPIX];
__device__ float g_buf1[NB*CCH*NPIX];
__device__ float g_out1[NB*CCH*NPIX];
__device__ float g_expd[NB*CCH*CCH];
__device__ float g_part[4718592];          // split-K partials (max NB*KS*M*N)

// ---------------- bf16 split scratch ----------------
__device__ __nv_bfloat16 g_wq_h[CR*CCH],  g_wq_l[CR*CCH];
__device__ __nv_bfloat16 g_wk_h[CR*CCH],  g_wk_l[CR*CCH];
__device__ __nv_bfloat16 g_wv_h[CCH*CCH], g_wv_l[CCH*CCH];
__device__ __nv_bfloat16 g_cw1_h[CCH*KCONV], g_cw1_l[CCH*KCONV];
__device__ __nv_bfloat16 g_cw2_h[CCH*KCONV], g_cw2_l[CCH*KCONV];
__device__ __nv_bfloat16 g_qw1_h[CH4*CCH], g_qw1_l[CH4*CCH];
__device__ __nv_bfloat16 g_qw2_h[CH4*CCH], g_qw2_l[CH4*CCH];
__device__ __nv_bfloat16 g_ew1_h[CCH*CH4], g_ew1_l[CCH*CH4];
__device__ __nv_bfloat16 g_ew2_h[CCH*CH4], g_ew2_l[CCH*CH4];
__device__ __nv_bfloat16 g_x_h[(size_t)NB*CCH*NPIX], g_x_l[(size_t)NB*CCH*NPIX];
__device__ __nv_bfloat16 g_qT_h[NB*NPIX*CR], g_qT_l[NB*NPIX*CR];
__device__ __nv_bfloat16 g_k_h[NB*CR*NPIX],  g_k_l[NB*CR*NPIX];
__device__ __nv_bfloat16 g_v_h[NB*CCH*NPIX], g_v_l[NB*CCH*NPIX];
__device__ __nv_bfloat16 g_at0_h[(size_t)NB*NPIX*NPIX], g_at0_l[(size_t)NB*NPIX*NPIX];
__device__ __nv_bfloat16 g_at1_h[(size_t)NB*NPIX*NPIX], g_at1_l[(size_t)NB*NPIX*NPIX];
__device__ __nv_bfloat16 g_at2_h[(size_t)NB*NPIX*NPIX], g_at2_l[(size_t)NB*NPIX*NPIX];
__device__ __nv_bfloat16 g_ci_h[(size_t)NB*KCONV*NPIX], g_ci_l[(size_t)NB*KCONV*NPIX];
__device__ __nv_bfloat16 g_b0_h[NB*CCH*NPIX], g_b0_l[NB*CCH*NPIX];
__device__ __nv_bfloat16 g_o1_h[NB*CCH*NPIX], g_o1_l[NB*CCH*NPIX];
__device__ __nv_bfloat16 g_qc_h[NB*CH4*NPIX], g_qc_l[NB*CH4*NPIX];
__device__ __nv_bfloat16 g_e2_h[NB*CH4*CCH],  g_e2_l[NB*CH4*CCH];
__device__ __nv_bfloat16 g_ac_h[NB*CCH*CCH],  g_ac_l[NB*CCH*CCH];
__device__ __nv_bfloat16 g_vc_h[NB*CCH*NPIX], g_vc_l[NB*CCH*NPIX];

// ---------------- reductions ----------------
__device__ __forceinline__ float warpMax(float v){
  #pragma unroll
  for (int o=16;o;o>>=1) v = fmaxf(v, __shfl_xor_sync(0xffffffffu, v, o));
  return v;
}
__device__ __forceinline__ float warpMin(float v){
  #pragma unroll
  for (int o=16;o;o>>=1) v = fminf(v, __shfl_xor_sync(0xffffffffu, v, o));
  return v;
}
__device__ __forceinline__ float warpSum(float v){
  #pragma unroll
  for (int o=16;o;o>>=1) v += __shfl_xor_sync(0xffffffffu, v, o);
  return v;
}
__device__ float blockMax(float v, float* sh){
  v = warpMax(v);
  if ((threadIdx.x & 31) == 0) sh[threadIdx.x >> 5] = v;
  __syncthreads();
  if (threadIdx.x < 32){
    float t = (threadIdx.x < (blockDim.x>>5)) ? sh[threadIdx.x] : -3.4e38f;
    t = warpMax(t);
    if (threadIdx.x == 0) sh[0] = t;
  }
  __syncthreads();
  float r = sh[0]; __syncthreads(); return r;
}
__device__ float blockMin(float v, float* sh){
  v = warpMin(v);
  if ((threadIdx.x & 31) == 0) sh[threadIdx.x >> 5] = v;
  __syncthreads();
  if (threadIdx.x < 32){
    float t = (threadIdx.x < (blockDim.x>>5)) ? sh[threadIdx.x] : 3.4e38f;
    t = warpMin(t);
    if (threadIdx.x == 0) sh[0] = t;
  }
  __syncthreads();
  float r = sh[0]; __syncthreads(); return r;
}
__device__ float blockSum(float v, float* sh){
  v = warpSum(v);
  if ((threadIdx.x & 31) == 0) sh[threadIdx.x >> 5] = v;
  __syncthreads();
  if (threadIdx.x < 32){
    float t = (threadIdx.x < (blockDim.x>>5)) ? sh[threadIdx.x] : 0.f;
    t = warpSum(t);
    if (threadIdx.x == 0) sh[0] = t;
  }
  __syncthreads();
  float r = sh[0]; __syncthreads(); return r;
}

// ---------------- helpers ----------------
__device__ __forceinline__ void mma_bf16(float* c, const uint32_t* a, const uint32_t* b){
  asm volatile("mma.sync.aligned.m16n8k16.row.col.f32.bf16.bf16.f32 "
    "{%0,%1,%2,%3}, {%4,%5,%6,%7}, {%8,%9}, {%0,%1,%2,%3};\n"
    : "+f"(c[0]), "+f"(c[1]), "+f"(c[2]), "+f"(c[3])
    : "r"(a[0]), "r"(a[1]), "r"(a[2]), "r"(a[3]), "r"(b[0]), "r"(b[1]));
}
__device__ __forceinline__ void ldsm_x4(uint32_t* r, uint32_t saddr){
  asm volatile("ldmatrix.sync.aligned.m8n8.x4.shared.b16 {%0,%1,%2,%3}, [%4];"
    : "=r"(r[0]), "=r"(r[1]), "=r"(r[2]), "=r"(r[3]) : "r"(saddr));
}
__device__ __forceinline__ void ldsm_x4t(uint32_t* r, uint32_t saddr){
  asm volatile("ldmatrix.sync.aligned.m8n8.x4.trans.shared.b16 {%0,%1,%2,%3}, [%4];"
    : "=r"(r[0]), "=r"(r[1]), "=r"(r[2]), "=r"(r[3]) : "r"(saddr));
}
__device__ __forceinline__ void cpasync16(void* dst, const void* src, int szbytes){
  uint32_t d = (uint32_t)__cvta_generic_to_shared(dst);
  asm volatile("cp.async.cg.shared.global [%0], [%1], 16, %2;\n"
               :: "r"(d), "l"(src), "r"(szbytes));
}
__device__ __forceinline__ void cp_commit(){ asm volatile("cp.async.commit_group;\n"); }
__device__ __forceinline__ void cp_wait0(){ asm volatile("cp.async.wait_group 0;\n"); }
__device__ __forceinline__ void cp_wait1(){ asm volatile("cp.async.wait_group 1;\n"); }

__device__ __forceinline__ void bsplit(float v, __nv_bfloat16& h, __nv_bfloat16& l){
  h = __float2bfloat16(v);
  l = __float2bfloat16(v - __bfloat162float(h));
}
__device__ __forceinline__ uint32_t bpack(__nv_bfloat16 a, __nv_bfloat16 b){
  return (uint32_t)__bfloat16_as_ushort(a) | ((uint32_t)__bfloat16_as_ushort(b) << 16);
}

// ---------------- BF16x3 tensor-core GEMM (ldmatrix, K-tile 32, 2-stage, split-K) ----------------
// A bf16 [M][K] row-major (hi/lo). BI: 0 = B bf16 [K][N] k-major; 2 = B bf16 [N][K] (NT).
// EPI: 0 fp32(+opt bias p0); 2 fp32 gamma*acc+res; 3 relu(acc*p0+p1)->fp32+split;
//      4 relu->split; 5 (+opt bias)->split; 6 (+bias)->transposed split (ldT);
//      7 fp32 partial store to Cm[blockIdx.z][M][N] (split-K).
// Block tile 128x128x32; N%128==0, (K/KS)%32==0. grid.z = NB*KS.
template<int BI, int EPI>
__global__ void __launch_bounds__(256,2) gemm3_kernel(
    const __nv_bfloat16* __restrict__ Ah, const __nv_bfloat16* __restrict__ Al, long sA,
    const __nv_bfloat16* __restrict__ Bh, const __nv_bfloat16* __restrict__ Bl, long sB,
    float* __restrict__ Cm, long sC,
    __nv_bfloat16* __restrict__ Dh, __nv_bfloat16* __restrict__ Dl, long sD,
    int M, int N, int K,
    const float* __restrict__ p0, const float* __restrict__ p1,
    const float* __restrict__ res, long sRes,
    const float* __restrict__ gamma, int ldT, int KS)
{
  constexpr int AROW = 40;
  constexpr int ABF  = 128*AROW;
  constexpr int ABYTES = 2*ABF*2;
  constexpr int BBF  = (BI==2) ? ABF : 32*136;
  constexpr int BBYTES = 2*BBF*2;
  constexpr int STAGEB = ABYTES + BBYTES;

  extern __shared__ char smc[];
  const uint32_t smem0 = (uint32_t)__cvta_generic_to_shared(smc);

  const int bz = blockIdx.z / KS;
  const int ksl = blockIdx.z - bz*KS;
  const int Kc = K / KS;
  const int k00 = ksl * Kc;

  Ah += (long)bz * sA;  Al += (long)bz * sA;
  Bh += (long)bz * sB;  Bl += (long)bz * sB;
  if (EPI == 7)      Cm += (long)blockIdx.z * ((long)M*N);
  else if (Cm)       Cm += (long)bz * sC;
  if (EPI >= 3 && EPI <= 6){ Dh += (long)bz * sD; Dl += (long)bz * sD; }
  if (EPI == 2) res += (long)bz * sRes;

  const int tid  = threadIdx.x;
  const int warp = tid >> 5;
  const int lane = tid & 31;
  const int g    = lane >> 2;
  const int ct   = lane & 3;
  const int warpM = warp >> 2;
  const int warpN = warp & 3;
  const int m0 = blockIdx.y * 128;
  const int n0 = blockIdx.x * 128;

  const int lo8 = lane & 7, b3 = (lane>>3)&1, b4 = (lane>>4)&1;
  const uint32_t aoff  = ((warpM*64 + lo8 + b3*8)*AROW + b4*8)*2;
  const uint32_t boff2 = ((warpN*32 + lo8 + b4*8)*AROW + b3*8)*2;
  const uint32_t boff0 = ((lo8 + b3*8)*136 + warpN*32 + b4*8)*2;

  float acc[4][4][4];
  #pragma unroll
  for (int i=0;i<4;i++)
    #pragma unroll
    for (int j=0;j<4;j++)
      #pragma unroll
      for (int c=0;c<4;c++) acc[i][j][c]=0.f;

  auto loadT = [&](int s, int k0){
    char* st = smc + s*STAGEB;
    __nv_bfloat16* Ahs = (__nv_bfloat16*)st;
    #pragma unroll
    for (int c = tid; c < 1024; c += 256){
      const __nv_bfloat16* base = (c < 512) ? Ah : Al;
      __nv_bfloat16* dst = Ahs + ((c < 512) ? 0 : ABF);
      int e = c & 511, row = e >> 2, q = e & 3;
      int gm = m0 + row;
      int sz = (gm < M) ? 16 : 0; if (gm >= M) gm = 0;
      cpasync16(dst + row*AROW + q*8, base + (long)gm*K + k0 + q*8, sz);
    }
    __nv_bfloat16* Bs = (__nv_bfloat16*)(st + ABYTES);
    if (BI == 2){
      #pragma unroll
      for (int c = tid; c < 1024; c += 256){
        const __nv_bfloat16* base = (c < 512) ? Bh : Bl;
        __nv_bfloat16* dst = Bs + ((c < 512) ? 0 : ABF);
        int e = c & 511, row = e >> 2, q = e & 3;
        cpasync16(dst + row*AROW + q*8, base + (long)(n0+row)*K + k0 + q*8, 16);
      }
    } else {
      #pragma unroll
      for (int c = tid; c < 1024; c += 256){
        const __nv_bfloat16* base = (c < 512) ? Bh : Bl;
        __nv_bfloat16* dst = Bs + ((c < 512) ? 0 : 32*136);
        int e = c & 511, row = e >> 4, ch = e & 15;
        cpasync16(dst + row*136 + ch*8, base + (long)(k0+row)*N + n0 + ch*8, 16);
      }
    }
  };

  const int T = Kc/32;
  loadT(0, k00); cp_commit();

  for (int i = 0; i < T; i++){
    if (i + 1 < T){ loadT((i+1)&1, k00 + (i+1)*32); cp_commit(); cp_wait1(); }
    else          { cp_wait0(); }
    __syncthreads();

    const uint32_t stb = smem0 + (uint32_t)((i&1)*STAGEB);
    const uint32_t bb  = stb + ABYTES;

    #pragma unroll
    for (int h = 0; h < 2; h++){
      const uint32_t aH = stb + aoff + h*32;
      const uint32_t aL = stb + ABF*2 + aoff + h*32;
      uint32_t ah[4][4], al[4][4], bhf[8], blf[8];
      #pragma unroll
      for (int mi=0; mi<4; mi++){
        ldsm_x4(ah[mi], aH + mi*(16*AROW*2));
        ldsm_x4(al[mi], aL + mi*(16*AROW*2));
      }
      if (BI == 2){
        const uint32_t bH = bb + boff2 + h*32;
        const uint32_t bL = bb + ABF*2 + boff2 + h*32;
        ldsm_x4(bhf,   bH);
        ldsm_x4(bhf+4, bH + 16*AROW*2);
        ldsm_x4(blf,   bL);
        ldsm_x4(blf+4, bL + 16*AROW*2);
      } else {
        const uint32_t bH = bb + boff0 + h*(16*136*2);
        const uint32_t bL = bb + 32*136*2 + boff0 + h*(16*136*2);
        ldsm_x4t(bhf,   bH);
        ldsm_x4t(bhf+4, bH + 16*2);
        ldsm_x4t(blf,   bL);
        ldsm_x4t(blf+4, bL + 16*2);
      }
      #pragma unroll
      for (int mi=0; mi<4; mi++)
        #pragma unroll
        for (int nj=0; nj<4; nj++){
          mma_bf16(acc[mi][nj], ah[mi], bhf + nj*2);
          mma_bf16(acc[mi][nj], ah[mi], blf + nj*2);
          mma_bf16(acc[mi][nj], al[mi], bhf + nj*2);
        }
    }
    __syncthreads();
  }

  // ---- epilogue
  #pragma unroll
  for (int mi=0; mi<4; mi++){
    int rr[2] = { m0 + warpM*64 + mi*16 + g, m0 + warpM*64 + mi*16 + g + 8 };
    float sc[2] = {0.f,0.f}, of[2] = {0.f,0.f};
    #pragma unroll
    for (int h=0; h<2; h++){
      if (rr[h] < M){
        if (EPI == 3 || EPI == 4){ sc[h] = p0[rr[h]]; of[h] = p1[rr[h]]; }
        else if (EPI == 0 || EPI == 5 || EPI == 6){ if (p0) of[h] = p0[rr[h]]; }
      }
    }
    #pragma unroll
    for (int nj=0; nj<4; nj++){
      int n = n0 + warpN*32 + nj*8 + 2*ct;
      #pragma unroll
      for (int h=0; h<2; h++){
        int r = rr[h];
        if (r >= M) continue;
        float wx = acc[mi][nj][2*h], wy = acc[mi][nj][2*h+1];
        if (EPI == 7){
          float2 w; w.x = wx; w.y = wy;
          *(float2*)&Cm[(long)r*N + n] = w;
          continue;
        }
        if (EPI == 0){ wx += of[h]; wy += of[h]; }
        else if (EPI == 2){
          float2 rv = *(const float2*)&res[(long)r*N + n];
          wx = gamma[0]*wx + rv.x; wy = gamma[0]*wy + rv.y;
        } else if (EPI == 3 || EPI == 4){
          wx = fmaxf(wx*sc[h] + of[h], 0.f);
          wy = fmaxf(wy*sc[h] + of[h], 0.f);
        } else { wx += of[h]; wy += of[h]; }
        if (EPI == 0 || EPI == 2 || EPI == 3){
          float2 w; w.x = wx; w.y = wy;
          *(float2*)&Cm[(long)r*N + n] = w;
        }
        if (EPI >= 3 && EPI <= 6){
          __nv_bfloat16 hx, lx, hy, ly;
          bsplit(wx, hx, lx); bsplit(wy, hy, ly);
          if (EPI == 6){
            Dh[(long)n*ldT + r] = hx;       Dl[(long)n*ldT + r] = lx;
            Dh[(long)(n+1)*ldT + r] = hy;   Dl[(long)(n+1)*ldT + r] = ly;
          } else {
            *(uint32_t*)&Dh[(long)r*N + n] = bpack(hx, hy);
            *(uint32_t*)&Dl[(long)r*N + n] = bpack(lx, ly);
          }
        }
      }
    }
  }
}

// ---------------- split-K finalize ----------------
// FM 0: +opt bias -> fp32 Cout; FM 4: relu(v*p0+p1) -> split; FM 5: +opt bias -> split;
// FM 6: +opt bias -> transposed split (ldT).
template<int FM>
__global__ __launch_bounds__(256) void fin_kernel(
    const float* __restrict__ P, int KS, int M, int N,
    const float* __restrict__ p0, const float* __restrict__ p1,
    float* __restrict__ Cout, __nv_bfloat16* __restrict__ Dh,
    __nv_bfloat16* __restrict__ Dl, int ldT)
{
  const long MN = (long)M*N;
  long total2 = (long)NB*M*(N/2);
  long w = (long)blockIdx.x*256 + threadIdx.x;
  if (w >= total2) return;
  int n2 = (int)(w % (N/2));
  long t = w / (N/2);
  int r = (int)(t % M);
  int b = (int)(t / M);
  long base = ((long)(b*KS))*MN + (long)r*N + 2*n2;
  float vx = 0.f, vy = 0.f;
  for (int ks = 0; ks < KS; ks++){
    float2 pv = *(const float2*)&P[base + (long)ks*MN];
    vx += pv.x; vy += pv.y;
  }
  if (FM == 0){
    float of = p0 ? p0[r] : 0.f;
    float2 o; o.x = vx + of; o.y = vy + of;
    *(float2*)&Cout[(long)b*MN + (long)r*N + 2*n2] = o;
  } else if (FM == 4){
    float scv = p0[r], of = p1[r];
    vx = fmaxf(vx*scv + of, 0.f); vy = fmaxf(vy*scv + of, 0.f);
    __nv_bfloat16 hx,lx,hy,ly; bsplit(vx,hx,lx); bsplit(vy,hy,ly);
    long o = (long)b*MN + (long)r*N + 2*n2;
    *(uint32_t*)&Dh[o] = bpack(hx,hy);
    *(uint32_t*)&Dl[o] = bpack(lx,ly);
  } else if (FM == 5){
    float of = p0 ? p0[r] : 0.f;
    vx += of; vy += of;
    __nv_bfloat16 hx,lx,hy,ly; bsplit(vx,hx,lx); bsplit(vy,hy,ly);
    long o = (long)b*MN + (long)r*N + 2*n2;
    *(uint32_t*)&Dh[o] = bpack(hx,hy);
    *(uint32_t*)&Dl[o] = bpack(lx,ly);
  } else {
    float of = p0 ? p0[r] : 0.f;
    vx += of; vy += of;
    __nv_bfloat16 hx,lx,hy,ly; bsplit(vx,hx,lx); bsplit(vy,hy,ly);
    long ob = (long)b*MN;
    int n = 2*n2;
    Dh[ob + (long)n*ldT + r] = hx;     Dl[ob + (long)n*ldT + r] = lx;
    Dh[ob + (long)(n+1)*ldT + r] = hy; Dl[ob + (long)(n+1)*ldT + r] = ly;
  }
}

// ---------------- fused softmax: one exp per element, all 3 variants ----------------
__global__ __launch_bounds__(288) void softmax_all_kernel(
    const float* __restrict__ E,
    const float* __restrict__ M1, const float* __restrict__ M2,
    __nv_bfloat16* __restrict__ a0h, __nv_bfloat16* __restrict__ a0l,
    __nv_bfloat16* __restrict__ a1h, __nv_bfloat16* __restrict__ a1l,
    __nv_bfloat16* __restrict__ a2h, __nv_bfloat16* __restrict__ a2l)
{
  __shared__ float sh[32];
  long row = blockIdx.x;
  int  mr  = (int)(row % NPIX);
  const float* e  = E  + row * NPIX;
  const float* m1 = M1 + (long)mr * NPIX;
  const float* m2 = M2 + (long)mr * NPIX;
  int tid = threadIdx.x;

  float ev[8], w1[8], w2[8];
  float mx = -3.4e38f;
  #pragma unroll
  for (int j = 0; j < 4; j++){
    int n = 2*(tid + j*288);
    float2 e2 = *(const float2*)&e[n];
    float2 u1 = *(const float2*)&m1[n];
    float2 u2 = *(const float2*)&m2[n];
    ev[2*j]=e2.x; ev[2*j+1]=e2.y;
    w1[2*j]=u1.x; w1[2*j+1]=u1.y;
    w2[2*j]=u2.x; w2[2*j+1]=u2.y;
    mx = fmaxf(mx, fmaxf(e2.x, e2.y));
  }
  mx = blockMax(mx, sh);

  float x0[8];
  float s0 = 0.f, s1 = 0.f, s2 = 0.f;
  #pragma unroll
  for (int i = 0; i < 8; i++){
    x0[i] = __expf(ev[i] - mx);
    s0 += x0[i];
    if (w1[i] > 0.f) s1 += x0[i];
    if (w2[i] > 0.f) s2 += x0[i];
  }
  s0 = blockSum(s0, sh);
  s1 = blockSum(s1, sh);
  s2 = blockSum(s2, sh);
  float r0 = 1.f/s0, r1 = 1.f/s1, r2 = 1.f/s2;

  #pragma unroll
  for (int j = 0; j < 4; j++){
    int n = 2*(tid + j*288);
    long o = row * NPIX + n;
    float px = x0[2*j], py = x0[2*j+1];
    __nv_bfloat16 hx, lx, hy, ly;
    bsplit(px*r0, hx, lx); bsplit(py*r0, hy, ly);
    *(uint32_t*)&a0h[o] = bpack(hx, hy);
    *(uint32_t*)&a0l[o] = bpack(lx, ly);
    float ax = (w1[2*j]   > 0.f) ? px*r1 : 0.f;
    float ay = (w1[2*j+1] > 0.f) ? py*r1 : 0.f;
    bsplit(ax, hx, lx); bsplit(ay, hy, ly);
    *(uint32_t*)&a1h[o] = bpack(hx, hy);
    *(uint32_t*)&a1l[o] = bpack(lx, ly);
    ax = (w2[2*j]   > 0.f) ? px*r2 : 0.f;
    ay = (w2[2*j+1] > 0.f) ? py*r2 : 0.f;
    bsplit(ax, hx, lx); bsplit(ay, hy, ly);
    *(uint32_t*)&a2h[o] = bpack(hx, hy);
    *(uint32_t*)&a2l[o] = bpack(lx, ly);
  }
}

// ---------------- chl softmax -> bf16 split ----------------
__global__ __launch_bounds__(256) void chl_softmax_kernel(
    const float* __restrict__ E, __nv_bfloat16* __restrict__ Ahd,
    __nv_bfloat16* __restrict__ Ald)
{
  __shared__ float sh[32];
  long row = blockIdx.x;
  const float* e = E + row * CCH;
  int tid = threadIdx.x;
  float v0 = e[tid], v1 = e[tid+256];
  float mn = blockMin(fminf(v0, v1), sh);
  float t0 = __expf(mn - v0), t1 = __expf(mn - v1);
  float s = blockSum(t0 + t1, sh);
  float rinv = 1.f/s;
  __nv_bfloat16 h,l;
  bsplit(t0*rinv, h, l); Ahd[row*CCH + tid]     = h; Ald[row*CCH + tid]     = l;
  bsplit(t1*rinv, h, l); Ahd[row*CCH + tid+256] = h; Ald[row*CCH + tid+256] = l;
}

// ---------------- im2col -> k-major bf16 split [KCONV][NPIX] ----------------
__global__ __launch_bounds__(256) void im2col_kernel(const float* __restrict__ X,
    __nv_bfloat16* __restrict__ Ch, __nv_bfloat16* __restrict__ Cl)
{
  const long total = (long)NB*KCONV*(NPIX/2);
  long w = (long)blockIdx.x * 256 + threadIdx.x;
  if (w >= total) return;
  int n2 = (int)(w % (NPIX/2));
  long t = w / (NPIX/2);
  int k  = (int)(t % KCONV);
  int b  = (int)(t / KCONV);
  int ic = k/9, kk = k - ic*9;
  int ky = kk/3, kx = kk - ky*3;
  const float* xs = X + ((long)(b*CCH + ic))*NPIX;
  float v[2];
  #pragma unroll
  for (int u=0; u<2; u++){
    int n = 2*n2 + u;
    int y = n/HW + ky - 1, x = n - (n/HW)*HW + kx - 1;
    v[u] = (y >= 0 && y < HW && x >= 0 && x < HW) ? xs[y*HW + x] : 0.f;
  }
  __nv_bfloat16 h0,l0,h1,l1;
  bsplit(v[0],h0,l0); bsplit(v[1],h1,l1);
  long o = ((long)(b*KCONV + k))*NPIX + 2*n2;
  *(uint32_t*)&Ch[o] = bpack(h0,h1);
  *(uint32_t*)&Cl[o] = bpack(l0,l1);
}

// ---------------- prepass: plain split ----------------
__global__ __launch_bounds__(256) void split_nat_kernel(const float* __restrict__ X,
    __nv_bfloat16* __restrict__ H, __nv_bfloat16* __restrict__ L, long total)
{
  for (long i = (long)blockIdx.x*256 + threadIdx.x; i < total; i += (long)gridDim.x*256){
    __nv_bfloat16 h,l; bsplit(X[i], h, l); H[i] = h; L[i] = l;
  }
}

// ---------------- host ----------------
template<int BI, int EPI>
static void rg(const __nv_bfloat16* Ah, const __nv_bfloat16* Al, long sA,
               const __nv_bfloat16* Bh, const __nv_bfloat16* Bl, long sB,
               float* C, long sC,
               __nv_bfloat16* Dh, __nv_bfloat16* Dl, long sD,
               int M, int N, int K,
               const float* p0, const float* p1,
               const float* res, long sRes, const float* gamma, int ldT, int KS = 1)
{
  constexpr int ABYTES = 2*128*40*2;
  constexpr int BBYTES = (BI==2) ? ABYTES : 2*32*136*2;
  constexpr int SMEM = 2*(ABYTES + BBYTES);
  cudaFuncSetAttribute(gemm3_kernel<BI,EPI>,
                       cudaFuncAttributeMaxDynamicSharedMemorySize, SMEM);
  dim3 grid(N/128, (M+127)/128, NB*KS);
  gemm3_kernel<BI,EPI><<<grid, 256, SMEM>>>(Ah, Al, sA, Bh, Bl, sB, C, sC,
                                            Dh, Dl, sD, M, N, K, p0, p1, res, sRes, gamma, ldT, KS);
}

template<typename T>
static T* sym(const void* s){ void* p = nullptr; cudaGetSymbolAddress(&p, s); return (T*)p; }

static int gsz(long t){ return (int)((t + 255)/256); }

template<int FM>
static void fin(const float* P, int KS, int M, int N,
                const float* p0, const float* p1,
                float* Cout, __nv_bfloat16* Dh, __nv_bfloat16* Dl, int ldT)
{
  long total2 = (long)NB*M*(N/2);
  fin_kernel<FM><<<gsz(total2), 256>>>(P, KS, M, N, p0, p1, Cout, Dh, Dl, ldT);
}

extern "C" void kernel_launch(void* const* d_in, const int* in_sizes, int n_in,
                              void* d_out, int out_size)
{
  const float* x       = (const float*)d_in[0];
  const float* wq      = (const float*)d_in[1];
  const float* bq      = (const float*)d_in[2];
  const float* wk      = (const float*)d_in[3];
  const float* bk      = (const float*)d_in[4];
  const float* wv0     = (const float*)d_in[5];
  const float* bv0     = (const float*)d_in[6];
  const float* conv1_w = (const float*)d_in[7];
  const float* conv1_s = (const float*)d_in[8];
  const float* conv1_b = (const float*)d_in[9];
  const float* conv2_w = (const float*)d_in[10];
  const float* conv2_s = (const float*)d_in[11];
  const float* conv2_b = (const float*)d_in[12];
  const float* gamma   = (const float*)d_in[13];
  const float* gamma1  = (const float*)d_in[14];
  const float* gamma2  = (const float*)d_in[15];
  const float* c1_qw   = (const float*)d_in[16];
  const float* c1_qs   = (const float*)d_in[17];
  const float* c1_qb   = (const float*)d_in[18];
  const float* c1_ew   = (const float*)d_in[19];
  const float* c1_eb   = (const float*)d_in[20];
  const float* c2_qw   = (const float*)d_in[21];
  const float* c2_qs   = (const float*)d_in[22];
  const float* c2_qb   = (const float*)d_in[23];
  const float* c2_ew   = (const float*)d_in[24];
  const float* c2_eb   = (const float*)d_in[25];
  const float* mask1   = (const float*)d_in[26];
  const float* mask2   = (const float*)d_in[27];

  typedef __nv_bfloat16 bf;
  float* E    = sym<float>(g_E);
  float* buf0 = sym<float>(g_buf0); float* buf1 = sym<float>(g_buf1);
  float* out1 = sym<float>(g_out1); float* expd = sym<float>(g_expd);
  float* part = sym<float>(g_part);
  bf *wq_h = sym<bf>(g_wq_h), *wq_l = sym<bf>(g_wq_l);
  bf *wk_h = sym<bf>(g_wk_h), *wk_l = sym<bf>(g_wk_l);
  bf *wv_h = sym<bf>(g_wv_h), *wv_l = sym<bf>(g_wv_l);
  bf *cw1_h = sym<bf>(g_cw1_h), *cw1_l = sym<bf>(g_cw1_l);
  bf *cw2_h = sym<bf>(g_cw2_h), *cw2_l = sym<bf>(g_cw2_l);
  bf *qw1_h = sym<bf>(g_qw1_h), *qw1_l = sym<bf>(g_qw1_l);
  bf *qw2_h = sym<bf>(g_qw2_h), *qw2_l = sym<bf>(g_qw2_l);
  bf *ew1_h = sym<bf>(g_ew1_h), *ew1_l = sym<bf>(g_ew1_l);
  bf *ew2_h = sym<bf>(g_ew2_h), *ew2_l = sym<bf>(g_ew2_l);
  bf *x_h = sym<bf>(g_x_h), *x_l = sym<bf>(g_x_l);
  bf *qT_h = sym<bf>(g_qT_h), *qT_l = sym<bf>(g_qT_l);
  bf *k_h  = sym<bf>(g_k_h),  *k_l  = sym<bf>(g_k_l);
  bf *v_h  = sym<bf>(g_v_h),  *v_l  = sym<bf>(g_v_l);
  bf *at0_h = sym<bf>(g_at0_h), *at0_l = sym<bf>(g_at0_l);
  bf *at1_h = sym<bf>(g_at1_h), *at1_l = sym<bf>(g_at1_l);
  bf *at2_h = sym<bf>(g_at2_h), *at2_l = sym<bf>(g_at2_l);
  bf *ci_h = sym<bf>(g_ci_h), *ci_l = sym<bf>(g_ci_l);
  bf *b0_h = sym<bf>(g_b0_h), *b0_l = sym<bf>(g_b0_l);
  bf *o1_h = sym<bf>(g_o1_h), *o1_l = sym<bf>(g_o1_l);
  bf *qc_h = sym<bf>(g_qc_h), *qc_l = sym<bf>(g_qc_l);
  bf *e2_h = sym<bf>(g_e2_h), *e2_l = sym<bf>(g_e2_l);
  bf *ac_h = sym<bf>(g_ac_h), *ac_l = sym<bf>(g_ac_l);
  bf *vc_h = sym<bf>(g_vc_h), *vc_l = sym<bf>(g_vc_l);
  float* out = (float*)d_out;

  const long sX  = (long)CCH*NPIX;
  const long sE  = (long)NPIX*NPIX;
  const long sCI = (long)KCONV*NPIX;
  const long sQT = (long)NPIX*CR;
  const long sK  = (long)CR*NPIX;
  const long sQC = (long)CH4*NPIX;
  const long sE2 = (long)CH4*CCH;
  const long sCC = (long)CCH*CCH;
  const int  R   = NB*NPIX;

  // ---- prepass splits needed for QKV ----
  split_nat_kernel<<<gsz(CR*CCH),256>>>(wq, wq_h, wq_l, CR*CCH);
  split_nat_kernel<<<gsz(CR*CCH),256>>>(wk, wk_h, wk_l, CR*CCH);
  split_nat_kernel<<<gsz(CCH*CCH),256>>>(wv0, wv_h, wv_l, CCH*CCH);
  split_nat_kernel<<<gsz((long)NB*sX),256>>>(x, x_h, x_l, (long)NB*sX);

  // ---- Q, K (split-K KS=4), V (full grid) ----
  rg<0,7>(wq_h, wq_l, 0, x_h, x_l, sX, part, 0, nullptr,nullptr,0,
          CR, NPIX, CCH, nullptr, nullptr, nullptr,0, nullptr, 0, 4);
  fin<6>(part, 4, CR, NPIX, bq, nullptr, nullptr, qT_h, qT_l, CR);
  rg<0,7>(wk_h, wk_l, 0, x_h, x_l, sX, part, 0, nullptr,nullptr,0,
          CR, NPIX, CCH, nullptr, nullptr, nullptr,0, nullptr, 0, 4);
  fin<5>(part, 4, CR, NPIX, bk, nullptr, nullptr, k_h, k_l, 0);
  rg<0,5>(wv_h, wv_l, 0, x_h, x_l, sX, nullptr,0, v_h, v_l, sX,
          CCH, NPIX, CCH, bv0, nullptr, nullptr,0, nullptr, 0);

  // ---- energy = qT * k ----
  rg<0,0>(qT_h, qT_l, sQT, k_h, k_l, sK, E, sE, nullptr,nullptr,0,
          NPIX, NPIX, CR, nullptr, nullptr, nullptr,0, nullptr, 0);

  // ---- remaining weight splits ----
  split_nat_kernel<<<gsz((long)CCH*KCONV),256>>>(conv1_w, cw1_h, cw1_l, (long)CCH*KCONV);
  split_nat_kernel<<<gsz((long)CCH*KCONV),256>>>(conv2_w, cw2_h, cw2_l, (long)CCH*KCONV);
  split_nat_kernel<<<gsz(CH4*CCH),256>>>(c1_qw, qw1_h, qw1_l, CH4*CCH);
  split_nat_kernel<<<gsz(CH4*CCH),256>>>(c2_qw, qw2_h, qw2_l, CH4*CCH);
  split_nat_kernel<<<gsz(CCH*CH4),256>>>(c1_ew, ew1_h, ew1_l, CCH*CH4);
  split_nat_kernel<<<gsz(CCH*CH4),256>>>(c2_ew, ew2_h, ew2_l, CCH*CH4);

  // ---- fused softmax ----
  softmax_all_kernel<<<R, 288>>>(E, mask1, mask2,
                                 at0_h, at0_l, at1_h, at1_l, at2_h, at2_l);

  // ---- pass 0 ----
  rg<2,2>(v_h, v_l, sX, at0_h, at0_l, sE, buf1, sX, nullptr,nullptr,0,
          CCH, NPIX, NPIX, nullptr, nullptr, (const float*)x, sX, gamma, 0);
  im2col_kernel<<<gsz((long)NB*KCONV*(NPIX/2)), 256>>>(buf1, ci_h, ci_l);
  rg<0,3>(cw1_h, cw1_l, 0, ci_h, ci_l, sCI, buf0, sX, b0_h, b0_l, sX,
          CCH, NPIX, KCONV, conv1_s, conv1_b, nullptr,0, nullptr, 0);

  // chl #1 (split-K on qc/e2/expand)
  rg<0,7>(qw1_h, qw1_l, 0, b0_h, b0_l, sX, part, 0, nullptr,nullptr,0,
          CH4, NPIX, CCH, nullptr, nullptr, nullptr,0, nullptr, 0, 4);
  fin<4>(part, 4, CH4, NPIX, c1_qs, c1_qb, nullptr, qc_h, qc_l, 0);
  rg<2,7>(qc_h, qc_l, sQC, b0_h, b0_l, sX, part, 0, nullptr,nullptr,0,
          CH4, CCH, NPIX, nullptr, nullptr, nullptr,0, nullptr, 0, 18);
  fin<5>(part, 18, CH4, CCH, nullptr, nullptr, nullptr, e2_h, e2_l, 0);
  rg<0,7>(ew1_h, ew1_l, 0, e2_h, e2_l, sE2, part, 0, nullptr,nullptr,0,
          CCH, CCH, CH4, nullptr, nullptr, nullptr,0, nullptr, 0, 4);
  fin<0>(part, 4, CCH, CCH, c1_eb, nullptr, expd, nullptr, nullptr, 0);
  chl_softmax_kernel<<<NB*CCH, 256>>>(expd, ac_h, ac_l);
  rg<0,5>(ac_h, ac_l, sCC, b0_h, b0_l, sX, nullptr,0, vc_h, vc_l, sX,
          CCH, NPIX, CCH, nullptr, nullptr, nullptr,0, nullptr, 0);

  // ---- pass 1 ----
  rg<2,2>(vc_h, vc_l, sX, at1_h, at1_l, sE, buf1, sX, nullptr,nullptr,0,
          CCH, NPIX, NPIX, nullptr, nullptr, buf0, sX, gamma1, 0);
  im2col_kernel<<<gsz((long)NB*KCONV*(NPIX/2)), 256>>>(buf1, ci_h, ci_l);
  rg<0,3>(cw2_h, cw2_l, 0, ci_h, ci_l, sCI, out1, sX, o1_h, o1_l, sX,
          CCH, NPIX, KCONV, conv2_s, conv2_b, nullptr,0, nullptr, 0);

  // chl #2
  rg<0,7>(qw2_h, qw2_l, 0, o1_h, o1_l, sX, part, 0, nullptr,nullptr,0,
          CH4, NPIX, CCH, nullptr, nullptr, nullptr,0, nullptr, 0, 4);
  fin<4>(part, 4, CH4, NPIX, c2_qs, c2_qb, nullptr, qc_h, qc_l, 0);
  rg<2,7>(qc_h, qc_l, sQC, o1_h, o1_l, sX, part, 0, nullptr,nullptr,0,
          CH4, CCH, NPIX, nullptr, nullptr, nullptr,0, nullptr, 0, 18);
  fin<5>(part, 18, CH4, CCH, nullptr, nullptr, nullptr, e2_h, e2_l, 0);
  rg<0,7>(ew2_h, ew2_l, 0, e2_h, e2_l, sE2, part, 0, nullptr,nullptr,0,
          CCH, CCH, CH4, nullptr, nullptr, nullptr,0, nullptr, 0, 4);
  fin<0>(part, 4, CCH, CCH, c2_eb, nullptr, expd, nullptr, nullptr, 0);
  chl_softmax_kernel<<<NB*CCH, 256>>>(expd, ac_h, ac_l);
  rg<0,5>(ac_h, ac_l, sCC, o1_h, o1_l, sX, nullptr,0, vc_h, vc_l, sX,
          CCH, NPIX, CCH, nullptr, nullptr, nullptr,0, nullptr, 0);

  // ---- pass 2 -> out ----
  rg<2,2>(vc_h, vc_l, sX, at2_h, at2_l, sE, out, sX, nullptr,nullptr,0,
          CCH, NPIX, NPIX, nullptr, nullptr, out1, sX, gamma2, 0);

  (void)in_sizes; (void)n_in; (void)out_size;
}

// round 13
// speedup vs baseline: 1.7602x; 1.3540x over previous
#include <cuda_runtime.h>
#include <cuda_bf16.h>
#include <cstdint>

#define NB   4
#define CCH  512
#define NPIX 2304
#define CR   64
#define CH4  128
#define HW   48
#define NT2  576            // 24*24 winograd tiles per image

// ---------------- fp32 scratch ----------------
__device__ float g_E[(size_t)NB*NPIX*NPIX];
__device__ float g_buf0[NB*CCH*NPIX];
__device__ float g_buf1[NB*CCH*NPIX];
__device__ float g_out1[NB*CCH*NPIX];
__device__ float g_expd[NB*CCH*CCH];
__device__ float g_part[4718592];                       // split-K partials
__device__ float g_M[(size_t)16*CCH*NPIX];              // winograd M planes (75MB)

// ---------------- bf16 split scratch ----------------
__device__ __nv_bfloat16 g_wq_h[CR*CCH],  g_wq_l[CR*CCH];
__device__ __nv_bfloat16 g_wk_h[CR*CCH],  g_wk_l[CR*CCH];
__device__ __nv_bfloat16 g_wv_h[CCH*CCH], g_wv_l[CCH*CCH];
__device__ __nv_bfloat16 g_ww1_h[(size_t)16*CCH*CCH], g_ww1_l[(size_t)16*CCH*CCH];
__device__ __nv_bfloat16 g_ww2_h[(size_t)16*CCH*CCH], g_ww2_l[(size_t)16*CCH*CCH];
__device__ __nv_bfloat16 g_din_h[(size_t)16*CCH*NPIX], g_din_l[(size_t)16*CCH*NPIX];
__device__ __nv_bfloat16 g_qw1_h[CH4*CCH], g_qw1_l[CH4*CCH];
__device__ __nv_bfloat16 g_qw2_h[CH4*CCH], g_qw2_l[CH4*CCH];
__device__ __nv_bfloat16 g_ew1_h[CCH*CH4], g_ew1_l[CCH*CH4];
__device__ __nv_bfloat16 g_ew2_h[CCH*CH4], g_ew2_l[CCH*CH4];
__device__ __nv_bfloat16 g_x_h[(size_t)NB*CCH*NPIX], g_x_l[(size_t)NB*CCH*NPIX];
__device__ __nv_bfloat16 g_qT_h[NB*NPIX*CR], g_qT_l[NB*NPIX*CR];
__device__ __nv_bfloat16 g_k_h[NB*CR*NPIX],  g_k_l[NB*CR*NPIX];
__device__ __nv_bfloat16 g_v_h[NB*CCH*NPIX], g_v_l[NB*CCH*NPIX];
__device__ __nv_bfloat16 g_at0_h[(size_t)NB*NPIX*NPIX], g_at0_l[(size_t)NB*NPIX*NPIX];
__device__ __nv_bfloat16 g_at1_h[(size_t)NB*NPIX*NPIX], g_at1_l[(size_t)NB*NPIX*NPIX];
__device__ __nv_bfloat16 g_at2_h[(size_t)NB*NPIX*NPIX], g_at2_l[(size_t)NB*NPIX*NPIX];
__device__ __nv_bfloat16 g_b0_h[NB*CCH*NPIX], g_b0_l[NB*CCH*NPIX];
__device__ __nv_bfloat16 g_o1_h[NB*CCH*NPIX], g_o1_l[NB*CCH*NPIX];
__device__ __nv_bfloat16 g_qc_h[NB*CH4*NPIX], g_qc_l[NB*CH4*NPIX];
__device__ __nv_bfloat16 g_e2_h[NB*CH4*CCH],  g_e2_l[NB*CH4*CCH];
__device__ __nv_bfloat16 g_ac_h[NB*CCH*CCH],  g_ac_l[NB*CCH*CCH];
__device__ __nv_bfloat16 g_vc_h[NB*CCH*NPIX], g_vc_l[NB*CCH*NPIX];

// ---------------- reductions ----------------
__device__ __forceinline__ float warpMax(float v){
  #pragma unroll
  for (int o=16;o;o>>=1) v = fmaxf(v, __shfl_xor_sync(0xffffffffu, v, o));
  return v;
}
__device__ __forceinline__ float warpMin(float v){
  #pragma unroll
  for (int o=16;o;o>>=1) v = fminf(v, __shfl_xor_sync(0xffffffffu, v, o));
  return v;
}
__device__ __forceinline__ float warpSum(float v){
  #pragma unroll
  for (int o=16;o;o>>=1) v += __shfl_xor_sync(0xffffffffu, v, o);
  return v;
}
__device__ float blockMax(float v, float* sh){
  v = warpMax(v);
  if ((threadIdx.x & 31) == 0) sh[threadIdx.x >> 5] = v;
  __syncthreads();
  if (threadIdx.x < 32){
    float t = (threadIdx.x < (blockDim.x>>5)) ? sh[threadIdx.x] : -3.4e38f;
    t = warpMax(t);
    if (threadIdx.x == 0) sh[0] = t;
  }
  __syncthreads();
  float r = sh[0]; __syncthreads(); return r;
}
__device__ float blockMin(float v, float* sh){
  v = warpMin(v);
  if ((threadIdx.x & 31) == 0) sh[threadIdx.x >> 5] = v;
  __syncthreads();
  if (threadIdx.x < 32){
    float t = (threadIdx.x < (blockDim.x>>5)) ? sh[threadIdx.x] : 3.4e38f;
    t = warpMin(t);
    if (threadIdx.x == 0) sh[0] = t;
  }
  __syncthreads();
  float r = sh[0]; __syncthreads(); return r;
}
__device__ float blockSum(float v, float* sh){
  v = warpSum(v);
  if ((threadIdx.x & 31) == 0) sh[threadIdx.x >> 5] = v;
  __syncthreads();
  if (threadIdx.x < 32){
    float t = (threadIdx.x < (blockDim.x>>5)) ? sh[threadIdx.x] : 0.f;
    t = warpSum(t);
    if (threadIdx.x == 0) sh[0] = t;
  }
  __syncthreads();
  float r = sh[0]; __syncthreads(); return r;
}

// ---------------- helpers ----------------
__device__ __forceinline__ void mma_bf16(float* c, const uint32_t* a, const uint32_t* b){
  asm volatile("mma.sync.aligned.m16n8k16.row.col.f32.bf16.bf16.f32 "
    "{%0,%1,%2,%3}, {%4,%5,%6,%7}, {%8,%9}, {%0,%1,%2,%3};\n"
    : "+f"(c[0]), "+f"(c[1]), "+f"(c[2]), "+f"(c[3])
    : "r"(a[0]), "r"(a[1]), "r"(a[2]), "r"(a[3]), "r"(b[0]), "r"(b[1]));
}
__device__ __forceinline__ void ldsm_x4(uint32_t* r, uint32_t saddr){
  asm volatile("ldmatrix.sync.aligned.m8n8.x4.shared.b16 {%0,%1,%2,%3}, [%4];"
    : "=r"(r[0]), "=r"(r[1]), "=r"(r[2]), "=r"(r[3]) : "r"(saddr));
}
__device__ __forceinline__ void ldsm_x4t(uint32_t* r, uint32_t saddr){
  asm volatile("ldmatrix.sync.aligned.m8n8.x4.trans.shared.b16 {%0,%1,%2,%3}, [%4];"
    : "=r"(r[0]), "=r"(r[1]), "=r"(r[2]), "=r"(r[3]) : "r"(saddr));
}
__device__ __forceinline__ void cpasync16(void* dst, const void* src, int szbytes){
  uint32_t d = (uint32_t)__cvta_generic_to_shared(dst);
  asm volatile("cp.async.cg.shared.global [%0], [%1], 16, %2;\n"
               :: "r"(d), "l"(src), "r"(szbytes));
}
__device__ __forceinline__ void cp_commit(){ asm volatile("cp.async.commit_group;\n"); }
__device__ __forceinline__ void cp_wait0(){ asm volatile("cp.async.wait_group 0;\n"); }
__device__ __forceinline__ void cp_wait1(){ asm volatile("cp.async.wait_group 1;\n"); }

__device__ __forceinline__ void bsplit(float v, __nv_bfloat16& h, __nv_bfloat16& l){
  h = __float2bfloat16(v);
  l = __float2bfloat16(v - __bfloat162float(h));
}
__device__ __forceinline__ uint32_t bpack(__nv_bfloat16 a, __nv_bfloat16 b){
  return (uint32_t)__bfloat16_as_ushort(a) | ((uint32_t)__bfloat16_as_ushort(b) << 16);
}

// ---------------- BF16x3 tensor-core GEMM (ldmatrix, K-tile 32, 2-stage, split-K) ----------------
// A bf16 [M][K] row-major (hi/lo). BI: 0 = B bf16 [K][N] k-major; 2 = B bf16 [N][K] (NT).
// EPI: 0 fp32(+opt bias p0); 2 fp32 gamma*acc+res; 4 relu->split; 5 (+opt bias)->split;
//      6 (+bias)->transposed split (ldT); 7 fp32 partial store (split-K).
// Block tile 128x128x32; N%128==0, (K/KS)%32==0. grid.z = NZ*KS.
template<int BI, int EPI>
__global__ void __launch_bounds__(256,2) gemm3_kernel(
    const __nv_bfloat16* __restrict__ Ah, const __nv_bfloat16* __restrict__ Al, long sA,
    const __nv_bfloat16* __restrict__ Bh, const __nv_bfloat16* __restrict__ Bl, long sB,
    float* __restrict__ Cm, long sC,
    __nv_bfloat16* __restrict__ Dh, __nv_bfloat16* __restrict__ Dl, long sD,
    int M, int N, int K,
    const float* __restrict__ p0, const float* __restrict__ p1,
    const float* __restrict__ res, long sRes,
    const float* __restrict__ gamma, int ldT, int KS)
{
  constexpr int AROW = 40;
  constexpr int ABF  = 128*AROW;
  constexpr int ABYTES = 2*ABF*2;
  constexpr int BBF  = (BI==2) ? ABF : 32*136;
  constexpr int BBYTES = 2*BBF*2;
  constexpr int STAGEB = ABYTES + BBYTES;

  extern __shared__ char smc[];
  const uint32_t smem0 = (uint32_t)__cvta_generic_to_shared(smc);

  const int bz = blockIdx.z / KS;
  const int ksl = blockIdx.z - bz*KS;
  const int Kc = K / KS;
  const int k00 = ksl * Kc;

  Ah += (long)bz * sA;  Al += (long)bz * sA;
  Bh += (long)bz * sB;  Bl += (long)bz * sB;
  if (EPI == 7)      Cm += (long)blockIdx.z * ((long)M*N);
  else if (Cm)       Cm += (long)bz * sC;
  if (EPI >= 3 && EPI <= 6){ Dh += (long)bz * sD; Dl += (long)bz * sD; }
  if (EPI == 2) res += (long)bz * sRes;

  const int tid  = threadIdx.x;
  const int warp = tid >> 5;
  const int lane = tid & 31;
  const int g    = lane >> 2;
  const int ct   = lane & 3;
  const int warpM = warp >> 2;
  const int warpN = warp & 3;
  const int m0 = blockIdx.y * 128;
  const int n0 = blockIdx.x * 128;

  const int lo8 = lane & 7, b3 = (lane>>3)&1, b4 = (lane>>4)&1;
  const uint32_t aoff  = ((warpM*64 + lo8 + b3*8)*AROW + b4*8)*2;
  const uint32_t boff2 = ((warpN*32 + lo8 + b4*8)*AROW + b3*8)*2;
  const uint32_t boff0 = ((lo8 + b3*8)*136 + warpN*32 + b4*8)*2;

  float acc[4][4][4];
  #pragma unroll
  for (int i=0;i<4;i++)
    #pragma unroll
    for (int j=0;j<4;j++)
      #pragma unroll
      for (int c=0;c<4;c++) acc[i][j][c]=0.f;

  auto loadT = [&](int s, int k0){
    char* st = smc + s*STAGEB;
    __nv_bfloat16* Ahs = (__nv_bfloat16*)st;
    #pragma unroll
    for (int c = tid; c < 1024; c += 256){
      const __nv_bfloat16* base = (c < 512) ? Ah : Al;
      __nv_bfloat16* dst = Ahs + ((c < 512) ? 0 : ABF);
      int e = c & 511, row = e >> 2, q = e & 3;
      int gm = m0 + row;
      int sz = (gm < M) ? 16 : 0; if (gm >= M) gm = 0;
      cpasync16(dst + row*AROW + q*8, base + (long)gm*K + k0 + q*8, sz);
    }
    __nv_bfloat16* Bs = (__nv_bfloat16*)(st + ABYTES);
    if (BI == 2){
      #pragma unroll
      for (int c = tid; c < 1024; c += 256){
        const __nv_bfloat16* base = (c < 512) ? Bh : Bl;
        __nv_bfloat16* dst = Bs + ((c < 512) ? 0 : ABF);
        int e = c & 511, row = e >> 2, q = e & 3;
        cpasync16(dst + row*AROW + q*8, base + (long)(n0+row)*K + k0 + q*8, 16);
      }
    } else {
      #pragma unroll
      for (int c = tid; c < 1024; c += 256){
        const __nv_bfloat16* base = (c < 512) ? Bh : Bl;
        __nv_bfloat16* dst = Bs + ((c < 512) ? 0 : 32*136);
        int e = c & 511, row = e >> 4, ch = e & 15;
        cpasync16(dst + row*136 + ch*8, base + (long)(k0+row)*N + n0 + ch*8, 16);
      }
    }
  };

  const int T = Kc/32;
  loadT(0, k00); cp_commit();

  for (int i = 0; i < T; i++){
    if (i + 1 < T){ loadT((i+1)&1, k00 + (i+1)*32); cp_commit(); cp_wait1(); }
    else          { cp_wait0(); }
    __syncthreads();

    const uint32_t stb = smem0 + (uint32_t)((i&1)*STAGEB);
    const uint32_t bb  = stb + ABYTES;

    #pragma unroll
    for (int h = 0; h < 2; h++){
      const uint32_t aH = stb + aoff + h*32;
      const uint32_t aL = stb + ABF*2 + aoff + h*32;
      uint32_t ah[4][4], al[4][4], bhf[8], blf[8];
      #pragma unroll
      for (int mi=0; mi<4; mi++){
        ldsm_x4(ah[mi], aH + mi*(16*AROW*2));
        ldsm_x4(al[mi], aL + mi*(16*AROW*2));
      }
      if (BI == 2){
        const uint32_t bH = bb + boff2 + h*32;
        const uint32_t bL = bb + ABF*2 + boff2 + h*32;
        ldsm_x4(bhf,   bH);
        ldsm_x4(bhf+4, bH + 16*AROW*2);
        ldsm_x4(blf,   bL);
        ldsm_x4(blf+4, bL + 16*AROW*2);
      } else {
        const uint32_t bH = bb + boff0 + h*(16*136*2);
        const uint32_t bL = bb + 32*136*2 + boff0 + h*(16*136*2);
        ldsm_x4t(bhf,   bH);
        ldsm_x4t(bhf+4, bH + 16*2);
        ldsm_x4t(blf,   bL);
        ldsm_x4t(blf+4, bL + 16*2);
      }
      #pragma unroll
      for (int mi=0; mi<4; mi++)
        #pragma unroll
        for (int nj=0; nj<4; nj++){
          mma_bf16(acc[mi][nj], ah[mi], bhf + nj*2);
          mma_bf16(acc[mi][nj], ah[mi], blf + nj*2);
          mma_bf16(acc[mi][nj], al[mi], bhf + nj*2);
        }
    }
    __syncthreads();
  }

  // ---- epilogue
  #pragma unroll
  for (int mi=0; mi<4; mi++){
    int rr[2] = { m0 + warpM*64 + mi*16 + g, m0 + warpM*64 + mi*16 + g + 8 };
    float sc[2] = {0.f,0.f}, of[2] = {0.f,0.f};
    #pragma unroll
    for (int h=0; h<2; h++){
      if (rr[h] < M){
        if (EPI == 4){ sc[h] = p0[rr[h]]; of[h] = p1[rr[h]]; }
        else if (EPI == 0 || EPI == 5 || EPI == 6){ if (p0) of[h] = p0[rr[h]]; }
      }
    }
    #pragma unroll
    for (int nj=0; nj<4; nj++){
      int n = n0 + warpN*32 + nj*8 + 2*ct;
      #pragma unroll
      for (int h=0; h<2; h++){
        int r = rr[h];
        if (r >= M) continue;
        float wx = acc[mi][nj][2*h], wy = acc[mi][nj][2*h+1];
        if (EPI == 7){
          float2 w; w.x = wx; w.y = wy;
          *(float2*)&Cm[(long)r*N + n] = w;
          continue;
        }
        if (EPI == 0){ wx += of[h]; wy += of[h]; }
        else if (EPI == 2){
          float2 rv = *(const float2*)&res[(long)r*N + n];
          wx = gamma[0]*wx + rv.x; wy = gamma[0]*wy + rv.y;
        } else if (EPI == 4){
          wx = fmaxf(wx*sc[h] + of[h], 0.f);
          wy = fmaxf(wy*sc[h] + of[h], 0.f);
        } else { wx += of[h]; wy += of[h]; }
        if (EPI == 0 || EPI == 2){
          float2 w; w.x = wx; w.y = wy;
          *(float2*)&Cm[(long)r*N + n] = w;
        }
        if (EPI >= 3 && EPI <= 6){
          __nv_bfloat16 hx, lx, hy, ly;
          bsplit(wx, hx, lx); bsplit(wy, hy, ly);
          if (EPI == 6){
            Dh[(long)n*ldT + r] = hx;       Dl[(long)n*ldT + r] = lx;
            Dh[(long)(n+1)*ldT + r] = hy;   Dl[(long)(n+1)*ldT + r] = ly;
          } else {
            *(uint32_t*)&Dh[(long)r*N + n] = bpack(hx, hy);
            *(uint32_t*)&Dl[(long)r*N + n] = bpack(lx, ly);
          }
        }
      }
    }
  }
}

// ---------------- split-K finalize ----------------
template<int FM>
__global__ __launch_bounds__(256) void fin_kernel(
    const float* __restrict__ P, int KS, int M, int N,
    const float* __restrict__ p0, const float* __restrict__ p1,
    float* __restrict__ Cout, __nv_bfloat16* __restrict__ Dh,
    __nv_bfloat16* __restrict__ Dl, int ldT)
{
  const long MN = (long)M*N;
  long total2 = (long)NB*M*(N/2);
  long w = (long)blockIdx.x*256 + threadIdx.x;
  if (w >= total2) return;
  int n2 = (int)(w % (N/2));
  long t = w / (N/2);
  int r = (int)(t % M);
  int b = (int)(t / M);
  long base = ((long)(b*KS))*MN + (long)r*N + 2*n2;
  float vx = 0.f, vy = 0.f;
  for (int ks = 0; ks < KS; ks++){
    float2 pv = *(const float2*)&P[base + (long)ks*MN];
    vx += pv.x; vy += pv.y;
  }
  if (FM == 0){
    float of = p0 ? p0[r] : 0.f;
    float2 o; o.x = vx + of; o.y = vy + of;
    *(float2*)&Cout[(long)b*MN + (long)r*N + 2*n2] = o;
  } else if (FM == 4){
    float scv = p0[r], of = p1[r];
    vx = fmaxf(vx*scv + of, 0.f); vy = fmaxf(vy*scv + of, 0.f);
    __nv_bfloat16 hx,lx,hy,ly; bsplit(vx,hx,lx); bsplit(vy,hy,ly);
    long o = (long)b*MN + (long)r*N + 2*n2;
    *(uint32_t*)&Dh[o] = bpack(hx,hy);
    *(uint32_t*)&Dl[o] = bpack(lx,ly);
  } else if (FM == 5){
    float of = p0 ? p0[r] : 0.f;
    vx += of; vy += of;
    __nv_bfloat16 hx,lx,hy,ly; bsplit(vx,hx,lx); bsplit(vy,hy,ly);
    long o = (long)b*MN + (long)r*N + 2*n2;
    *(uint32_t*)&Dh[o] = bpack(hx,hy);
    *(uint32_t*)&Dl[o] = bpack(lx,ly);
  } else {
    float of = p0 ? p0[r] : 0.f;
    vx += of; vy += of;
    __nv_bfloat16 hx,lx,hy,ly; bsplit(vx,hx,lx); bsplit(vy,hy,ly);
    long ob = (long)b*MN;
    int n = 2*n2;
    Dh[ob + (long)n*ldT + r] = hx;     Dl[ob + (long)n*ldT + r] = lx;
    Dh[ob + (long)(n+1)*ldT + r] = hy; Dl[ob + (long)(n+1)*ldT + r] = ly;
  }
}

// ---------------- winograd F(2x2,3x3) transforms ----------------
// weight: W' = G g G^T; planes [uv][oc][ic], split.
__global__ __launch_bounds__(256) void wino_wt_kernel(const float* __restrict__ Wsrc,
    __nv_bfloat16* __restrict__ Wh, __nv_bfloat16* __restrict__ Wl)
{
  int idx = blockIdx.x*256 + threadIdx.x;
  if (idx >= CCH*CCH) return;
  int ic = idx & (CCH-1);
  int oc = idx >> 9;
  const float* gp = Wsrc + ((long)oc*CCH + ic)*9;
  float gm[3][3];
  #pragma unroll
  for (int i=0;i<3;i++)
    #pragma unroll
    for (int j=0;j<3;j++) gm[i][j] = gp[i*3+j];
  float r[4][3];
  #pragma unroll
  for (int j=0;j<3;j++){
    r[0][j] = gm[0][j];
    r[1][j] = 0.5f*(gm[0][j]+gm[1][j]+gm[2][j]);
    r[2][j] = 0.5f*(gm[0][j]-gm[1][j]+gm[2][j]);
    r[3][j] = gm[2][j];
  }
  #pragma unroll
  for (int u=0;u<4;u++){
    float w0 = r[u][0];
    float w1 = 0.5f*(r[u][0]+r[u][1]+r[u][2]);
    float w2 = 0.5f*(r[u][0]-r[u][1]+r[u][2]);
    float w3 = r[u][2];
    float wv[4] = {w0,w1,w2,w3};
    #pragma unroll
    for (int v=0;v<4;v++){
      __nv_bfloat16 h,l; bsplit(wv[v],h,l);
      long o = ((long)(u*4+v)*CCH + oc)*CCH + ic;
      Wh[o] = h; Wl[o] = l;
    }
  }
}

// input: D' = B^T d B; planes [uv][ic][b*576+t] (k-major for GEMM B), split.
__global__ __launch_bounds__(256) void wino_in_kernel(const float* __restrict__ X,
    __nv_bfloat16* __restrict__ Dh, __nv_bfloat16* __restrict__ Dl)
{
  long w = (long)blockIdx.x*256 + threadIdx.x;
  const long total = (long)NB*CCH*NT2;
  if (w >= total) return;
  int t = (int)(w % NT2);
  long r = w / NT2;
  int c = (int)(r % CCH);
  int b = (int)(r / CCH);
  int ty = t / 24, tx = t - (t/24)*24;
  const float* xs = X + ((long)(b*CCH + c))*NPIX;
  float d[4][4];
  #pragma unroll
  for (int i=0;i<4;i++){
    int iy = 2*ty - 1 + i;
    #pragma unroll
    for (int j=0;j<4;j++){
      int ix = 2*tx - 1 + j;
      d[i][j] = (iy >= 0 && iy < HW && ix >= 0 && ix < HW) ? xs[iy*HW+ix] : 0.f;
    }
  }
  float tb[4][4];
  #pragma unroll
  for (int j=0;j<4;j++){
    tb[0][j] = d[0][j] - d[2][j];
    tb[1][j] = d[1][j] + d[2][j];
    tb[2][j] = d[2][j] - d[1][j];
    tb[3][j] = d[1][j] - d[3][j];
  }
  long nidx = (long)b*NT2 + t;
  #pragma unroll
  for (int i=0;i<4;i++){
    float D0 = tb[i][0] - tb[i][2];
    float D1 = tb[i][1] + tb[i][2];
    float D2 = tb[i][2] - tb[i][1];
    float D3 = tb[i][1] - tb[i][3];
    float Dv[4] = {D0,D1,D2,D3};
    #pragma unroll
    for (int j=0;j<4;j++){
      __nv_bfloat16 h,l; bsplit(Dv[j],h,l);
      long o = ((long)(i*4+j)*CCH + c)*NPIX + nidx;
      Dh[o] = h; Dl[o] = l;
    }
  }
}

// output: Y = A^T M A, BN+ReLU, write fp32 + split.
__global__ __launch_bounds__(256) void wino_out_kernel(const float* __restrict__ Mp,
    const float* __restrict__ scale, const float* __restrict__ bias,
    float* __restrict__ Y, __nv_bfloat16* __restrict__ Yh, __nv_bfloat16* __restrict__ Yl)
{
  const long MN = (long)CCH*NPIX;
  long w = (long)blockIdx.x*256 + threadIdx.x;
  const long total = (long)NB*CCH*NT2;
  if (w >= total) return;
  int t = (int)(w % NT2);
  long r = w / NT2;
  int oc = (int)(r % CCH);
  int b  = (int)(r / CCH);
  int ty = t / 24, tx = t - (t/24)*24;
  long base = (long)oc*NPIX + (long)b*NT2 + t;
  float m[4][4];
  #pragma unroll
  for (int u=0;u<4;u++)
    #pragma unroll
    for (int v=0;v<4;v++) m[u][v] = Mp[(long)(u*4+v)*MN + base];
  float s0[4], s1[4];
  #pragma unroll
  for (int v=0;v<4;v++){
    s0[v] = m[0][v] + m[1][v] + m[2][v];
    s1[v] = m[1][v] - m[2][v] - m[3][v];
  }
  float y00 = s0[0]+s0[1]+s0[2], y01 = s0[1]-s0[2]-s0[3];
  float y10 = s1[0]+s1[1]+s1[2], y11 = s1[1]-s1[2]-s1[3];
  float sc = scale[oc], bi = bias[oc];
  y00 = fmaxf(y00*sc+bi, 0.f); y01 = fmaxf(y01*sc+bi, 0.f);
  y10 = fmaxf(y10*sc+bi, 0.f); y11 = fmaxf(y11*sc+bi, 0.f);
  long ob = ((long)(b*CCH + oc))*NPIX;
  long p0i = ob + (2*ty)*HW + 2*tx;
  long p1i = ob + (2*ty+1)*HW + 2*tx;
  float2 w0; w0.x = y00; w0.y = y01;
  float2 w1; w1.x = y10; w1.y = y11;
  *(float2*)&Y[p0i] = w0;
  *(float2*)&Y[p1i] = w1;
  __nv_bfloat16 h0,l0,h1,l1;
  bsplit(y00,h0,l0); bsplit(y01,h1,l1);
  *(uint32_t*)&Yh[p0i] = bpack(h0,h1);
  *(uint32_t*)&Yl[p0i] = bpack(l0,l1);
  bsplit(y10,h0,l0); bsplit(y11,h1,l1);
  *(uint32_t*)&Yh[p1i] = bpack(h0,h1);
  *(uint32_t*)&Yl[p1i] = bpack(l0,l1);
}

// ---------------- fused softmax: one exp per element, all 3 variants ----------------
__global__ __launch_bounds__(288) void softmax_all_kernel(
    const float* __restrict__ E,
    const float* __restrict__ M1, const float* __restrict__ M2,
    __nv_bfloat16* __restrict__ a0h, __nv_bfloat16* __restrict__ a0l,
    __nv_bfloat16* __restrict__ a1h, __nv_bfloat16* __restrict__ a1l,
    __nv_bfloat16* __restrict__ a2h, __nv_bfloat16* __restrict__ a2l)
{
  __shared__ float sh[32];
  long row = blockIdx.x;
  int  mr  = (int)(row % NPIX);
  const float* e  = E  + row * NPIX;
  const float* m1 = M1 + (long)mr * NPIX;
  const float* m2 = M2 + (long)mr * NPIX;
  int tid = threadIdx.x;

  float ev[8], w1[8], w2[8];
  float mx = -3.4e38f;
  #pragma unroll
  for (int j = 0; j < 4; j++){
    int n = 2*(tid + j*288);
    float2 e2 = *(const float2*)&e[n];
    float2 u1 = *(const float2*)&m1[n];
    float2 u2 = *(const float2*)&m2[n];
    ev[2*j]=e2.x; ev[2*j+1]=e2.y;
    w1[2*j]=u1.x; w1[2*j+1]=u1.y;
    w2[2*j]=u2.x; w2[2*j+1]=u2.y;
    mx = fmaxf(mx, fmaxf(e2.x, e2.y));
  }
  mx = blockMax(mx, sh);

  float x0[8];
  float s0 = 0.f, s1 = 0.f, s2 = 0.f;
  #pragma unroll
  for (int i = 0; i < 8; i++){
    x0[i] = __expf(ev[i] - mx);
    s0 += x0[i];
    if (w1[i] > 0.f) s1 += x0[i];
    if (w2[i] > 0.f) s2 += x0[i];
  }
  s0 = blockSum(s0, sh);
  s1 = blockSum(s1, sh);
  s2 = blockSum(s2, sh);
  float r0 = 1.f/s0, r1 = 1.f/s1, r2 = 1.f/s2;

  #pragma unroll
  for (int j = 0; j < 4; j++){
    int n = 2*(tid + j*288);
    long o = row * NPIX + n;
    float px = x0[2*j], py = x0[2*j+1];
    __nv_bfloat16 hx, lx, hy, ly;
    bsplit(px*r0, hx, lx); bsplit(py*r0, hy, ly);
    *(uint32_t*)&a0h[o] = bpack(hx, hy);
    *(uint32_t*)&a0l[o] = bpack(lx, ly);
    float ax = (w1[2*j]   > 0.f) ? px*r1 : 0.f;
    float ay = (w1[2*j+1] > 0.f) ? py*r1 : 0.f;
    bsplit(ax, hx, lx); bsplit(ay, hy, ly);
    *(uint32_t*)&a1h[o] = bpack(hx, hy);
    *(uint32_t*)&a1l[o] = bpack(lx, ly);
    ax = (w2[2*j]   > 0.f) ? px*r2 : 0.f;
    ay = (w2[2*j+1] > 0.f) ? py*r2 : 0.f;
    bsplit(ax, hx, lx); bsplit(ay, hy, ly);
    *(uint32_t*)&a2h[o] = bpack(hx, hy);
    *(uint32_t*)&a2l[o] = bpack(lx, ly);
  }
}

// ---------------- chl softmax -> bf16 split ----------------
__global__ __launch_bounds__(256) void chl_softmax_kernel(
    const float* __restrict__ E, __nv_bfloat16* __restrict__ Ahd,
    __nv_bfloat16* __restrict__ Ald)
{
  __shared__ float sh[32];
  long row = blockIdx.x;
  const float* e = E + row * CCH;
  int tid = threadIdx.x;
  float v0 = e[tid], v1 = e[tid+256];
  float mn = blockMin(fminf(v0, v1), sh);
  float t0 = __expf(mn - v0), t1 = __expf(mn - v1);
  float s = blockSum(t0 + t1, sh);
  float rinv = 1.f/s;
  __nv_bfloat16 h,l;
  bsplit(t0*rinv, h, l); Ahd[row*CCH + tid]     = h; Ald[row*CCH + tid]     = l;
  bsplit(t1*rinv, h, l); Ahd[row*CCH + tid+256] = h; Ald[row*CCH + tid+256] = l;
}

// ---------------- prepass: plain split ----------------
__global__ __launch_bounds__(256) void split_nat_kernel(const float* __restrict__ X,
    __nv_bfloat16* __restrict__ H, __nv_bfloat16* __restrict__ L, long total)
{
  for (long i = (long)blockIdx.x*256 + threadIdx.x; i < total; i += (long)gridDim.x*256){
    __nv_bfloat16 h,l; bsplit(X[i], h, l); H[i] = h; L[i] = l;
  }
}

// ---------------- host ----------------
template<int BI, int EPI>
static void rg(const __nv_bfloat16* Ah, const __nv_bfloat16* Al, long sA,
               const __nv_bfloat16* Bh, const __nv_bfloat16* Bl, long sB,
               float* C, long sC,
               __nv_bfloat16* Dh, __nv_bfloat16* Dl, long sD,
               int M, int N, int K,
               const float* p0, const float* p1,
               const float* res, long sRes, const float* gamma, int ldT,
               int KS = 1, int NZ = NB)
{
  constexpr int ABYTES = 2*128*40*2;
  constexpr int BBYTES = (BI==2) ? ABYTES : 2*32*136*2;
  constexpr int SMEM = 2*(ABYTES + BBYTES);
  cudaFuncSetAttribute(gemm3_kernel<BI,EPI>,
                       cudaFuncAttributeMaxDynamicSharedMemorySize, SMEM);
  dim3 grid(N/128, (M+127)/128, NZ*KS);
  gemm3_kernel<BI,EPI><<<grid, 256, SMEM>>>(Ah, Al, sA, Bh, Bl, sB, C, sC,
                                            Dh, Dl, sD, M, N, K, p0, p1, res, sRes, gamma, ldT, KS);
}

template<typename T>
static T* sym(const void* s){ void* p = nullptr; cudaGetSymbolAddress(&p, s); return (T*)p; }

static int gsz(long t){ return (int)((t + 255)/256); }

template<int FM>
static void fin(const float* P, int KS, int M, int N,
                const float* p0, const float* p1,
                float* Cout, __nv_bfloat16* Dh, __nv_bfloat16* Dl, int ldT)
{
  long total2 = (long)NB*M*(N/2);
  fin_kernel<FM><<<gsz(total2), 256>>>(P, KS, M, N, p0, p1, Cout, Dh, Dl, ldT);
}

extern "C" void kernel_launch(void* const* d_in, const int* in_sizes, int n_in,
                              void* d_out, int out_size)
{
  const float* x       = (const float*)d_in[0];
  const float* wq      = (const float*)d_in[1];
  const float* bq      = (const float*)d_in[2];
  const float* wk      = (const float*)d_in[3];
  const float* bk      = (const float*)d_in[4];
  const float* wv0     = (const float*)d_in[5];
  const float* bv0     = (const float*)d_in[6];
  const float* conv1_w = (const float*)d_in[7];
  const float* conv1_s = (const float*)d_in[8];
  const float* conv1_b = (const float*)d_in[9];
  const float* conv2_w = (const float*)d_in[10];
  const float* conv2_s = (const float*)d_in[11];
  const float* conv2_b = (const float*)d_in[12];
  const float* gamma   = (const float*)d_in[13];
  const float* gamma1  = (const float*)d_in[14];
  const float* gamma2  = (const float*)d_in[15];
  const float* c1_qw   = (const float*)d_in[16];
  const float* c1_qs   = (const float*)d_in[17];
  const float* c1_qb   = (const float*)d_in[18];
  const float* c1_ew   = (const float*)d_in[19];
  const float* c1_eb   = (const float*)d_in[20];
  const float* c2_qw   = (const float*)d_in[21];
  const float* c2_qs   = (const float*)d_in[22];
  const float* c2_qb   = (const float*)d_in[23];
  const float* c2_ew   = (const float*)d_in[24];
  const float* c2_eb   = (const float*)d_in[25];
  const float* mask1   = (const float*)d_in[26];
  const float* mask2   = (const float*)d_in[27];

  typedef __nv_bfloat16 bf;
  float* E    = sym<float>(g_E);
  float* buf0 = sym<float>(g_buf0); float* buf1 = sym<float>(g_buf1);
  float* out1 = sym<float>(g_out1); float* expd = sym<float>(g_expd);
  float* part = sym<float>(g_part); float* Mw   = sym<float>(g_M);
  bf *wq_h = sym<bf>(g_wq_h), *wq_l = sym<bf>(g_wq_l);
  bf *wk_h = sym<bf>(g_wk_h), *wk_l = sym<bf>(g_wk_l);
  bf *wv_h = sym<bf>(g_wv_h), *wv_l = sym<bf>(g_wv_l);
  bf *ww1_h = sym<bf>(g_ww1_h), *ww1_l = sym<bf>(g_ww1_l);
  bf *ww2_h = sym<bf>(g_ww2_h), *ww2_l = sym<bf>(g_ww2_l);
  bf *din_h = sym<bf>(g_din_h), *din_l = sym<bf>(g_din_l);
  bf *qw1_h = sym<bf>(g_qw1_h), *qw1_l = sym<bf>(g_qw1_l);
  bf *qw2_h = sym<bf>(g_qw2_h), *qw2_l = sym<bf>(g_qw2_l);
  bf *ew1_h = sym<bf>(g_ew1_h), *ew1_l = sym<bf>(g_ew1_l);
  bf *ew2_h = sym<bf>(g_ew2_h), *ew2_l = sym<bf>(g_ew2_l);
  bf *x_h = sym<bf>(g_x_h), *x_l = sym<bf>(g_x_l);
  bf *qT_h = sym<bf>(g_qT_h), *qT_l = sym<bf>(g_qT_l);
  bf *k_h  = sym<bf>(g_k_h),  *k_l  = sym<bf>(g_k_l);
  bf *v_h  = sym<bf>(g_v_h),  *v_l  = sym<bf>(g_v_l);
  bf *at0_h = sym<bf>(g_at0_h), *at0_l = sym<bf>(g_at0_l);
  bf *at1_h = sym<bf>(g_at1_h), *at1_l = sym<bf>(g_at1_l);
  bf *at2_h = sym<bf>(g_at2_h), *at2_l = sym<bf>(g_at2_l);
  bf *b0_h = sym<bf>(g_b0_h), *b0_l = sym<bf>(g_b0_l);
  bf *o1_h = sym<bf>(g_o1_h), *o1_l = sym<bf>(g_o1_l);
  bf *qc_h = sym<bf>(g_qc_h), *qc_l = sym<bf>(g_qc_l);
  bf *e2_h = sym<bf>(g_e2_h), *e2_l = sym<bf>(g_e2_l);
  bf *ac_h = sym<bf>(g_ac_h), *ac_l = sym<bf>(g_ac_l);
  bf *vc_h = sym<bf>(g_vc_h), *vc_l = sym<bf>(g_vc_l);
  float* out = (float*)d_out;

  const long sX  = (long)CCH*NPIX;
  const long sE  = (long)NPIX*NPIX;
  const long sQT = (long)NPIX*CR;
  const long sK  = (long)CR*NPIX;
  const long sQC = (long)CH4*NPIX;
  const long sE2 = (long)CH4*CCH;
  const long sCC = (long)CCH*CCH;
  const long sWW = (long)CCH*CCH;      // per-uv weight plane
  const long sDI = (long)CCH*NPIX;     // per-uv data plane
  const int  R   = NB*NPIX;
  const long winoTot = (long)NB*CCH*NT2;

  // ---- prepass splits ----
  split_nat_kernel<<<gsz(CR*CCH),256>>>(wq, wq_h, wq_l, CR*CCH);
  split_nat_kernel<<<gsz(CR*CCH),256>>>(wk, wk_h, wk_l, CR*CCH);
  split_nat_kernel<<<gsz(CCH*CCH),256>>>(wv0, wv_h, wv_l, CCH*CCH);
  split_nat_kernel<<<gsz((long)NB*sX),256>>>(x, x_h, x_l, (long)NB*sX);

  // ---- Q, K (split-K KS=4), V ----
  rg<0,7>(wq_h, wq_l, 0, x_h, x_l, sX, part, 0, nullptr,nullptr,0,
          CR, NPIX, CCH, nullptr, nullptr, nullptr,0, nullptr, 0, 4);
  fin<6>(part, 4, CR, NPIX, bq, nullptr, nullptr, qT_h, qT_l, CR);
  rg<0,7>(wk_h, wk_l, 0, x_h, x_l, sX, part, 0, nullptr,nullptr,0,
          CR, NPIX, CCH, nullptr, nullptr, nullptr,0, nullptr, 0, 4);
  fin<5>(part, 4, CR, NPIX, bk, nullptr, nullptr, k_h, k_l, 0);
  rg<0,5>(wv_h, wv_l, 0, x_h, x_l, sX, nullptr,0, v_h, v_l, sX,
          CCH, NPIX, CCH, bv0, nullptr, nullptr,0, nullptr, 0);

  // ---- energy = qT * k ----
  rg<0,0>(qT_h, qT_l, sQT, k_h, k_l, sK, E, sE, nullptr,nullptr,0,
          NPIX, NPIX, CR, nullptr, nullptr, nullptr,0, nullptr, 0);

  // ---- remaining weight transforms/splits ----
  wino_wt_kernel<<<gsz(CCH*CCH),256>>>(conv1_w, ww1_h, ww1_l);
  wino_wt_kernel<<<gsz(CCH*CCH),256>>>(conv2_w, ww2_h, ww2_l);
  split_nat_kernel<<<gsz(CH4*CCH),256>>>(c1_qw, qw1_h, qw1_l, CH4*CCH);
  split_nat_kernel<<<gsz(CH4*CCH),256>>>(c2_qw, qw2_h, qw2_l, CH4*CCH);
  split_nat_kernel<<<gsz(CCH*CH4),256>>>(c1_ew, ew1_h, ew1_l, CCH*CH4);
  split_nat_kernel<<<gsz(CCH*CH4),256>>>(c2_ew, ew2_h, ew2_l, CCH*CH4);

  // ---- fused softmax ----
  softmax_all_kernel<<<R, 288>>>(E, mask1, mask2,
                                 at0_h, at0_l, at1_h, at1_l, at2_h, at2_l);

  // ---- pass 0 ----
  rg<2,2>(v_h, v_l, sX, at0_h, at0_l, sE, buf1, sX, nullptr,nullptr,0,
          CCH, NPIX, NPIX, nullptr, nullptr, (const float*)x, sX, gamma, 0);
  wino_in_kernel<<<gsz(winoTot),256>>>(buf1, din_h, din_l);
  rg<0,0>(ww1_h, ww1_l, sWW, din_h, din_l, sDI, Mw, sDI, nullptr,nullptr,0,
          CCH, NPIX, CCH, nullptr, nullptr, nullptr,0, nullptr, 0, 1, 16);
  wino_out_kernel<<<gsz(winoTot),256>>>(Mw, conv1_s, conv1_b, buf0, b0_h, b0_l);

  // chl #1 (split-K on qc/e2/expand)
  rg<0,7>(qw1_h, qw1_l, 0, b0_h, b0_l, sX, part, 0, nullptr,nullptr,0,
          CH4, NPIX, CCH, nullptr, nullptr, nullptr,0, nullptr, 0, 4);
  fin<4>(part, 4, CH4, NPIX, c1_qs, c1_qb, nullptr, qc_h, qc_l, 0);
  rg<2,7>(qc_h, qc_l, sQC, b0_h, b0_l, sX, part, 0, nullptr,nullptr,0,
          CH4, CCH, NPIX, nullptr, nullptr, nullptr,0, nullptr, 0, 18);
  fin<5>(part, 18, CH4, CCH, nullptr, nullptr, nullptr, e2_h, e2_l, 0);
  rg<0,7>(ew1_h, ew1_l, 0, e2_h, e2_l, sE2, part, 0, nullptr,nullptr,0,
          CCH, CCH, CH4, nullptr, nullptr, nullptr,0, nullptr, 0, 4);
  fin<0>(part, 4, CCH, CCH, c1_eb, nullptr, expd, nullptr, nullptr, 0);
  chl_softmax_kernel<<<NB*CCH, 256>>>(expd, ac_h, ac_l);
  rg<0,5>(ac_h, ac_l, sCC, b0_h, b0_l, sX, nullptr,0, vc_h, vc_l, sX,
          CCH, NPIX, CCH, nullptr, nullptr, nullptr,0, nullptr, 0);

  // ---- pass 1 ----
  rg<2,2>(vc_h, vc_l, sX, at1_h, at1_l, sE, buf1, sX, nullptr,nullptr,0,
          CCH, NPIX, NPIX, nullptr, nullptr, buf0, sX, gamma1, 0);
  wino_in_kernel<<<gsz(winoTot),256>>>(buf1, din_h, din_l);
  rg<0,0>(ww2_h, ww2_l, sWW, din_h, din_l, sDI, Mw, sDI, nullptr,nullptr,0,
          CCH, NPIX, CCH, nullptr, nullptr, nullptr,0, nullptr, 0, 1, 16);
  wino_out_kernel<<<gsz(winoTot),256>>>(Mw, conv2_s, conv2_b, out1, o1_h, o1_l);

  // chl #2
  rg<0,7>(qw2_h, qw2_l, 0, o1_h, o1_l, sX, part, 0, nullptr,nullptr,0,
          CH4, NPIX, CCH, nullptr, nullptr, nullptr,0, nullptr, 0, 4);
  fin<4>(part, 4, CH4, NPIX, c2_qs, c2_qb, nullptr, qc_h, qc_l, 0);
  rg<2,7>(qc_h, qc_l, sQC, o1_h, o1_l, sX, part, 0, nullptr,nullptr,0,
          CH4, CCH, NPIX, nullptr, nullptr, nullptr,0, nullptr, 0, 18);
  fin<5>(part, 18, CH4, CCH, nullptr, nullptr, nullptr, e2_h, e2_l, 0);
  rg<0,7>(ew2_h, ew2_l, 0, e2_h, e2_l, sE2, part, 0, nullptr,nullptr,0,
          CCH, CCH, CH4, nullptr, nullptr, nullptr,0, nullptr, 0, 4);
  fin<0>(part, 4, CCH, CCH, c2_eb, nullptr, expd, nullptr, nullptr, 0);
  chl_softmax_kernel<<<NB*CCH, 256>>>(expd, ac_h, ac_l);
  rg<0,5>(ac_h, ac_l, sCC, o1_h, o1_l, sX, nullptr,0, vc_h, vc_l, sX,
          CCH, NPIX, CCH, nullptr, nullptr, nullptr,0, nullptr, 0);

  // ---- pass 2 -> out ----
  rg<2,2>(vc_h, vc_l, sX, at2_h, at2_l, sE, out, sX, nullptr,nullptr,0,
          CCH, NPIX, NPIX, nullptr, nullptr, out1, sX, gamma2, 0);

  (void)in_sizes; (void)n_in; (void)out_size;
}

// round 15
// speedup vs baseline: 2.0690x; 1.1754x over previous
#include <cuda_runtime.h>
#include <cuda_bf16.h>
#include <cuda_fp16.h>
#include <cstdint>

#define NB   4
#define CCH  512
#define NPIX 2304
#define CR   64
#define CH4  128
#define HW   48
#define NT2  576            // 24*24 winograd tiles per image

// ---------------- fp32 scratch ----------------
__device__ float g_E[(size_t)NB*NPIX*NPIX];
__device__ float g_buf0[NB*CCH*NPIX];
__device__ float g_buf1[NB*CCH*NPIX];
__device__ float g_out1[NB*CCH*NPIX];
__device__ float g_expd[NB*CCH*CCH];
__device__ float g_part[4718592];                       // split-K partials
__device__ float g_M[(size_t)16*CCH*NPIX];              // winograd M planes

// ---------------- bf16 split scratch ----------------
__device__ __nv_bfloat16 g_wq_h[CR*CCH],  g_wq_l[CR*CCH];
__device__ __nv_bfloat16 g_wk_h[CR*CCH],  g_wk_l[CR*CCH];
__device__ __nv_bfloat16 g_wv_h[CCH*CCH], g_wv_l[CCH*CCH];
__device__ __nv_bfloat16 g_ww1_h[(size_t)16*CCH*CCH], g_ww1_l[(size_t)16*CCH*CCH];
__device__ __nv_bfloat16 g_ww2_h[(size_t)16*CCH*CCH], g_ww2_l[(size_t)16*CCH*CCH];
__device__ __nv_bfloat16 g_din_h[(size_t)16*CCH*NPIX], g_din_l[(size_t)16*CCH*NPIX];
__device__ __nv_bfloat16 g_qw1_h[CH4*CCH], g_qw1_l[CH4*CCH];
__device__ __nv_bfloat16 g_qw2_h[CH4*CCH], g_qw2_l[CH4*CCH];
__device__ __nv_bfloat16 g_ew1_h[CCH*CH4], g_ew1_l[CCH*CH4];
__device__ __nv_bfloat16 g_ew2_h[CCH*CH4], g_ew2_l[CCH*CH4];
__device__ __nv_bfloat16 g_x_h[(size_t)NB*CCH*NPIX], g_x_l[(size_t)NB*CCH*NPIX];
__device__ __nv_bfloat16 g_qT_h[NB*NPIX*CR], g_qT_l[NB*NPIX*CR];
__device__ __nv_bfloat16 g_k_h[NB*CR*NPIX],  g_k_l[NB*CR*NPIX];
__device__ __nv_bfloat16 g_b0_h[NB*CCH*NPIX], g_b0_l[NB*CCH*NPIX];
__device__ __nv_bfloat16 g_o1_h[NB*CCH*NPIX], g_o1_l[NB*CCH*NPIX];
__device__ __nv_bfloat16 g_qc_h[NB*CH4*NPIX], g_qc_l[NB*CH4*NPIX];
__device__ __nv_bfloat16 g_e2_h[NB*CH4*CCH],  g_e2_l[NB*CH4*CCH];

// ---------------- fp16 scratch (softmax-weight path) ----------------
__device__ __half g_v_h[NB*CCH*NPIX],  g_v_l[NB*CCH*NPIX];
__device__ __half g_vc_h[NB*CCH*NPIX], g_vc_l[NB*CCH*NPIX];
__device__ __half g_b0f_h[NB*CCH*NPIX], g_b0f_l[NB*CCH*NPIX];
__device__ __half g_o1f_h[NB*CCH*NPIX], g_o1f_l[NB*CCH*NPIX];
__device__ __half g_at0_h[(size_t)NB*NPIX*NPIX];
__device__ __half g_at1_h[(size_t)NB*NPIX*NPIX];
__device__ __half g_at2_h[(size_t)NB*NPIX*NPIX];
__device__ __half g_ac_h[NB*CCH*CCH];

// ---------------- reductions ----------------
__device__ __forceinline__ float warpMax(float v){
  #pragma unroll
  for (int o=16;o;o>>=1) v = fmaxf(v, __shfl_xor_sync(0xffffffffu, v, o));
  return v;
}
__device__ __forceinline__ float warpMin(float v){
  #pragma unroll
  for (int o=16;o;o>>=1) v = fminf(v, __shfl_xor_sync(0xffffffffu, v, o));
  return v;
}
__device__ __forceinline__ float warpSum(float v){
  #pragma unroll
  for (int o=16;o;o>>=1) v += __shfl_xor_sync(0xffffffffu, v, o);
  return v;
}
__device__ float blockMax(float v, float* sh){
  v = warpMax(v);
  if ((threadIdx.x & 31) == 0) sh[threadIdx.x >> 5] = v;
  __syncthreads();
  if (threadIdx.x < 32){
    float t = (threadIdx.x < (blockDim.x>>5)) ? sh[threadIdx.x] : -3.4e38f;
    t = warpMax(t);
    if (threadIdx.x == 0) sh[0] = t;
  }
  __syncthreads();
  float r = sh[0]; __syncthreads(); return r;
}
__device__ float blockMin(float v, float* sh){
  v = warpMin(v);
  if ((threadIdx.x & 31) == 0) sh[threadIdx.x >> 5] = v;
  __syncthreads();
  if (threadIdx.x < 32){
    float t = (threadIdx.x < (blockDim.x>>5)) ? sh[threadIdx.x] : 3.4e38f;
    t = warpMin(t);
    if (threadIdx.x == 0) sh[0] = t;
  }
  __syncthreads();
  float r = sh[0]; __syncthreads(); return r;
}
__device__ float blockSum(float v, float* sh){
  v = warpSum(v);
  if ((threadIdx.x & 31) == 0) sh[threadIdx.x >> 5] = v;
  __syncthreads();
  if (threadIdx.x < 32){
    float t = (threadIdx.x < (blockDim.x>>5)) ? sh[threadIdx.x] : 0.f;
    t = warpSum(t);
    if (threadIdx.x == 0) sh[0] = t;
  }
  __syncthreads();
  float r = sh[0]; __syncthreads(); return r;
}

// ---------------- type helpers ----------------
template<typename T> __device__ __forceinline__ void mma_t(float* c, const uint32_t* a, const uint32_t* b);
template<> __device__ __forceinline__ void mma_t<__nv_bfloat16>(float* c, const uint32_t* a, const uint32_t* b){
  asm volatile("mma.sync.aligned.m16n8k16.row.col.f32.bf16.bf16.f32 "
    "{%0,%1,%2,%3}, {%4,%5,%6,%7}, {%8,%9}, {%0,%1,%2,%3};\n"
    : "+f"(c[0]), "+f"(c[1]), "+f"(c[2]), "+f"(c[3])
    : "r"(a[0]), "r"(a[1]), "r"(a[2]), "r"(a[3]), "r"(b[0]), "r"(b[1]));
}
template<> __device__ __forceinline__ void mma_t<__half>(float* c, const uint32_t* a, const uint32_t* b){
  asm volatile("mma.sync.aligned.m16n8k16.row.col.f32.f16.f16.f32 "
    "{%0,%1,%2,%3}, {%4,%5,%6,%7}, {%8,%9}, {%0,%1,%2,%3};\n"
    : "+f"(c[0]), "+f"(c[1]), "+f"(c[2]), "+f"(c[3])
    : "r"(a[0]), "r"(a[1]), "r"(a[2]), "r"(a[3]), "r"(b[0]), "r"(b[1]));
}
__device__ __forceinline__ void ldsm_x4(uint32_t* r, uint32_t saddr){
  asm volatile("ldmatrix.sync.aligned.m8n8.x4.shared.b16 {%0,%1,%2,%3}, [%4];"
    : "=r"(r[0]), "=r"(r[1]), "=r"(r[2]), "=r"(r[3]) : "r"(saddr));
}
__device__ __forceinline__ void ldsm_x4t(uint32_t* r, uint32_t saddr){
  asm volatile("ldmatrix.sync.aligned.m8n8.x4.trans.shared.b16 {%0,%1,%2,%3}, [%4];"
    : "=r"(r[0]), "=r"(r[1]), "=r"(r[2]), "=r"(r[3]) : "r"(saddr));
}
__device__ __forceinline__ void cpasync16(void* dst, const void* src, int szbytes){
  uint32_t d = (uint32_t)__cvta_generic_to_shared(dst);
  asm volatile("cp.async.cg.shared.global [%0], [%1], 16, %2;\n"
               :: "r"(d), "l"(src), "r"(szbytes));
}
__device__ __forceinline__ void cp_commit(){ asm volatile("cp.async.commit_group;\n"); }
__device__ __forceinline__ void cp_wait0(){ asm volatile("cp.async.wait_group 0;\n"); }
__device__ __forceinline__ void cp_wait1(){ asm volatile("cp.async.wait_group 1;\n"); }

__device__ __forceinline__ void tsplit(float v, __nv_bfloat16& h, __nv_bfloat16& l){
  h = __float2bfloat16(v);
  l = __float2bfloat16(v - __bfloat162float(h));
}
__device__ __forceinline__ void tsplit(float v, __half& h, __half& l){
  h = __float2half_rn(v);
  l = __float2half_rn(v - __half2float(h));
}
__device__ __forceinline__ uint32_t tpack(__nv_bfloat16 a, __nv_bfloat16 b){
  return (uint32_t)__bfloat16_as_ushort(a) | ((uint32_t)__bfloat16_as_ushort(b) << 16);
}
__device__ __forceinline__ uint32_t tpack(__half a, __half b){
  return (uint32_t)__half_as_ushort(a) | ((uint32_t)__half_as_ushort(b) << 16);
}
__device__ __forceinline__ void bsplit(float v, __nv_bfloat16& h, __nv_bfloat16& l){ tsplit(v,h,l); }
__device__ __forceinline__ uint32_t bpack(__nv_bfloat16 a, __nv_bfloat16 b){ return tpack(a,b); }

// ---------------- tensor-core GEMM (typed, ldmatrix, K-tile 32, 2-stage, split-K) ----------------
// T = operand type (bf16/fp16), DT = split-output type.
// A T [M][K] row-major. BI: 0 = B [K][N] k-major; 2 = B [N][K] (NT).
// AL/BL: operand has a lo array.
// EPI: 0 fp32(+opt bias p0); 2 fp32 gamma*acc+res; 4 relu->split; 5 (+opt bias)->split;
//      6 (+bias)->transposed split (ldT); 7 fp32 partial store (split-K).
template<typename T, int BI, int EPI, int AL, int BL, typename DT>
__global__ void __launch_bounds__(256,2) gemm3_kernel(
    const T* __restrict__ Ah, const T* __restrict__ Al, long sA,
    const T* __restrict__ Bh, const T* __restrict__ Bl, long sB,
    float* __restrict__ Cm, long sC,
    DT* __restrict__ Dh, DT* __restrict__ Dl, long sD,
    int M, int N, int K,
    const float* __restrict__ p0, const float* __restrict__ p1,
    const float* __restrict__ res, long sRes,
    const float* __restrict__ gamma, int ldT, int KS)
{
  constexpr int AROW = 40;
  constexpr int ABF  = 128*AROW;
  constexpr int ABYTES = 2*ABF*2;
  constexpr int BBF  = (BI==2) ? ABF : 32*136;
  constexpr int BBYTES = 2*BBF*2;
  constexpr int STAGEB = ABYTES + BBYTES;

  extern __shared__ char smc[];
  const uint32_t smem0 = (uint32_t)__cvta_generic_to_shared(smc);

  const int bz = blockIdx.z / KS;
  const int ksl = blockIdx.z - bz*KS;
  const int Kc = K / KS;
  const int k00 = ksl * Kc;

  Ah += (long)bz * sA;  if (AL) Al += (long)bz * sA;
  Bh += (long)bz * sB;  if (BL) Bl += (long)bz * sB;
  if (EPI == 7)      Cm += (long)blockIdx.z * ((long)M*N);
  else if (Cm)       Cm += (long)bz * sC;
  if (EPI >= 3 && EPI <= 6){ Dh += (long)bz * sD; Dl += (long)bz * sD; }
  if (EPI == 2) res += (long)bz * sRes;

  const int tid  = threadIdx.x;
  const int warp = tid >> 5;
  const int lane = tid & 31;
  const int g    = lane >> 2;
  const int ct   = lane & 3;
  const int warpM = warp >> 2;
  const int warpN = warp & 3;
  const int m0 = blockIdx.y * 128;
  const int n0 = blockIdx.x * 128;

  const int lo8 = lane & 7, b3 = (lane>>3)&1, b4 = (lane>>4)&1;
  const uint32_t aoff  = ((warpM*64 + lo8 + b3*8)*AROW + b4*8)*2;
  const uint32_t boff2 = ((warpN*32 + lo8 + b4*8)*AROW + b3*8)*2;
  const uint32_t boff0 = ((lo8 + b3*8)*136 + warpN*32 + b4*8)*2;

  float acc[4][4][4];
  #pragma unroll
  for (int i=0;i<4;i++)
    #pragma unroll
    for (int j=0;j<4;j++)
      #pragma unroll
      for (int c=0;c<4;c++) acc[i][j][c]=0.f;

  auto loadT = [&](int s, int k0){
    char* st = smc + s*STAGEB;
    T* Ahs = (T*)st;
    constexpr int ACNT = AL ? 1024 : 512;
    #pragma unroll
    for (int c = tid; c < ACNT; c += 256){
      const T* base = (c < 512) ? Ah : Al;
      T* dst = Ahs + ((c < 512) ? 0 : ABF);
      int e = c & 511, row = e >> 2, q = e & 3;
      int gm = m0 + row;
      int sz = (gm < M) ? 16 : 0; if (gm >= M) gm = 0;
      cpasync16(dst + row*AROW + q*8, base + (long)gm*K + k0 + q*8, sz);
    }
    T* Bs = (T*)(st + ABYTES);
    constexpr int BCNT = BL ? 1024 : 512;
    if (BI == 2){
      #pragma unroll
      for (int c = tid; c < BCNT; c += 256){
        const T* base = (c < 512) ? Bh : Bl;
        T* dst = Bs + ((c < 512) ? 0 : ABF);
        int e = c & 511, row = e >> 2, q = e & 3;
        cpasync16(dst + row*AROW + q*8, base + (long)(n0+row)*K + k0 + q*8, 16);
      }
    } else {
      #pragma unroll
      for (int c = tid; c < BCNT; c += 256){
        const T* base = (c < 512) ? Bh : Bl;
        T* dst = Bs + ((c < 512) ? 0 : 32*136);
        int e = c & 511, row = e >> 4, ch = e & 15;
        cpasync16(dst + row*136 + ch*8, base + (long)(k0+row)*N + n0 + ch*8, 16);
      }
    }
  };

  const int T_ = Kc/32;
  loadT(0, k00); cp_commit();

  for (int i = 0; i < T_; i++){
    if (i + 1 < T_){ loadT((i+1)&1, k00 + (i+1)*32); cp_commit(); cp_wait1(); }
    else           { cp_wait0(); }
    __syncthreads();

    const uint32_t stb = smem0 + (uint32_t)((i&1)*STAGEB);
    const uint32_t bb  = stb + ABYTES;

    #pragma unroll
    for (int h = 0; h < 2; h++){
      const uint32_t aH = stb + aoff + h*32;
      const uint32_t aL = stb + ABF*2 + aoff + h*32;
      uint32_t ah[4][4], al[4][4], bhf[8], blf[8];
      #pragma unroll
      for (int mi=0; mi<4; mi++){
        ldsm_x4(ah[mi], aH + mi*(16*AROW*2));
        if (AL) ldsm_x4(al[mi], aL + mi*(16*AROW*2));
      }
      if (BI == 2){
        const uint32_t bH = bb + boff2 + h*32;
        const uint32_t bL = bb + ABF*2 + boff2 + h*32;
        ldsm_x4(bhf,   bH);
        ldsm_x4(bhf+4, bH + 16*AROW*2);
        if (BL){
          ldsm_x4(blf,   bL);
          ldsm_x4(blf+4, bL + 16*AROW*2);
        }
      } else {
        const uint32_t bH = bb + boff0 + h*(16*136*2);
        const uint32_t bL = bb + 32*136*2 + boff0 + h*(16*136*2);
        ldsm_x4t(bhf,   bH);
        ldsm_x4t(bhf+4, bH + 16*2);
        if (BL){
          ldsm_x4t(blf,   bL);
          ldsm_x4t(blf+4, bL + 16*2);
        }
      }
      #pragma unroll
      for (int mi=0; mi<4; mi++)
        #pragma unroll
        for (int nj=0; nj<4; nj++){
          mma_t<T>(acc[mi][nj], ah[mi], bhf + nj*2);
          if (BL) mma_t<T>(acc[mi][nj], ah[mi], blf + nj*2);
          if (AL) mma_t<T>(acc[mi][nj], al[mi], bhf + nj*2);
        }
    }
    __syncthreads();
  }

  // ---- epilogue
  #pragma unroll
  for (int mi=0; mi<4; mi++){
    int rr[2] = { m0 + warpM*64 + mi*16 + g, m0 + warpM*64 + mi*16 + g + 8 };
    float sc[2] = {0.f,0.f}, of[2] = {0.f,0.f};
    #pragma unroll
    for (int h=0; h<2; h++){
      if (rr[h] < M){
        if (EPI == 4){ sc[h] = p0[rr[h]]; of[h] = p1[rr[h]]; }
        else if (EPI == 0 || EPI == 5 || EPI == 6){ if (p0) of[h] = p0[rr[h]]; }
      }
    }
    #pragma unroll
    for (int nj=0; nj<4; nj++){
      int n = n0 + warpN*32 + nj*8 + 2*ct;
      #pragma unroll
      for (int h=0; h<2; h++){
        int r = rr[h];
        if (r >= M) continue;
        float wx = acc[mi][nj][2*h], wy = acc[mi][nj][2*h+1];
        if (EPI == 7){
          float2 w; w.x = wx; w.y = wy;
          *(float2*)&Cm[(long)r*N + n] = w;
          continue;
        }
        if (EPI == 0){ wx += of[h]; wy += of[h]; }
        else if (EPI == 2){
          float2 rv = *(const float2*)&res[(long)r*N + n];
          wx = gamma[0]*wx + rv.x; wy = gamma[0]*wy + rv.y;
        } else if (EPI == 4){
          wx = fmaxf(wx*sc[h] + of[h], 0.f);
          wy = fmaxf(wy*sc[h] + of[h], 0.f);
        } else { wx += of[h]; wy += of[h]; }
        if (EPI == 0 || EPI == 2){
          float2 w; w.x = wx; w.y = wy;
          *(float2*)&Cm[(long)r*N + n] = w;
        }
        if (EPI >= 3 && EPI <= 6){
          DT hx, lx, hy, ly;
          tsplit(wx, hx, lx); tsplit(wy, hy, ly);
          if (EPI == 6){
            Dh[(long)n*ldT + r] = hx;       Dl[(long)n*ldT + r] = lx;
            Dh[(long)(n+1)*ldT + r] = hy;   Dl[(long)(n+1)*ldT + r] = ly;
          } else {
            *(uint32_t*)&Dh[(long)r*N + n] = tpack(hx, hy);
            *(uint32_t*)&Dl[(long)r*N + n] = tpack(lx, ly);
          }
        }
      }
    }
  }
}

// ---------------- split-K finalize (bf16 outputs) ----------------
template<int FM>
__global__ __launch_bounds__(256) void fin_kernel(
    const float* __restrict__ P, int KS, int M, int N,
    const float* __restrict__ p0, const float* __restrict__ p1,
    float* __restrict__ Cout, __nv_bfloat16* __restrict__ Dh,
    __nv_bfloat16* __restrict__ Dl, int ldT)
{
  const long MN = (long)M*N;
  long total2 = (long)NB*M*(N/2);
  long w = (long)blockIdx.x*256 + threadIdx.x;
  if (w >= total2) return;
  int n2 = (int)(w % (N/2));
  long t = w / (N/2);
  int r = (int)(t % M);
  int b = (int)(t / M);
  long base = ((long)(b*KS))*MN + (long)r*N + 2*n2;
  float vx = 0.f, vy = 0.f;
  for (int ks = 0; ks < KS; ks++){
    float2 pv = *(const float2*)&P[base + (long)ks*MN];
    vx += pv.x; vy += pv.y;
  }
  if (FM == 0){
    float of = p0 ? p0[r] : 0.f;
    float2 o; o.x = vx + of; o.y = vy + of;
    *(float2*)&Cout[(long)b*MN + (long)r*N + 2*n2] = o;
  } else if (FM == 4){
    float scv = p0[r], of = p1[r];
    vx = fmaxf(vx*scv + of, 0.f); vy = fmaxf(vy*scv + of, 0.f);
    __nv_bfloat16 hx,lx,hy,ly; bsplit(vx,hx,lx); bsplit(vy,hy,ly);
    long o = (long)b*MN + (long)r*N + 2*n2;
    *(uint32_t*)&Dh[o] = bpack(hx,hy);
    *(uint32_t*)&Dl[o] = bpack(lx,ly);
  } else if (FM == 5){
    float of = p0 ? p0[r] : 0.f;
    vx += of; vy += of;
    __nv_bfloat16 hx,lx,hy,ly; bsplit(vx,hx,lx); bsplit(vy,hy,ly);
    long o = (long)b*MN + (long)r*N + 2*n2;
    *(uint32_t*)&Dh[o] = bpack(hx,hy);
    *(uint32_t*)&Dl[o] = bpack(lx,ly);
  } else {
    float of = p0 ? p0[r] : 0.f;
    vx += of; vy += of;
    __nv_bfloat16 hx,lx,hy,ly; bsplit(vx,hx,lx); bsplit(vy,hy,ly);
    long ob = (long)b*MN;
    int n = 2*n2;
    Dh[ob + (long)n*ldT + r] = hx;     Dl[ob + (long)n*ldT + r] = lx;
    Dh[ob + (long)(n+1)*ldT + r] = hy; Dl[ob + (long)(n+1)*ldT + r] = ly;
  }
}

// ---------------- winograd F(2x2,3x3) transforms ----------------
__global__ __launch_bounds__(256) void wino_wt_kernel(const float* __restrict__ Wsrc,
    __nv_bfloat16* __restrict__ Wh, __nv_bfloat16* __restrict__ Wl)
{
  int idx = blockIdx.x*256 + threadIdx.x;
  if (idx >= CCH*CCH) return;
  int ic = idx & (CCH-1);
  int oc = idx >> 9;
  const float* gp = Wsrc + ((long)oc*CCH + ic)*9;
  float gm[3][3];
  #pragma unroll
  for (int i=0;i<3;i++)
    #pragma unroll
    for (int j=0;j<3;j++) gm[i][j] = gp[i*3+j];
  float r[4][3];
  #pragma unroll
  for (int j=0;j<3;j++){
    r[0][j] = gm[0][j];
    r[1][j] = 0.5f*(gm[0][j]+gm[1][j]+gm[2][j]);
    r[2][j] = 0.5f*(gm[0][j]-gm[1][j]+gm[2][j]);
    r[3][j] = gm[2][j];
  }
  #pragma unroll
  for (int u=0;u<4;u++){
    float w0 = r[u][0];
    float w1 = 0.5f*(r[u][0]+r[u][1]+r[u][2]);
    float w2 = 0.5f*(r[u][0]-r[u][1]+r[u][2]);
    float w3 = r[u][2];
    float wv[4] = {w0,w1,w2,w3};
    #pragma unroll
    for (int v=0;v<4;v++){
      __nv_bfloat16 h,l; bsplit(wv[v],h,l);
      long o = ((long)(u*4+v)*CCH + oc)*CCH + ic;
      Wh[o] = h; Wl[o] = l;
    }
  }
}

__global__ __launch_bounds__(256) void wino_in_kernel(const float* __restrict__ X,
    __nv_bfloat16* __restrict__ Dh, __nv_bfloat16* __restrict__ Dl)
{
  long w = (long)blockIdx.x*256 + threadIdx.x;
  const long total = (long)NB*CCH*NT2;
  if (w >= total) return;
  int t = (int)(w % NT2);
  long r = w / NT2;
  int c = (int)(r % CCH);
  int b = (int)(r / CCH);
  int ty = t / 24, tx = t - (t/24)*24;
  const float* xs = X + ((long)(b*CCH + c))*NPIX;
  float d[4][4];
  #pragma unroll
  for (int i=0;i<4;i++){
    int iy = 2*ty - 1 + i;
    #pragma unroll
    for (int j=0;j<4;j++){
      int ix = 2*tx - 1 + j;
      d[i][j] = (iy >= 0 && iy < HW && ix >= 0 && ix < HW) ? xs[iy*HW+ix] : 0.f;
    }
  }
  float tb[4][4];
  #pragma unroll
  for (int j=0;j<4;j++){
    tb[0][j] = d[0][j] - d[2][j];
    tb[1][j] = d[1][j] + d[2][j];
    tb[2][j] = d[2][j] - d[1][j];
    tb[3][j] = d[1][j] - d[3][j];
  }
  long nidx = (long)b*NT2 + t;
  #pragma unroll
  for (int i=0;i<4;i++){
    float D0 = tb[i][0] - tb[i][2];
    float D1 = tb[i][1] + tb[i][2];
    float D2 = tb[i][2] - tb[i][1];
    float D3 = tb[i][1] - tb[i][3];
    float Dv[4] = {D0,D1,D2,D3};
    #pragma unroll
    for (int j=0;j<4;j++){
      __nv_bfloat16 h,l; bsplit(Dv[j],h,l);
      long o = ((long)(i*4+j)*CCH + c)*NPIX + nidx;
      Dh[o] = h; Dl[o] = l;
    }
  }
}

// output transform: Y = A^T M A, BN+ReLU; fp32 + bf16 split + fp16 split.
__global__ __launch_bounds__(256) void wino_out_kernel(const float* __restrict__ Mp,
    const float* __restrict__ scale, const float* __restrict__ bias,
    float* __restrict__ Y, __nv_bfloat16* __restrict__ Yh, __nv_bfloat16* __restrict__ Yl,
    __half* __restrict__ Fh, __half* __restrict__ Fl)
{
  const long MN = (long)CCH*NPIX;
  long w = (long)blockIdx.x*256 + threadIdx.x;
  const long total = (long)NB*CCH*NT2;
  if (w >= total) return;
  int t = (int)(w % NT2);
  long r = w / NT2;
  int oc = (int)(r % CCH);
  int b  = (int)(r / CCH);
  int ty = t / 24, tx = t - (t/24)*24;
  long base = (long)oc*NPIX + (long)b*NT2 + t;
  float m[4][4];
  #pragma unroll
  for (int u=0;u<4;u++)
    #pragma unroll
    for (int v=0;v<4;v++) m[u][v] = Mp[(long)(u*4+v)*MN + base];
  float s0[4], s1[4];
  #pragma unroll
  for (int v=0;v<4;v++){
    s0[v] = m[0][v] + m[1][v] + m[2][v];
    s1[v] = m[1][v] - m[2][v] - m[3][v];
  }
  float y00 = s0[0]+s0[1]+s0[2], y01 = s0[1]-s0[2]-s0[3];
  float y10 = s1[0]+s1[1]+s1[2], y11 = s1[1]-s1[2]-s1[3];
  float sc = scale[oc], bi = bias[oc];
  y00 = fmaxf(y00*sc+bi, 0.f); y01 = fmaxf(y01*sc+bi, 0.f);
  y10 = fmaxf(y10*sc+bi, 0.f); y11 = fmaxf(y11*sc+bi, 0.f);
  long ob = ((long)(b*CCH + oc))*NPIX;
  long p0i = ob + (2*ty)*HW + 2*tx;
  long p1i = ob + (2*ty+1)*HW + 2*tx;
  float2 w0; w0.x = y00; w0.y = y01;
  float2 w1; w1.x = y10; w1.y = y11;
  *(float2*)&Y[p0i] = w0;
  *(float2*)&Y[p1i] = w1;
  __nv_bfloat16 h0,l0,h1,l1;
  bsplit(y00,h0,l0); bsplit(y01,h1,l1);
  *(uint32_t*)&Yh[p0i] = bpack(h0,h1);
  *(uint32_t*)&Yl[p0i] = bpack(l0,l1);
  bsplit(y10,h0,l0); bsplit(y11,h1,l1);
  *(uint32_t*)&Yh[p1i] = bpack(h0,h1);
  *(uint32_t*)&Yl[p1i] = bpack(l0,l1);
  __half f0,g0,f1,g1;
  tsplit(y00,f0,g0); tsplit(y01,f1,g1);
  *(uint32_t*)&Fh[p0i] = tpack(f0,f1);
  *(uint32_t*)&Fl[p0i] = tpack(g0,g1);
  tsplit(y10,f0,g0); tsplit(y11,f1,g1);
  *(uint32_t*)&Fh[p1i] = tpack(f0,f1);
  *(uint32_t*)&Fl[p1i] = tpack(g0,g1);
}

// ---------------- fused softmax: one exp per element, all 3 variants (fp16 out) ----------------
__global__ __launch_bounds__(288) void softmax_all_kernel(
    const float* __restrict__ E,
    const float* __restrict__ M1, const float* __restrict__ M2,
    __half* __restrict__ a0h, __half* __restrict__ a1h, __half* __restrict__ a2h)
{
  __shared__ float sh[32];
  long row = blockIdx.x;
  int  mr  = (int)(row % NPIX);
  const float* e  = E  + row * NPIX;
  const float* m1 = M1 + (long)mr * NPIX;
  const float* m2 = M2 + (long)mr * NPIX;
  int tid = threadIdx.x;

  float ev[8], w1[8], w2[8];
  float mx = -3.4e38f;
  #pragma unroll
  for (int j = 0; j < 4; j++){
    int n = 2*(tid + j*288);
    float2 e2 = *(const float2*)&e[n];
    float2 u1 = *(const float2*)&m1[n];
    float2 u2 = *(const float2*)&m2[n];
    ev[2*j]=e2.x; ev[2*j+1]=e2.y;
    w1[2*j]=u1.x; w1[2*j+1]=u1.y;
    w2[2*j]=u2.x; w2[2*j+1]=u2.y;
    mx = fmaxf(mx, fmaxf(e2.x, e2.y));
  }
  mx = blockMax(mx, sh);

  float x0[8];
  float s0 = 0.f, s1 = 0.f, s2 = 0.f;
  #pragma unroll
  for (int i = 0; i < 8; i++){
    x0[i] = __expf(ev[i] - mx);
    s0 += x0[i];
    if (w1[i] > 0.f) s1 += x0[i];
    if (w2[i] > 0.f) s2 += x0[i];
  }
  s0 = blockSum(s0, sh);
  s1 = blockSum(s1, sh);
  s2 = blockSum(s2, sh);
  float r0 = 1.f/s0, r1 = 1.f/s1, r2 = 1.f/s2;

  #pragma unroll
  for (int j = 0; j < 4; j++){
    int n = 2*(tid + j*288);
    long o = row * NPIX + n;
    float px = x0[2*j], py = x0[2*j+1];
    *(uint32_t*)&a0h[o] = tpack(__float2half_rn(px*r0), __float2half_rn(py*r0));
    float ax = (w1[2*j]   > 0.f) ? px*r1 : 0.f;
    float ay = (w1[2*j+1] > 0.f) ? py*r1 : 0.f;
    *(uint32_t*)&a1h[o] = tpack(__float2half_rn(ax), __float2half_rn(ay));
    ax = (w2[2*j]   > 0.f) ? px*r2 : 0.f;
    ay = (w2[2*j+1] > 0.f) ? py*r2 : 0.f;
    *(uint32_t*)&a2h[o] = tpack(__float2half_rn(ax), __float2half_rn(ay));
  }
}

// ---------------- chl softmax -> fp16 ----------------
__global__ __launch_bounds__(256) void chl_softmax_kernel(
    const float* __restrict__ E, __half* __restrict__ Ahd)
{
  __shared__ float sh[32];
  long row = blockIdx.x;
  const float* e = E + row * CCH;
  int tid = threadIdx.x;
  float v0 = e[tid], v1 = e[tid+256];
  float mn = blockMin(fminf(v0, v1), sh);
  float t0 = __expf(mn - v0), t1 = __expf(mn - v1);
  float s = blockSum(t0 + t1, sh);
  float rinv = 1.f/s;
  Ahd[row*CCH + tid]     = __float2half_rn(t0*rinv);
  Ahd[row*CCH + tid+256] = __float2half_rn(t1*rinv);
}

// ---------------- prepass: plain split (bf16) ----------------
__global__ __launch_bounds__(256) void split_nat_kernel(const float* __restrict__ X,
    __nv_bfloat16* __restrict__ H, __nv_bfloat16* __restrict__ L, long total)
{
  for (long i = (long)blockIdx.x*256 + threadIdx.x; i < total; i += (long)gridDim.x*256){
    __nv_bfloat16 h,l; bsplit(X[i], h, l); H[i] = h; L[i] = l;
  }
}

// ---------------- host ----------------
template<typename T, int BI, int EPI, int AL = 1, int BL = 1, typename DT = T>
static void rg(const T* Ah, const T* Al, long sA,
               const T* Bh, const T* Bl, long sB,
               float* C, long sC,
               DT* Dh, DT* Dl, long sD,
               int M, int N, int K,
               const float* p0, const float* p1,
               const float* res, long sRes, const float* gamma, int ldT,
               int KS = 1, int NZ = NB)
{
  constexpr int ABYTES = 2*128*40*2;
  constexpr int BBYTES = (BI==2) ? ABYTES : 2*32*136*2;
  constexpr int SMEM = 2*(ABYTES + BBYTES);
  cudaFuncSetAttribute(gemm3_kernel<T,BI,EPI,AL,BL,DT>,
                       cudaFuncAttributeMaxDynamicSharedMemorySize, SMEM);
  dim3 grid(N/128, (M+127)/128, NZ*KS);
  gemm3_kernel<T,BI,EPI,AL,BL,DT><<<grid, 256, SMEM>>>(Ah, Al, sA, Bh, Bl, sB, C, sC,
                                                       Dh, Dl, sD, M, N, K, p0, p1, res, sRes, gamma, ldT, KS);
}

template<typename T>
static T* sym(const void* s){ void* p = nullptr; cudaGetSymbolAddress(&p, s); return (T*)p; }

static int gsz(long t){ return (int)((t + 255)/256); }

template<int FM>
static void fin(const float* P, int KS, int M, int N,
                const float* p0, const float* p1,
                float* Cout, __nv_bfloat16* Dh, __nv_bfloat16* Dl, int ldT)
{
  long total2 = (long)NB*M*(N/2);
  fin_kernel<FM><<<gsz(total2), 256>>>(P, KS, M, N, p0, p1, Cout, Dh, Dl, ldT);
}

extern "C" void kernel_launch(void* const* d_in, const int* in_sizes, int n_in,
                              void* d_out, int out_size)
{
  const float* x       = (const float*)d_in[0];
  const float* wq      = (const float*)d_in[1];
  const float* bq      = (const float*)d_in[2];
  const float* wk      = (const float*)d_in[3];
  const float* bk      = (const float*)d_in[4];
  const float* wv0     = (const float*)d_in[5];
  const float* bv0     = (const float*)d_in[6];
  const float* conv1_w = (const float*)d_in[7];
  const float* conv1_s = (const float*)d_in[8];
  const float* conv1_b = (const float*)d_in[9];
  const float* conv2_w = (const float*)d_in[10];
  const float* conv2_s = (const float*)d_in[11];
  const float* conv2_b = (const float*)d_in[12];
  const float* gamma   = (const float*)d_in[13];
  const float* gamma1  = (const float*)d_in[14];
  const float* gamma2  = (const float*)d_in[15];
  const float* c1_qw   = (const float*)d_in[16];
  const float* c1_qs   = (const float*)d_in[17];
  const float* c1_qb   = (const float*)d_in[18];
  const float* c1_ew   = (const float*)d_in[19];
  const float* c1_eb   = (const float*)d_in[20];
  const float* c2_qw   = (const float*)d_in[21];
  const float* c2_qs   = (const float*)d_in[22];
  const float* c2_qb   = (const float*)d_in[23];
  const float* c2_ew   = (const float*)d_in[24];
  const float* c2_eb   = (const float*)d_in[25];
  const float* mask1   = (const float*)d_in[26];
  const float* mask2   = (const float*)d_in[27];

  typedef __nv_bfloat16 bf;
  typedef __half hf;
  float* E    = sym<float>(g_E);
  float* buf0 = sym<float>(g_buf0); float* buf1 = sym<float>(g_buf1);
  float* out1 = sym<float>(g_out1); float* expd = sym<float>(g_expd);
  float* part = sym<float>(g_part); float* Mw   = sym<float>(g_M);
  bf *wq_h = sym<bf>(g_wq_h), *wq_l = sym<bf>(g_wq_l);
  bf *wk_h = sym<bf>(g_wk_h), *wk_l = sym<bf>(g_wk_l);
  bf *wv_h = sym<bf>(g_wv_h), *wv_l = sym<bf>(g_wv_l);
  bf *ww1_h = sym<bf>(g_ww1_h), *ww1_l = sym<bf>(g_ww1_l);
  bf *ww2_h = sym<bf>(g_ww2_h), *ww2_l = sym<bf>(g_ww2_l);
  bf *din_h = sym<bf>(g_din_h), *din_l = sym<bf>(g_din_l);
  bf *qw1_h = sym<bf>(g_qw1_h), *qw1_l = sym<bf>(g_qw1_l);
  bf *qw2_h = sym<bf>(g_qw2_h), *qw2_l = sym<bf>(g_qw2_l);
  bf *ew1_h = sym<bf>(g_ew1_h), *ew1_l = sym<bf>(g_ew1_l);
  bf *ew2_h = sym<bf>(g_ew2_h), *ew2_l = sym<bf>(g_ew2_l);
  bf *x_h = sym<bf>(g_x_h), *x_l = sym<bf>(g_x_l);
  bf *qT_h = sym<bf>(g_qT_h), *qT_l = sym<bf>(g_qT_l);
  bf *k_h  = sym<bf>(g_k_h),  *k_l  = sym<bf>(g_k_l);
  bf *b0_h = sym<bf>(g_b0_h), *b0_l = sym<bf>(g_b0_l);
  bf *o1_h = sym<bf>(g_o1_h), *o1_l = sym<bf>(g_o1_l);
  bf *qc_h = sym<bf>(g_qc_h), *qc_l = sym<bf>(g_qc_l);
  bf *e2_h = sym<bf>(g_e2_h), *e2_l = sym<bf>(g_e2_l);
  hf *v_h  = sym<hf>(g_v_h),  *v_l  = sym<hf>(g_v_l);
  hf *vc_h = sym<hf>(g_vc_h), *vc_l = sym<hf>(g_vc_l);
  hf *b0f_h = sym<hf>(g_b0f_h), *b0f_l = sym<hf>(g_b0f_l);
  hf *o1f_h = sym<hf>(g_o1f_h), *o1f_l = sym<hf>(g_o1f_l);
  hf *at0_h = sym<hf>(g_at0_h);
  hf *at1_h = sym<hf>(g_at1_h);
  hf *at2_h = sym<hf>(g_at2_h);
  hf *ac_h  = sym<hf>(g_ac_h);
  float* out = (float*)d_out;

  const long sX  = (long)CCH*NPIX;
  const long sE  = (long)NPIX*NPIX;
  const long sQT = (long)NPIX*CR;
  const long sK  = (long)CR*NPIX;
  const long sQC = (long)CH4*NPIX;
  const long sE2 = (long)CH4*CCH;
  const long sCC = (long)CCH*CCH;
  const long sWW = (long)CCH*CCH;
  const long sDI = (long)CCH*NPIX;
  const int  R   = NB*NPIX;
  const long winoTot = (long)NB*CCH*NT2;

  // ---- prepass splits ----
  split_nat_kernel<<<gsz(CR*CCH),256>>>(wq, wq_h, wq_l, CR*CCH);
  split_nat_kernel<<<gsz(CR*CCH),256>>>(wk, wk_h, wk_l, CR*CCH);
  split_nat_kernel<<<gsz(CCH*CCH),256>>>(wv0, wv_h, wv_l, CCH*CCH);
  split_nat_kernel<<<gsz((long)NB*sX),256>>>(x, x_h, x_l, (long)NB*sX);

  // ---- Q, K (split-K KS=4), V (fp16 split out) ----
  rg<bf,0,7>(wq_h, wq_l, 0, x_h, x_l, sX, part, 0, (bf*)nullptr,(bf*)nullptr,0,
          CR, NPIX, CCH, nullptr, nullptr, nullptr,0, nullptr, 0, 4);
  fin<6>(part, 4, CR, NPIX, bq, nullptr, nullptr, qT_h, qT_l, CR);
  rg<bf,0,7>(wk_h, wk_l, 0, x_h, x_l, sX, part, 0, (bf*)nullptr,(bf*)nullptr,0,
          CR, NPIX, CCH, nullptr, nullptr, nullptr,0, nullptr, 0, 4);
  fin<5>(part, 4, CR, NPIX, bk, nullptr, nullptr, k_h, k_l, 0);
  rg<bf,0,5,1,1,hf>(wv_h, wv_l, 0, x_h, x_l, sX, nullptr,0, v_h, v_l, sX,
          CCH, NPIX, CCH, bv0, nullptr, nullptr,0, nullptr, 0);

  // ---- energy = qT * k ----
  rg<bf,0,0>(qT_h, qT_l, sQT, k_h, k_l, sK, E, sE, (bf*)nullptr,(bf*)nullptr,0,
          NPIX, NPIX, CR, nullptr, nullptr, nullptr,0, nullptr, 0);

  // ---- remaining weight transforms/splits ----
  wino_wt_kernel<<<gsz(CCH*CCH),256>>>(conv1_w, ww1_h, ww1_l);
  wino_wt_kernel<<<gsz(CCH*CCH),256>>>(conv2_w, ww2_h, ww2_l);
  split_nat_kernel<<<gsz(CH4*CCH),256>>>(c1_qw, qw1_h, qw1_l, CH4*CCH);
  split_nat_kernel<<<gsz(CH4*CCH),256>>>(c2_qw, qw2_h, qw2_l, CH4*CCH);
  split_nat_kernel<<<gsz(CCH*CH4),256>>>(c1_ew, ew1_h, ew1_l, CCH*CH4);
  split_nat_kernel<<<gsz(CCH*CH4),256>>>(c2_ew, ew2_h, ew2_l, CCH*CH4);

  // ---- fused softmax (fp16 attention matrices) ----
  softmax_all_kernel<<<R, 288>>>(E, mask1, mask2, at0_h, at1_h, at2_h);

  // ---- pass 0: attention (fp16, v split + at single) ----
  rg<hf,2,2,1,0>(v_h, v_l, sX, at0_h, (hf*)nullptr, sE, buf1, sX, (hf*)nullptr,(hf*)nullptr,0,
          CCH, NPIX, NPIX, nullptr, nullptr, (const float*)x, sX, gamma, 0);
  wino_in_kernel<<<gsz(winoTot),256>>>(buf1, din_h, din_l);
  rg<bf,0,0>(ww1_h, ww1_l, sWW, din_h, din_l, sDI, Mw, sDI, (bf*)nullptr,(bf*)nullptr,0,
          CCH, NPIX, CCH, nullptr, nullptr, nullptr,0, nullptr, 0, 1, 16);
  wino_out_kernel<<<gsz(winoTot),256>>>(Mw, conv1_s, conv1_b, buf0, b0_h, b0_l, b0f_h, b0f_l);

  // chl #1 (split-K on qc/e2/expand)
  rg<bf,0,7>(qw1_h, qw1_l, 0, b0_h, b0_l, sX, part, 0, (bf*)nullptr,(bf*)nullptr,0,
          CH4, NPIX, CCH, nullptr, nullptr, nullptr,0, nullptr, 0, 4);
  fin<4>(part, 4, CH4, NPIX, c1_qs, c1_qb, nullptr, qc_h, qc_l, 0);
  rg<bf,2,7>(qc_h, qc_l, sQC, b0_h, b0_l, sX, part, 0, (bf*)nullptr,(bf*)nullptr,0,
          CH4, CCH, NPIX, nullptr, nullptr, nullptr,0, nullptr, 0, 18);
  fin<5>(part, 18, CH4, CCH, nullptr, nullptr, nullptr, e2_h, e2_l, 0);
  rg<bf,0,7>(ew1_h, ew1_l, 0, e2_h, e2_l, sE2, part, 0, (bf*)nullptr,(bf*)nullptr,0,
          CCH, CCH, CH4, nullptr, nullptr, nullptr,0, nullptr, 0, 4);
  fin<0>(part, 4, CCH, CCH, c1_eb, nullptr, expd, nullptr, nullptr, 0);
  chl_softmax_kernel<<<NB*CCH, 256>>>(expd, ac_h);
  rg<hf,0,5,0,1,hf>(ac_h, (hf*)nullptr, sCC, b0f_h, b0f_l, sX, nullptr,0, vc_h, vc_l, sX,
          CCH, NPIX, CCH, nullptr, nullptr, nullptr,0, nullptr, 0);

  // ---- pass 1 ----
  rg<hf,2,2,1,0>(vc_h, vc_l, sX, at1_h, (hf*)nullptr, sE, buf1, sX, (hf*)nullptr,(hf*)nullptr,0,
          CCH, NPIX, NPIX, nullptr, nullptr, buf0, sX, gamma1, 0);
  wino_in_kernel<<<gsz(winoTot),256>>>(buf1, din_h, din_l);
  rg<bf,0,0>(ww2_h, ww2_l, sWW, din_h, din_l, sDI, Mw, sDI, (bf*)nullptr,(bf*)nullptr,0,
          CCH, NPIX, CCH, nullptr, nullptr, nullptr,0, nullptr, 0, 1, 16);
  wino_out_kernel<<<gsz(winoTot),256>>>(Mw, conv2_s, conv2_b, out1, o1_h, o1_l, o1f_h, o1f_l);

  // chl #2
  rg<bf,0,7>(qw2_h, qw2_l, 0, o1_h, o1_l, sX, part, 0, (bf*)nullptr,(bf*)nullptr,0,
          CH4, NPIX, CCH, nullptr, nullptr, nullptr,0, nullptr, 0, 4);
  fin<4>(part, 4, CH4, NPIX, c2_qs, c2_qb, nullptr, qc_h, qc_l, 0);
  rg<bf,2,7>(qc_h, qc_l, sQC, o1_h, o1_l, sX, part, 0, (bf*)nullptr,(bf*)nullptr,0,
          CH4, CCH, NPIX, nullptr, nullptr, nullptr,0, nullptr, 0, 18);
  fin<5>(part, 18, CH4, CCH, nullptr, nullptr, nullptr, e2_h, e2_l, 0);
  rg<bf,0,7>(ew2_h, ew2_l, 0, e2_h, e2_l, sE2, part, 0, (bf*)nullptr,(bf*)nullptr,0,
          CCH, CCH, CH4, nullptr, nullptr, nullptr,0, nullptr, 0, 4);
  fin<0>(part, 4, CCH, CCH, c2_eb, nullptr, expd, nullptr, nullptr, 0);
  chl_softmax_kernel<<<NB*CCH, 256>>>(expd, ac_h);
  rg<hf,0,5,0,1,hf>(ac_h, (hf*)nullptr, sCC, o1f_h, o1f_l, sX, nullptr,0, vc_h, vc_l, sX,
          CCH, NPIX, CCH, nullptr, nullptr, nullptr,0, nullptr, 0);

  // ---- pass 2 -> out ----
  rg<hf,2,2,1,0>(vc_h, vc_l, sX, at2_h, (hf*)nullptr, sE, out, sX, (hf*)nullptr,(hf*)nullptr,0,
          CCH, NPIX, NPIX, nullptr, nullptr, out1, sX, gamma2, 0);

  (void)in_sizes; (void)n_in; (void)out_size;
}

// round 16
// speedup vs baseline: 2.2467x; 1.0859x over previous
#include <cuda_runtime.h>
#include <cuda_bf16.h>
#include <cuda_fp16.h>
#include <cstdint>

#define NB   4
#define CCH  512
#define NPIX 2304
#define CR   64
#define CH4  128
#define HW   48
#define NT2  576            // 24*24 winograd tiles per image

// ---------------- fp32 scratch ----------------
__device__ float g_E[(size_t)NB*NPIX*NPIX];
__device__ float g_buf0[NB*CCH*NPIX];
__device__ float g_buf1[NB*CCH*NPIX];
__device__ float g_out1[NB*CCH*NPIX];
__device__ float g_expd[NB*CCH*CCH];
__device__ float g_part[4718592];                       // split-K partials
__device__ float g_M[(size_t)16*CCH*NPIX];              // winograd M planes

// ---------------- bf16 split scratch ----------------
__device__ __nv_bfloat16 g_wq_h[CR*CCH],  g_wq_l[CR*CCH];
__device__ __nv_bfloat16 g_wk_h[CR*CCH],  g_wk_l[CR*CCH];
__device__ __nv_bfloat16 g_wv_h[CCH*CCH], g_wv_l[CCH*CCH];
__device__ __nv_bfloat16 g_qw1_h[CH4*CCH], g_qw1_l[CH4*CCH];
__device__ __nv_bfloat16 g_qw2_h[CH4*CCH], g_qw2_l[CH4*CCH];
__device__ __nv_bfloat16 g_ew1_h[CCH*CH4], g_ew1_l[CCH*CH4];
__device__ __nv_bfloat16 g_ew2_h[CCH*CH4], g_ew2_l[CCH*CH4];
__device__ __nv_bfloat16 g_x_h[(size_t)NB*CCH*NPIX], g_x_l[(size_t)NB*CCH*NPIX];
__device__ __nv_bfloat16 g_qT_h[NB*NPIX*CR], g_qT_l[NB*NPIX*CR];
__device__ __nv_bfloat16 g_k_h[NB*CR*NPIX],  g_k_l[NB*CR*NPIX];
__device__ __nv_bfloat16 g_b0_h[NB*CCH*NPIX], g_b0_l[NB*CCH*NPIX];
__device__ __nv_bfloat16 g_o1_h[NB*CCH*NPIX], g_o1_l[NB*CCH*NPIX];
__device__ __nv_bfloat16 g_qc_h[NB*CH4*NPIX], g_qc_l[NB*CH4*NPIX];
__device__ __nv_bfloat16 g_e2_h[NB*CH4*CCH],  g_e2_l[NB*CH4*CCH];

// ---------------- fp16 scratch ----------------
__device__ __half g_ww1_h[(size_t)16*CCH*CCH], g_ww1_l[(size_t)16*CCH*CCH];
__device__ __half g_ww2_h[(size_t)16*CCH*CCH], g_ww2_l[(size_t)16*CCH*CCH];
__device__ __half g_din[(size_t)16*CCH*NPIX];
__device__ __half g_v_h[NB*CCH*NPIX],  g_v_l[NB*CCH*NPIX];
__device__ __half g_vc_h[NB*CCH*NPIX], g_vc_l[NB*CCH*NPIX];
__device__ __half g_b0f_h[NB*CCH*NPIX], g_b0f_l[NB*CCH*NPIX];
__device__ __half g_o1f_h[NB*CCH*NPIX], g_o1f_l[NB*CCH*NPIX];
__device__ __half g_at0_h[(size_t)NB*NPIX*NPIX];
__device__ __half g_at1_h[(size_t)NB*NPIX*NPIX];
__device__ __half g_at2_h[(size_t)NB*NPIX*NPIX];
__device__ __half g_ac_h[NB*CCH*CCH];

// ---------------- reductions ----------------
__device__ __forceinline__ float warpMax(float v){
  #pragma unroll
  for (int o=16;o;o>>=1) v = fmaxf(v, __shfl_xor_sync(0xffffffffu, v, o));
  return v;
}
__device__ __forceinline__ float warpMin(float v){
  #pragma unroll
  for (int o=16;o;o>>=1) v = fminf(v, __shfl_xor_sync(0xffffffffu, v, o));
  return v;
}
__device__ __forceinline__ float warpSum(float v){
  #pragma unroll
  for (int o=16;o;o>>=1) v += __shfl_xor_sync(0xffffffffu, v, o);
  return v;
}
__device__ float blockMax(float v, float* sh){
  v = warpMax(v);
  if ((threadIdx.x & 31) == 0) sh[threadIdx.x >> 5] = v;
  __syncthreads();
  if (threadIdx.x < 32){
    float t = (threadIdx.x < (blockDim.x>>5)) ? sh[threadIdx.x] : -3.4e38f;
    t = warpMax(t);
    if (threadIdx.x == 0) sh[0] = t;
  }
  __syncthreads();
  float r = sh[0]; __syncthreads(); return r;
}
__device__ float blockMin(float v, float* sh){
  v = warpMin(v);
  if ((threadIdx.x & 31) == 0) sh[threadIdx.x >> 5] = v;
  __syncthreads();
  if (threadIdx.x < 32){
    float t = (threadIdx.x < (blockDim.x>>5)) ? sh[threadIdx.x] : 3.4e38f;
    t = warpMin(t);
    if (threadIdx.x == 0) sh[0] = t;
  }
  __syncthreads();
  float r = sh[0]; __syncthreads(); return r;
}
__device__ float blockSum(float v, float* sh){
  v = warpSum(v);
  if ((threadIdx.x & 31) == 0) sh[threadIdx.x >> 5] = v;
  __syncthreads();
  if (threadIdx.x < 32){
    float t = (threadIdx.x < (blockDim.x>>5)) ? sh[threadIdx.x] : 0.f;
    t = warpSum(t);
    if (threadIdx.x == 0) sh[0] = t;
  }
  __syncthreads();
  float r = sh[0]; __syncthreads(); return r;
}

// ---------------- type helpers ----------------
template<typename T> __device__ __forceinline__ void mma_t(float* c, const uint32_t* a, const uint32_t* b);
template<> __device__ __forceinline__ void mma_t<__nv_bfloat16>(float* c, const uint32_t* a, const uint32_t* b){
  asm volatile("mma.sync.aligned.m16n8k16.row.col.f32.bf16.bf16.f32 "
    "{%0,%1,%2,%3}, {%4,%5,%6,%7}, {%8,%9}, {%0,%1,%2,%3};\n"
    : "+f"(c[0]), "+f"(c[1]), "+f"(c[2]), "+f"(c[3])
    : "r"(a[0]), "r"(a[1]), "r"(a[2]), "r"(a[3]), "r"(b[0]), "r"(b[1]));
}
template<> __device__ __forceinline__ void mma_t<__half>(float* c, const uint32_t* a, const uint32_t* b){
  asm volatile("mma.sync.aligned.m16n8k16.row.col.f32.f16.f16.f32 "
    "{%0,%1,%2,%3}, {%4,%5,%6,%7}, {%8,%9}, {%0,%1,%2,%3};\n"
    : "+f"(c[0]), "+f"(c[1]), "+f"(c[2]), "+f"(c[3])
    : "r"(a[0]), "r"(a[1]), "r"(a[2]), "r"(a[3]), "r"(b[0]), "r"(b[1]));
}
__device__ __forceinline__ void ldsm_x4(uint32_t* r, uint32_t saddr){
  asm volatile("ldmatrix.sync.aligned.m8n8.x4.shared.b16 {%0,%1,%2,%3}, [%4];"
    : "=r"(r[0]), "=r"(r[1]), "=r"(r[2]), "=r"(r[3]) : "r"(saddr));
}
__device__ __forceinline__ void ldsm_x4t(uint32_t* r, uint32_t saddr){
  asm volatile("ldmatrix.sync.aligned.m8n8.x4.trans.shared.b16 {%0,%1,%2,%3}, [%4];"
    : "=r"(r[0]), "=r"(r[1]), "=r"(r[2]), "=r"(r[3]) : "r"(saddr));
}
__device__ __forceinline__ void cpasync16(void* dst, const void* src, int szbytes){
  uint32_t d = (uint32_t)__cvta_generic_to_shared(dst);
  asm volatile("cp.async.cg.shared.global [%0], [%1], 16, %2;\n"
               :: "r"(d), "l"(src), "r"(szbytes));
}
__device__ __forceinline__ void cp_commit(){ asm volatile("cp.async.commit_group;\n"); }
__device__ __forceinline__ void cp_wait0(){ asm volatile("cp.async.wait_group 0;\n"); }
__device__ __forceinline__ void cp_wait1(){ asm volatile("cp.async.wait_group 1;\n"); }

__device__ __forceinline__ void tsplit(float v, __nv_bfloat16& h, __nv_bfloat16& l){
  h = __float2bfloat16(v);
  l = __float2bfloat16(v - __bfloat162float(h));
}
__device__ __forceinline__ void tsplit(float v, __half& h, __half& l){
  h = __float2half_rn(v);
  l = __float2half_rn(v - __half2float(h));
}
__device__ __forceinline__ uint32_t tpack(__nv_bfloat16 a, __nv_bfloat16 b){
  return (uint32_t)__bfloat16_as_ushort(a) | ((uint32_t)__bfloat16_as_ushort(b) << 16);
}
__device__ __forceinline__ uint32_t tpack(__half a, __half b){
  return (uint32_t)__half_as_ushort(a) | ((uint32_t)__half_as_ushort(b) << 16);
}
__device__ __forceinline__ void bsplit(float v, __nv_bfloat16& h, __nv_bfloat16& l){ tsplit(v,h,l); }
__device__ __forceinline__ uint32_t bpack(__nv_bfloat16 a, __nv_bfloat16 b){ return tpack(a,b); }

// ---------------- tensor-core GEMM (typed, ldmatrix, K-tile 32, 2-stage, split-K) ----------------
template<typename T, int BI, int EPI, int AL, int BL, typename DT>
__global__ void __launch_bounds__(256,2) gemm3_kernel(
    const T* __restrict__ Ah, const T* __restrict__ Al, long sA,
    const T* __restrict__ Bh, const T* __restrict__ Bl, long sB,
    float* __restrict__ Cm, long sC,
    DT* __restrict__ Dh, DT* __restrict__ Dl, long sD,
    int M, int N, int K,
    const float* __restrict__ p0, const float* __restrict__ p1,
    const float* __restrict__ res, long sRes,
    const float* __restrict__ gamma, int ldT, int KS)
{
  constexpr int AROW = 40;
  constexpr int ABF  = 128*AROW;
  constexpr int ABYTES = 2*ABF*2;
  constexpr int BBF  = (BI==2) ? ABF : 32*136;
  constexpr int BBYTES = 2*BBF*2;
  constexpr int STAGEB = ABYTES + BBYTES;

  extern __shared__ char smc[];
  const uint32_t smem0 = (uint32_t)__cvta_generic_to_shared(smc);

  const int bz = blockIdx.z / KS;
  const int ksl = blockIdx.z - bz*KS;
  const int Kc = K / KS;
  const int k00 = ksl * Kc;

  Ah += (long)bz * sA;  if (AL) Al += (long)bz * sA;
  Bh += (long)bz * sB;  if (BL) Bl += (long)bz * sB;
  if (EPI == 7)      Cm += (long)blockIdx.z * ((long)M*N);
  else if (Cm)       Cm += (long)bz * sC;
  if (EPI >= 3 && EPI <= 6){ Dh += (long)bz * sD; Dl += (long)bz * sD; }
  if (EPI == 2) res += (long)bz * sRes;

  const int tid  = threadIdx.x;
  const int warp = tid >> 5;
  const int lane = tid & 31;
  const int g    = lane >> 2;
  const int ct   = lane & 3;
  const int warpM = warp >> 2;
  const int warpN = warp & 3;
  const int m0 = blockIdx.y * 128;
  const int n0 = blockIdx.x * 128;

  const int lo8 = lane & 7, b3 = (lane>>3)&1, b4 = (lane>>4)&1;
  const uint32_t aoff  = ((warpM*64 + lo8 + b3*8)*AROW + b4*8)*2;
  const uint32_t boff2 = ((warpN*32 + lo8 + b4*8)*AROW + b3*8)*2;
  const uint32_t boff0 = ((lo8 + b3*8)*136 + warpN*32 + b4*8)*2;

  float acc[4][4][4];
  #pragma unroll
  for (int i=0;i<4;i++)
    #pragma unroll
    for (int j=0;j<4;j++)
      #pragma unroll
      for (int c=0;c<4;c++) acc[i][j][c]=0.f;

  auto loadT = [&](int s, int k0){
    char* st = smc + s*STAGEB;
    T* Ahs = (T*)st;
    constexpr int ACNT = AL ? 1024 : 512;
    #pragma unroll
    for (int c = tid; c < ACNT; c += 256){
      const T* base = (c < 512) ? Ah : Al;
      T* dst = Ahs + ((c < 512) ? 0 : ABF);
      int e = c & 511, row = e >> 2, q = e & 3;
      int gm = m0 + row;
      int sz = (gm < M) ? 16 : 0; if (gm >= M) gm = 0;
      cpasync16(dst + row*AROW + q*8, base + (long)gm*K + k0 + q*8, sz);
    }
    T* Bs = (T*)(st + ABYTES);
    constexpr int BCNT = BL ? 1024 : 512;
    if (BI == 2){
      #pragma unroll
      for (int c = tid; c < BCNT; c += 256){
        const T* base = (c < 512) ? Bh : Bl;
        T* dst = Bs + ((c < 512) ? 0 : ABF);
        int e = c & 511, row = e >> 2, q = e & 3;
        cpasync16(dst + row*AROW + q*8, base + (long)(n0+row)*K + k0 + q*8, 16);
      }
    } else {
      #pragma unroll
      for (int c = tid; c < BCNT; c += 256){
        const T* base = (c < 512) ? Bh : Bl;
        T* dst = Bs + ((c < 512) ? 0 : 32*136);
        int e = c & 511, row = e >> 4, ch = e & 15;
        cpasync16(dst + row*136 + ch*8, base + (long)(k0+row)*N + n0 + ch*8, 16);
      }
    }
  };

  const int T_ = Kc/32;
  loadT(0, k00); cp_commit();

  for (int i = 0; i < T_; i++){
    if (i + 1 < T_){ loadT((i+1)&1, k00 + (i+1)*32); cp_commit(); cp_wait1(); }
    else           { cp_wait0(); }
    __syncthreads();

    const uint32_t stb = smem0 + (uint32_t)((i&1)*STAGEB);
    const uint32_t bb  = stb + ABYTES;

    #pragma unroll
    for (int h = 0; h < 2; h++){
      const uint32_t aH = stb + aoff + h*32;
      const uint32_t aL = stb + ABF*2 + aoff + h*32;
      uint32_t ah[4][4], al[4][4], bhf[8], blf[8];
      #pragma unroll
      for (int mi=0; mi<4; mi++){
        ldsm_x4(ah[mi], aH + mi*(16*AROW*2));
        if (AL) ldsm_x4(al[mi], aL + mi*(16*AROW*2));
      }
      if (BI == 2){
        const uint32_t bH = bb + boff2 + h*32;
        const uint32_t bL = bb + ABF*2 + boff2 + h*32;
        ldsm_x4(bhf,   bH);
        ldsm_x4(bhf+4, bH + 16*AROW*2);
        if (BL){
          ldsm_x4(blf,   bL);
          ldsm_x4(blf+4, bL + 16*AROW*2);
        }
      } else {
        const uint32_t bH = bb + boff0 + h*(16*136*2);
        const uint32_t bL = bb + 32*136*2 + boff0 + h*(16*136*2);
        ldsm_x4t(bhf,   bH);
        ldsm_x4t(bhf+4, bH + 16*2);
        if (BL){
          ldsm_x4t(blf,   bL);
          ldsm_x4t(blf+4, bL + 16*2);
        }
      }
      #pragma unroll
      for (int mi=0; mi<4; mi++)
        #pragma unroll
        for (int nj=0; nj<4; nj++){
          mma_t<T>(acc[mi][nj], ah[mi], bhf + nj*2);
          if (BL) mma_t<T>(acc[mi][nj], ah[mi], blf + nj*2);
          if (AL) mma_t<T>(acc[mi][nj], al[mi], bhf + nj*2);
        }
    }
    __syncthreads();
  }

  // ---- epilogue
  #pragma unroll
  for (int mi=0; mi<4; mi++){
    int rr[2] = { m0 + warpM*64 + mi*16 + g, m0 + warpM*64 + mi*16 + g + 8 };
    float sc[2] = {0.f,0.f}, of[2] = {0.f,0.f};
    #pragma unroll
    for (int h=0; h<2; h++){
      if (rr[h] < M){
        if (EPI == 4){ sc[h] = p0[rr[h]]; of[h] = p1[rr[h]]; }
        else if (EPI == 0 || EPI == 5 || EPI == 6){ if (p0) of[h] = p0[rr[h]]; }
      }
    }
    #pragma unroll
    for (int nj=0; nj<4; nj++){
      int n = n0 + warpN*32 + nj*8 + 2*ct;
      #pragma unroll
      for (int h=0; h<2; h++){
        int r = rr[h];
        if (r >= M) continue;
        float wx = acc[mi][nj][2*h], wy = acc[mi][nj][2*h+1];
        if (EPI == 7){
          float2 w; w.x = wx; w.y = wy;
          *(float2*)&Cm[(long)r*N + n] = w;
          continue;
        }
        if (EPI == 0){ wx += of[h]; wy += of[h]; }
        else if (EPI == 2){
          float2 rv = *(const float2*)&res[(long)r*N + n];
          wx = gamma[0]*wx + rv.x; wy = gamma[0]*wy + rv.y;
        } else if (EPI == 4){
          wx = fmaxf(wx*sc[h] + of[h], 0.f);
          wy = fmaxf(wy*sc[h] + of[h], 0.f);
        } else { wx += of[h]; wy += of[h]; }
        if (EPI == 0 || EPI == 2){
          float2 w; w.x = wx; w.y = wy;
          *(float2*)&Cm[(long)r*N + n] = w;
        }
        if (EPI >= 3 && EPI <= 6){
          DT hx, lx, hy, ly;
          tsplit(wx, hx, lx); tsplit(wy, hy, ly);
          if (EPI == 6){
            Dh[(long)n*ldT + r] = hx;       Dl[(long)n*ldT + r] = lx;
            Dh[(long)(n+1)*ldT + r] = hy;   Dl[(long)(n+1)*ldT + r] = ly;
          } else {
            *(uint32_t*)&Dh[(long)r*N + n] = tpack(hx, hy);
            *(uint32_t*)&Dl[(long)r*N + n] = tpack(lx, ly);
          }
        }
      }
    }
  }
}

// ---------------- split-K finalize (bf16 outputs) ----------------
template<int FM>
__global__ __launch_bounds__(256) void fin_kernel(
    const float* __restrict__ P, int KS, int M, int N,
    const float* __restrict__ p0, const float* __restrict__ p1,
    float* __restrict__ Cout, __nv_bfloat16* __restrict__ Dh,
    __nv_bfloat16* __restrict__ Dl, int ldT)
{
  const long MN = (long)M*N;
  long total2 = (long)NB*M*(N/2);
  long w = (long)blockIdx.x*256 + threadIdx.x;
  if (w >= total2) return;
  int n2 = (int)(w % (N/2));
  long t = w / (N/2);
  int r = (int)(t % M);
  int b = (int)(t / M);
  long base = ((long)(b*KS))*MN + (long)r*N + 2*n2;
  float vx = 0.f, vy = 0.f;
  for (int ks = 0; ks < KS; ks++){
    float2 pv = *(const float2*)&P[base + (long)ks*MN];
    vx += pv.x; vy += pv.y;
  }
  if (FM == 0){
    float of = p0 ? p0[r] : 0.f;
    float2 o; o.x = vx + of; o.y = vy + of;
    *(float2*)&Cout[(long)b*MN + (long)r*N + 2*n2] = o;
  } else if (FM == 4){
    float scv = p0[r], of = p1[r];
    vx = fmaxf(vx*scv + of, 0.f); vy = fmaxf(vy*scv + of, 0.f);
    __nv_bfloat16 hx,lx,hy,ly; bsplit(vx,hx,lx); bsplit(vy,hy,ly);
    long o = (long)b*MN + (long)r*N + 2*n2;
    *(uint32_t*)&Dh[o] = bpack(hx,hy);
    *(uint32_t*)&Dl[o] = bpack(lx,ly);
  } else if (FM == 5){
    float of = p0 ? p0[r] : 0.f;
    vx += of; vy += of;
    __nv_bfloat16 hx,lx,hy,ly; bsplit(vx,hx,lx); bsplit(vy,hy,ly);
    long o = (long)b*MN + (long)r*N + 2*n2;
    *(uint32_t*)&Dh[o] = bpack(hx,hy);
    *(uint32_t*)&Dl[o] = bpack(lx,ly);
  } else {
    float of = p0 ? p0[r] : 0.f;
    vx += of; vy += of;
    __nv_bfloat16 hx,lx,hy,ly; bsplit(vx,hx,lx); bsplit(vy,hy,ly);
    long ob = (long)b*MN;
    int n = 2*n2;
    Dh[ob + (long)n*ldT + r] = hx;     Dl[ob + (long)n*ldT + r] = lx;
    Dh[ob + (long)(n+1)*ldT + r] = hy; Dl[ob + (long)(n+1)*ldT + r] = ly;
  }
}

// ---------------- winograd F(2x2,3x3) transforms ----------------
// weight: W' = G g G^T; fp16 hi/lo planes [uv][oc][ic].
__global__ __launch_bounds__(256) void wino_wt_kernel(const float* __restrict__ Wsrc,
    __half* __restrict__ Wh, __half* __restrict__ Wl)
{
  int idx = blockIdx.x*256 + threadIdx.x;
  if (idx >= CCH*CCH) return;
  int ic = idx & (CCH-1);
  int oc = idx >> 9;
  const float* gp = Wsrc + ((long)oc*CCH + ic)*9;
  float gm[3][3];
  #pragma unroll
  for (int i=0;i<3;i++)
    #pragma unroll
    for (int j=0;j<3;j++) gm[i][j] = gp[i*3+j];
  float r[4][3];
  #pragma unroll
  for (int j=0;j<3;j++){
    r[0][j] = gm[0][j];
    r[1][j] = 0.5f*(gm[0][j]+gm[1][j]+gm[2][j]);
    r[2][j] = 0.5f*(gm[0][j]-gm[1][j]+gm[2][j]);
    r[3][j] = gm[2][j];
  }
  #pragma unroll
  for (int u=0;u<4;u++){
    float w0 = r[u][0];
    float w1 = 0.5f*(r[u][0]+r[u][1]+r[u][2]);
    float w2 = 0.5f*(r[u][0]-r[u][1]+r[u][2]);
    float w3 = r[u][2];
    float wv[4] = {w0,w1,w2,w3};
    #pragma unroll
    for (int v=0;v<4;v++){
      __half h,l; tsplit(wv[v],h,l);
      long o = ((long)(u*4+v)*CCH + oc)*CCH + ic;
      Wh[o] = h; Wl[o] = l;
    }
  }
}

// input: D' = B^T d B; single fp16 planes [uv][ic][b*576+t].
__global__ __launch_bounds__(256) void wino_in_kernel(const float* __restrict__ X,
    __half* __restrict__ Dd)
{
  long w = (long)blockIdx.x*256 + threadIdx.x;
  const long total = (long)NB*CCH*NT2;
  if (w >= total) return;
  int t = (int)(w % NT2);
  long r = w / NT2;
  int c = (int)(r % CCH);
  int b = (int)(r / CCH);
  int ty = t / 24, tx = t - (t/24)*24;
  const float* xs = X + ((long)(b*CCH + c))*NPIX;
  float d[4][4];
  #pragma unroll
  for (int i=0;i<4;i++){
    int iy = 2*ty - 1 + i;
    #pragma unroll
    for (int j=0;j<4;j++){
      int ix = 2*tx - 1 + j;
      d[i][j] = (iy >= 0 && iy < HW && ix >= 0 && ix < HW) ? xs[iy*HW+ix] : 0.f;
    }
  }
  float tb[4][4];
  #pragma unroll
  for (int j=0;j<4;j++){
    tb[0][j] = d[0][j] - d[2][j];
    tb[1][j] = d[1][j] + d[2][j];
    tb[2][j] = d[2][j] - d[1][j];
    tb[3][j] = d[1][j] - d[3][j];
  }
  long nidx = (long)b*NT2 + t;
  #pragma unroll
  for (int i=0;i<4;i++){
    float D0 = tb[i][0] - tb[i][2];
    float D1 = tb[i][1] + tb[i][2];
    float D2 = tb[i][2] - tb[i][1];
    float D3 = tb[i][1] - tb[i][3];
    float Dv[4] = {D0,D1,D2,D3};
    #pragma unroll
    for (int j=0;j<4;j++){
      long o = ((long)(i*4+j)*CCH + c)*NPIX + nidx;
      Dd[o] = __float2half_rn(Dv[j]);
    }
  }
}

// output transform: Y = A^T M A, BN+ReLU; fp32 + bf16 split + fp16 split.
__global__ __launch_bounds__(256) void wino_out_kernel(const float* __restrict__ Mp,
    const float* __restrict__ scale, const float* __restrict__ bias,
    float* __restrict__ Y, __nv_bfloat16* __restrict__ Yh, __nv_bfloat16* __restrict__ Yl,
    __half* __restrict__ Fh, __half* __restrict__ Fl)
{
  const long MN = (long)CCH*NPIX;
  long w = (long)blockIdx.x*256 + threadIdx.x;
  const long total = (long)NB*CCH*NT2;
  if (w >= total) return;
  int t = (int)(w % NT2);
  long r = w / NT2;
  int oc = (int)(r % CCH);
  int b  = (int)(r / CCH);
  int ty = t / 24, tx = t - (t/24)*24;
  long base = (long)oc*NPIX + (long)b*NT2 + t;
  float m[4][4];
  #pragma unroll
  for (int u=0;u<4;u++)
    #pragma unroll
    for (int v=0;v<4;v++) m[u][v] = Mp[(long)(u*4+v)*MN + base];
  float s0[4], s1[4];
  #pragma unroll
  for (int v=0;v<4;v++){
    s0[v] = m[0][v] + m[1][v] + m[2][v];
    s1[v] = m[1][v] - m[2][v] - m[3][v];
  }
  float y00 = s0[0]+s0[1]+s0[2], y01 = s0[1]-s0[2]-s0[3];
  float y10 = s1[0]+s1[1]+s1[2], y11 = s1[1]-s1[2]-s1[3];
  float sc = scale[oc], bi = bias[oc];
  y00 = fmaxf(y00*sc+bi, 0.f); y01 = fmaxf(y01*sc+bi, 0.f);
  y10 = fmaxf(y10*sc+bi, 0.f); y11 = fmaxf(y11*sc+bi, 0.f);
  long ob = ((long)(b*CCH + oc))*NPIX;
  long p0i = ob + (2*ty)*HW + 2*tx;
  long p1i = ob + (2*ty+1)*HW + 2*tx;
  float2 w0; w0.x = y00; w0.y = y01;
  float2 w1; w1.x = y10; w1.y = y11;
  *(float2*)&Y[p0i] = w0;
  *(float2*)&Y[p1i] = w1;
  __nv_bfloat16 h0,l0,h1,l1;
  bsplit(y00,h0,l0); bsplit(y01,h1,l1);
  *(uint32_t*)&Yh[p0i] = bpack(h0,h1);
  *(uint32_t*)&Yl[p0i] = bpack(l0,l1);
  bsplit(y10,h0,l0); bsplit(y11,h1,l1);
  *(uint32_t*)&Yh[p1i] = bpack(h0,h1);
  *(uint32_t*)&Yl[p1i] = bpack(l0,l1);
  __half f0,g0,f1,g1;
  tsplit(y00,f0,g0); tsplit(y01,f1,g1);
  *(uint32_t*)&Fh[p0i] = tpack(f0,f1);
  *(uint32_t*)&Fl[p0i] = tpack(g0,g1);
  tsplit(y10,f0,g0); tsplit(y11,f1,g1);
  *(uint32_t*)&Fh[p1i] = tpack(f0,f1);
  *(uint32_t*)&Fl[p1i] = tpack(g0,g1);
}

// ---------------- fused softmax: one exp per element, all 3 variants (fp16 out) ----------------
__global__ __launch_bounds__(288) void softmax_all_kernel(
    const float* __restrict__ E,
    const float* __restrict__ M1, const float* __restrict__ M2,
    __half* __restrict__ a0h, __half* __restrict__ a1h, __half* __restrict__ a2h)
{
  __shared__ float sh[32];
  long row = blockIdx.x;
  int  mr  = (int)(row % NPIX);
  const float* e  = E  + row * NPIX;
  const float* m1 = M1 + (long)mr * NPIX;
  const float* m2 = M2 + (long)mr * NPIX;
  int tid = threadIdx.x;

  float ev[8], w1[8], w2[8];
  float mx = -3.4e38f;
  #pragma unroll
  for (int j = 0; j < 4; j++){
    int n = 2*(tid + j*288);
    float2 e2 = *(const float2*)&e[n];
    float2 u1 = *(const float2*)&m1[n];
    float2 u2 = *(const float2*)&m2[n];
    ev[2*j]=e2.x; ev[2*j+1]=e2.y;
    w1[2*j]=u1.x; w1[2*j+1]=u1.y;
    w2[2*j]=u2.x; w2[2*j+1]=u2.y;
    mx = fmaxf(mx, fmaxf(e2.x, e2.y));
  }
  mx = blockMax(mx, sh);

  float x0[8];
  float s0 = 0.f, s1 = 0.f, s2 = 0.f;
  #pragma unroll
  for (int i = 0; i < 8; i++){
    x0[i] = __expf(ev[i] - mx);
    s0 += x0[i];
    if (w1[i] > 0.f) s1 += x0[i];
    if (w2[i] > 0.f) s2 += x0[i];
  }
  s0 = blockSum(s0, sh);
  s1 = blockSum(s1, sh);
  s2 = blockSum(s2, sh);
  float r0 = 1.f/s0, r1 = 1.f/s1, r2 = 1.f/s2;

  #pragma unroll
  for (int j = 0; j < 4; j++){
    int n = 2*(tid + j*288);
    long o = row * NPIX + n;
    float px = x0[2*j], py = x0[2*j+1];
    *(uint32_t*)&a0h[o] = tpack(__float2half_rn(px*r0), __float2half_rn(py*r0));
    float ax = (w1[2*j]   > 0.f) ? px*r1 : 0.f;
    float ay = (w1[2*j+1] > 0.f) ? py*r1 : 0.f;
    *(uint32_t*)&a1h[o] = tpack(__float2half_rn(ax), __float2half_rn(ay));
    ax = (w2[2*j]   > 0.f) ? px*r2 : 0.f;
    ay = (w2[2*j+1] > 0.f) ? py*r2 : 0.f;
    *(uint32_t*)&a2h[o] = tpack(__float2half_rn(ax), __float2half_rn(ay));
  }
}

// ---------------- chl softmax -> fp16 ----------------
__global__ __launch_bounds__(256) void chl_softmax_kernel(
    const float* __restrict__ E, __half* __restrict__ Ahd)
{
  __shared__ float sh[32];
  long row = blockIdx.x;
  const float* e = E + row * CCH;
  int tid = threadIdx.x;
  float v0 = e[tid], v1 = e[tid+256];
  float mn = blockMin(fminf(v0, v1), sh);
  float t0 = __expf(mn - v0), t1 = __expf(mn - v1);
  float s = blockSum(t0 + t1, sh);
  float rinv = 1.f/s;
  Ahd[row*CCH + tid]     = __float2half_rn(t0*rinv);
  Ahd[row*CCH + tid+256] = __float2half_rn(t1*rinv);
}

// ---------------- prepass: plain split (bf16) ----------------
__global__ __launch_bounds__(256) void split_nat_kernel(const float* __restrict__ X,
    __nv_bfloat16* __restrict__ H, __nv_bfloat16* __restrict__ L, long total)
{
  for (long i = (long)blockIdx.x*256 + threadIdx.x; i < total; i += (long)gridDim.x*256){
    __nv_bfloat16 h,l; bsplit(X[i], h, l); H[i] = h; L[i] = l;
  }
}

// ---------------- host ----------------
template<typename T, int BI, int EPI, int AL = 1, int BL = 1, typename DT = T>
static void rg(const T* Ah, const T* Al, long sA,
               const T* Bh, const T* Bl, long sB,
               float* C, long sC,
               DT* Dh, DT* Dl, long sD,
               int M, int N, int K,
               const float* p0, const float* p1,
               const float* res, long sRes, const float* gamma, int ldT,
               int KS = 1, int NZ = NB)
{
  constexpr int ABYTES = 2*128*40*2;
  constexpr int BBYTES = (BI==2) ? ABYTES : 2*32*136*2;
  constexpr int SMEM = 2*(ABYTES + BBYTES);
  cudaFuncSetAttribute(gemm3_kernel<T,BI,EPI,AL,BL,DT>,
                       cudaFuncAttributeMaxDynamicSharedMemorySize, SMEM);
  dim3 grid(N/128, (M+127)/128, NZ*KS);
  gemm3_kernel<T,BI,EPI,AL,BL,DT><<<grid, 256, SMEM>>>(Ah, Al, sA, Bh, Bl, sB, C, sC,
                                                       Dh, Dl, sD, M, N, K, p0, p1, res, sRes, gamma, ldT, KS);
}

template<typename T>
static T* sym(const void* s){ void* p = nullptr; cudaGetSymbolAddress(&p, s); return (T*)p; }

static int gsz(long t){ return (int)((t + 255)/256); }

template<int FM>
static void fin(const float* P, int KS, int M, int N,
                const float* p0, const float* p1,
                float* Cout, __nv_bfloat16* Dh, __nv_bfloat16* Dl, int ldT)
{
  long total2 = (long)NB*M*(N/2);
  fin_kernel<FM><<<gsz(total2), 256>>>(P, KS, M, N, p0, p1, Cout, Dh, Dl, ldT);
}

extern "C" void kernel_launch(void* const* d_in, const int* in_sizes, int n_in,
                              void* d_out, int out_size)
{
  const float* x       = (const float*)d_in[0];
  const float* wq      = (const float*)d_in[1];
  const float* bq      = (const float*)d_in[2];
  const float* wk      = (const float*)d_in[3];
  const float* bk      = (const float*)d_in[4];
  const float* wv0     = (const float*)d_in[5];
  const float* bv0     = (const float*)d_in[6];
  const float* conv1_w = (const float*)d_in[7];
  const float* conv1_s = (const float*)d_in[8];
  const float* conv1_b = (const float*)d_in[9];
  const float* conv2_w = (const float*)d_in[10];
  const float* conv2_s = (const float*)d_in[11];
  const float* conv2_b = (const float*)d_in[12];
  const float* gamma   = (const float*)d_in[13];
  const float* gamma1  = (const float*)d_in[14];
  const float* gamma2  = (const float*)d_in[15];
  const float* c1_qw   = (const float*)d_in[16];
  const float* c1_qs   = (const float*)d_in[17];
  const float* c1_qb   = (const float*)d_in[18];
  const float* c1_ew   = (const float*)d_in[19];
  const float* c1_eb   = (const float*)d_in[20];
  const float* c2_qw   = (const float*)d_in[21];
  const float* c2_qs   = (const float*)d_in[22];
  const float* c2_qb   = (const float*)d_in[23];
  const float* c2_ew   = (const float*)d_in[24];
  const float* c2_eb   = (const float*)d_in[25];
  const float* mask1   = (const float*)d_in[26];
  const float* mask2   = (const float*)d_in[27];

  typedef __nv_bfloat16 bf;
  typedef __half hf;
  float* E    = sym<float>(g_E);
  float* buf0 = sym<float>(g_buf0); float* buf1 = sym<float>(g_buf1);
  float* out1 = sym<float>(g_out1); float* expd = sym<float>(g_expd);
  float* part = sym<float>(g_part); float* Mw   = sym<float>(g_M);
  bf *wq_h = sym<bf>(g_wq_h), *wq_l = sym<bf>(g_wq_l);
  bf *wk_h = sym<bf>(g_wk_h), *wk_l = sym<bf>(g_wk_l);
  bf *wv_h = sym<bf>(g_wv_h), *wv_l = sym<bf>(g_wv_l);
  hf *ww1_h = sym<hf>(g_ww1_h), *ww1_l = sym<hf>(g_ww1_l);
  hf *ww2_h = sym<hf>(g_ww2_h), *ww2_l = sym<hf>(g_ww2_l);
  hf *din  = sym<hf>(g_din);
  bf *qw1_h = sym<bf>(g_qw1_h), *qw1_l = sym<bf>(g_qw1_l);
  bf *qw2_h = sym<bf>(g_qw2_h), *qw2_l = sym<bf>(g_qw2_l);
  bf *ew1_h = sym<bf>(g_ew1_h), *ew1_l = sym<bf>(g_ew1_l);
  bf *ew2_h = sym<bf>(g_ew2_h), *ew2_l = sym<bf>(g_ew2_l);
  bf *x_h = sym<bf>(g_x_h), *x_l = sym<bf>(g_x_l);
  bf *qT_h = sym<bf>(g_qT_h), *qT_l = sym<bf>(g_qT_l);
  bf *k_h  = sym<bf>(g_k_h),  *k_l  = sym<bf>(g_k_l);
  bf *b0_h = sym<bf>(g_b0_h), *b0_l = sym<bf>(g_b0_l);
  bf *o1_h = sym<bf>(g_o1_h), *o1_l = sym<bf>(g_o1_l);
  bf *qc_h = sym<bf>(g_qc_h), *qc_l = sym<bf>(g_qc_l);
  bf *e2_h = sym<bf>(g_e2_h), *e2_l = sym<bf>(g_e2_l);
  hf *v_h  = sym<hf>(g_v_h),  *v_l  = sym<hf>(g_v_l);
  hf *vc_h = sym<hf>(g_vc_h), *vc_l = sym<hf>(g_vc_l);
  hf *b0f_h = sym<hf>(g_b0f_h), *b0f_l = sym<hf>(g_b0f_l);
  hf *o1f_h = sym<hf>(g_o1f_h), *o1f_l = sym<hf>(g_o1f_l);
  hf *at0_h = sym<hf>(g_at0_h);
  hf *at1_h = sym<hf>(g_at1_h);
  hf *at2_h = sym<hf>(g_at2_h);
  hf *ac_h  = sym<hf>(g_ac_h);
  float* out = (float*)d_out;

  const long sX  = (long)CCH*NPIX;
  const long sE  = (long)NPIX*NPIX;
  const long sQT = (long)NPIX*CR;
  const long sK  = (long)CR*NPIX;
  const long sQC = (long)CH4*NPIX;
  const long sE2 = (long)CH4*CCH;
  const long sCC = (long)CCH*CCH;
  const long sWW = (long)CCH*CCH;
  const long sDI = (long)CCH*NPIX;
  const int  R   = NB*NPIX;
  const long winoTot = (long)NB*CCH*NT2;

  // ---- prepass splits ----
  split_nat_kernel<<<gsz(CR*CCH),256>>>(wq, wq_h, wq_l, CR*CCH);
  split_nat_kernel<<<gsz(CR*CCH),256>>>(wk, wk_h, wk_l, CR*CCH);
  split_nat_kernel<<<gsz(CCH*CCH),256>>>(wv0, wv_h, wv_l, CCH*CCH);
  split_nat_kernel<<<gsz((long)NB*sX),256>>>(x, x_h, x_l, (long)NB*sX);

  // ---- Q, K (split-K KS=4), V (fp16 split out) ----
  rg<bf,0,7>(wq_h, wq_l, 0, x_h, x_l, sX, part, 0, (bf*)nullptr,(bf*)nullptr,0,
          CR, NPIX, CCH, nullptr, nullptr, nullptr,0, nullptr, 0, 4);
  fin<6>(part, 4, CR, NPIX, bq, nullptr, nullptr, qT_h, qT_l, CR);
  rg<bf,0,7>(wk_h, wk_l, 0, x_h, x_l, sX, part, 0, (bf*)nullptr,(bf*)nullptr,0,
          CR, NPIX, CCH, nullptr, nullptr, nullptr,0, nullptr, 0, 4);
  fin<5>(part, 4, CR, NPIX, bk, nullptr, nullptr, k_h, k_l, 0);
  rg<bf,0,5,1,1,hf>(wv_h, wv_l, 0, x_h, x_l, sX, nullptr,0, v_h, v_l, sX,
          CCH, NPIX, CCH, bv0, nullptr, nullptr,0, nullptr, 0);

  // ---- energy = qT * k ----
  rg<bf,0,0>(qT_h, qT_l, sQT, k_h, k_l, sK, E, sE, (bf*)nullptr,(bf*)nullptr,0,
          NPIX, NPIX, CR, nullptr, nullptr, nullptr,0, nullptr, 0);

  // ---- remaining weight transforms/splits ----
  wino_wt_kernel<<<gsz(CCH*CCH),256>>>(conv1_w, ww1_h, ww1_l);
  wino_wt_kernel<<<gsz(CCH*CCH),256>>>(conv2_w, ww2_h, ww2_l);
  split_nat_kernel<<<gsz(CH4*CCH),256>>>(c1_qw, qw1_h, qw1_l, CH4*CCH);
  split_nat_kernel<<<gsz(CH4*CCH),256>>>(c2_qw, qw2_h, qw2_l, CH4*CCH);
  split_nat_kernel<<<gsz(CCH*CH4),256>>>(c1_ew, ew1_h, ew1_l, CCH*CH4);
  split_nat_kernel<<<gsz(CCH*CH4),256>>>(c2_ew, ew2_h, ew2_l, CCH*CH4);

  // ---- fused softmax (fp16 attention matrices) ----
  softmax_all_kernel<<<R, 288>>>(E, mask1, mask2, at0_h, at1_h, at2_h);

  // ---- pass 0: attention (fp16, v split + at single) ----
  rg<hf,2,2,1,0>(v_h, v_l, sX, at0_h, (hf*)nullptr, sE, buf1, sX, (hf*)nullptr,(hf*)nullptr,0,
          CCH, NPIX, NPIX, nullptr, nullptr, (const float*)x, sX, gamma, 0);
  wino_in_kernel<<<gsz(winoTot),256>>>(buf1, din);
  rg<hf,0,0,1,0>(ww1_h, ww1_l, sWW, din, (hf*)nullptr, sDI, Mw, sDI, (hf*)nullptr,(hf*)nullptr,0,
          CCH, NPIX, CCH, nullptr, nullptr, nullptr,0, nullptr, 0, 1, 16);
  wino_out_kernel<<<gsz(winoTot),256>>>(Mw, conv1_s, conv1_b, buf0, b0_h, b0_l, b0f_h, b0f_l);

  // chl #1 (split-K on qc/e2/expand)
  rg<bf,0,7>(qw1_h, qw1_l, 0, b0_h, b0_l, sX, part, 0, (bf*)nullptr,(bf*)nullptr,0,
          CH4, NPIX, CCH, nullptr, nullptr, nullptr,0, nullptr, 0, 4);
  fin<4>(part, 4, CH4, NPIX, c1_qs, c1_qb, nullptr, qc_h, qc_l, 0);
  rg<bf,2,7>(qc_h, qc_l, sQC, b0_h, b0_l, sX, part, 0, (bf*)nullptr,(bf*)nullptr,0,
          CH4, CCH, NPIX, nullptr, nullptr, nullptr,0, nullptr, 0, 18);
  fin<5>(part, 18, CH4, CCH, nullptr, nullptr, nullptr, e2_h, e2_l, 0);
  rg<bf,0,7>(ew1_h, ew1_l, 0, e2_h, e2_l, sE2, part, 0, (bf*)nullptr,(bf*)nullptr,0,
          CCH, CCH, CH4, nullptr, nullptr, nullptr,0, nullptr, 0, 4);
  fin<0>(part, 4, CCH, CCH, c1_eb, nullptr, expd, nullptr, nullptr, 0);
  chl_softmax_kernel<<<NB*CCH, 256>>>(expd, ac_h);
  rg<hf,0,5,0,1,hf>(ac_h, (hf*)nullptr, sCC, b0f_h, b0f_l, sX, nullptr,0, vc_h, vc_l, sX,
          CCH, NPIX, CCH, nullptr, nullptr, nullptr,0, nullptr, 0);

  // ---- pass 1 ----
  rg<hf,2,2,1,0>(vc_h, vc_l, sX, at1_h, (hf*)nullptr, sE, buf1, sX, (hf*)nullptr,(hf*)nullptr,0,
          CCH, NPIX, NPIX, nullptr, nullptr, buf0, sX, gamma1, 0);
  wino_in_kernel<<<gsz(winoTot),256>>>(buf1, din);
  rg<hf,0,0,1,0>(ww2_h, ww2_l, sWW, din, (hf*)nullptr, sDI, Mw, sDI, (hf*)nullptr,(hf*)nullptr,0,
          CCH, NPIX, CCH, nullptr, nullptr, nullptr,0, nullptr, 0, 1, 16);
  wino_out_kernel<<<gsz(winoTot),256>>>(Mw, conv2_s, conv2_b, out1, o1_h, o1_l, o1f_h, o1f_l);

  // chl #2
  rg<bf,0,7>(qw2_h, qw2_l, 0, o1_h, o1_l, sX, part, 0, (bf*)nullptr,(bf*)nullptr,0,
          CH4, NPIX, CCH, nullptr, nullptr, nullptr,0, nullptr, 0, 4);
  fin<4>(part, 4, CH4, NPIX, c2_qs, c2_qb, nullptr, qc_h, qc_l, 0);
  rg<bf,2,7>(qc_h, qc_l, sQC, o1_h, o1_l, sX, part, 0, (bf*)nullptr,(bf*)nullptr,0,
          CH4, CCH, NPIX, nullptr, nullptr, nullptr,0, nullptr, 0, 18);
  fin<5>(part, 18, CH4, CCH, nullptr, nullptr, nullptr, e2_h, e2_l, 0);
  rg<bf,0,7>(ew2_h, ew2_l, 0, e2_h, e2_l, sE2, part, 0, (bf*)nullptr,(bf*)nullptr,0,
          CCH, CCH, CH4, nullptr, nullptr, nullptr,0, nullptr, 0, 4);
  fin<0>(part, 4, CCH, CCH, c2_eb, nullptr, expd, nullptr, nullptr, 0);
  chl_softmax_kernel<<<NB*CCH, 256>>>(expd, ac_h);
  rg<hf,0,5,0,1,hf>(ac_h, (hf*)nullptr, sCC, o1f_h, o1f_l, sX, nullptr,0, vc_h, vc_l, sX,
          CCH, NPIX, CCH, nullptr, nullptr, nullptr,0, nullptr, 0);

  // ---- pass 2 -> out ----
  rg<hf,2,2,1,0>(vc_h, vc_l, sX, at2_h, (hf*)nullptr, sE, out, sX, (hf*)nullptr,(hf*)nullptr,0,
          CCH, NPIX, NPIX, nullptr, nullptr, out1, sX, gamma2, 0);

  (void)in_sizes; (void)n_in; (void)out_size;
}

// round 17
// speedup vs baseline: 2.7397x; 1.2194x over previous
#include <cuda_runtime.h>
#include <cuda_bf16.h>
#include <cuda_fp16.h>
#include <cstdint>

#define NB   4
#define CCH  512
#define NPIX 2304
#define CR   64
#define CH4  128
#define HW   48
#define NT2  576            // 24*24 winograd tiles per image

// ---------------- fp32 scratch ----------------
__device__ float g_E[(size_t)NB*NPIX*NPIX];
__device__ float g_buf0[NB*CCH*NPIX];
__device__ float g_buf1[NB*CCH*NPIX];
__device__ float g_out1[NB*CCH*NPIX];
__device__ float g_expd[NB*CCH*CCH];
__device__ float g_part[4718592];                       // split-K partials
__device__ float g_M[(size_t)16*CCH*NPIX];              // winograd M planes

// ---------------- bf16 split scratch ----------------
__device__ __nv_bfloat16 g_wq_h[CR*CCH],  g_wq_l[CR*CCH];
__device__ __nv_bfloat16 g_wk_h[CR*CCH],  g_wk_l[CR*CCH];
__device__ __nv_bfloat16 g_wv_h[CCH*CCH], g_wv_l[CCH*CCH];
__device__ __nv_bfloat16 g_qw1_h[CH4*CCH], g_qw1_l[CH4*CCH];
__device__ __nv_bfloat16 g_qw2_h[CH4*CCH], g_qw2_l[CH4*CCH];
__device__ __nv_bfloat16 g_ew1_h[CCH*CH4], g_ew1_l[CCH*CH4];
__device__ __nv_bfloat16 g_ew2_h[CCH*CH4], g_ew2_l[CCH*CH4];
__device__ __nv_bfloat16 g_x_h[(size_t)NB*CCH*NPIX], g_x_l[(size_t)NB*CCH*NPIX];
__device__ __nv_bfloat16 g_qT_h[NB*NPIX*CR], g_qT_l[NB*NPIX*CR];
__device__ __nv_bfloat16 g_k_h[NB*CR*NPIX],  g_k_l[NB*CR*NPIX];
__device__ __nv_bfloat16 g_b0_h[NB*CCH*NPIX], g_b0_l[NB*CCH*NPIX];
__device__ __nv_bfloat16 g_o1_h[NB*CCH*NPIX], g_o1_l[NB*CCH*NPIX];
__device__ __nv_bfloat16 g_qc_h[NB*CH4*NPIX], g_qc_l[NB*CH4*NPIX];
__device__ __nv_bfloat16 g_e2_h[NB*CH4*CCH],  g_e2_l[NB*CH4*CCH];

// ---------------- fp16 scratch ----------------
__device__ __half g_ww1_h[(size_t)16*CCH*CCH], g_ww1_l[(size_t)16*CCH*CCH];
__device__ __half g_ww2_h[(size_t)16*CCH*CCH], g_ww2_l[(size_t)16*CCH*CCH];
__device__ __half g_din[(size_t)16*CCH*NPIX];
__device__ __half g_v_h[NB*CCH*NPIX];
__device__ __half g_vc_h[NB*CCH*NPIX];
__device__ __half g_b0f_h[NB*CCH*NPIX];
__device__ __half g_o1f_h[NB*CCH*NPIX];
__device__ __half g_at0_h[(size_t)NB*NPIX*NPIX];
__device__ __half g_at1_h[(size_t)NB*NPIX*NPIX];
__device__ __half g_at2_h[(size_t)NB*NPIX*NPIX];
__device__ __half g_ac_h[NB*CCH*CCH];

// ---------------- reductions ----------------
__device__ __forceinline__ float warpMax(float v){
  #pragma unroll
  for (int o=16;o;o>>=1) v = fmaxf(v, __shfl_xor_sync(0xffffffffu, v, o));
  return v;
}
__device__ __forceinline__ float warpMin(float v){
  #pragma unroll
  for (int o=16;o;o>>=1) v = fminf(v, __shfl_xor_sync(0xffffffffu, v, o));
  return v;
}
__device__ __forceinline__ float warpSum(float v){
  #pragma unroll
  for (int o=16;o;o>>=1) v += __shfl_xor_sync(0xffffffffu, v, o);
  return v;
}
__device__ float blockMax(float v, float* sh){
  v = warpMax(v);
  if ((threadIdx.x & 31) == 0) sh[threadIdx.x >> 5] = v;
  __syncthreads();
  if (threadIdx.x < 32){
    float t = (threadIdx.x < (blockDim.x>>5)) ? sh[threadIdx.x] : -3.4e38f;
    t = warpMax(t);
    if (threadIdx.x == 0) sh[0] = t;
  }
  __syncthreads();
  float r = sh[0]; __syncthreads(); return r;
}
__device__ float blockMin(float v, float* sh){
  v = warpMin(v);
  if ((threadIdx.x & 31) == 0) sh[threadIdx.x >> 5] = v;
  __syncthreads();
  if (threadIdx.x < 32){
    float t = (threadIdx.x < (blockDim.x>>5)) ? sh[threadIdx.x] : 3.4e38f;
    t = warpMin(t);
    if (threadIdx.x == 0) sh[0] = t;
  }
  __syncthreads();
  float r = sh[0]; __syncthreads(); return r;
}
__device__ float blockSum(float v, float* sh){
  v = warpSum(v);
  if ((threadIdx.x & 31) == 0) sh[threadIdx.x >> 5] = v;
  __syncthreads();
  if (threadIdx.x < 32){
    float t = (threadIdx.x < (blockDim.x>>5)) ? sh[threadIdx.x] : 0.f;
    t = warpSum(t);
    if (threadIdx.x == 0) sh[0] = t;
  }
  __syncthreads();
  float r = sh[0]; __syncthreads(); return r;
}

// ---------------- type helpers ----------------
template<typename T> __device__ __forceinline__ void mma_t(float* c, const uint32_t* a, const uint32_t* b);
template<> __device__ __forceinline__ void mma_t<__nv_bfloat16>(float* c, const uint32_t* a, const uint32_t* b){
  asm volatile("mma.sync.aligned.m16n8k16.row.col.f32.bf16.bf16.f32 "
    "{%0,%1,%2,%3}, {%4,%5,%6,%7}, {%8,%9}, {%0,%1,%2,%3};\n"
    : "+f"(c[0]), "+f"(c[1]), "+f"(c[2]), "+f"(c[3])
    : "r"(a[0]), "r"(a[1]), "r"(a[2]), "r"(a[3]), "r"(b[0]), "r"(b[1]));
}
template<> __device__ __forceinline__ void mma_t<__half>(float* c, const uint32_t* a, const uint32_t* b){
  asm volatile("mma.sync.aligned.m16n8k16.row.col.f32.f16.f16.f32 "
    "{%0,%1,%2,%3}, {%4,%5,%6,%7}, {%8,%9}, {%0,%1,%2,%3};\n"
    : "+f"(c[0]), "+f"(c[1]), "+f"(c[2]), "+f"(c[3])
    : "r"(a[0]), "r"(a[1]), "r"(a[2]), "r"(a[3]), "r"(b[0]), "r"(b[1]));
}
__device__ __forceinline__ void ldsm_x4(uint32_t* r, uint32_t saddr){
  asm volatile("ldmatrix.sync.aligned.m8n8.x4.shared.b16 {%0,%1,%2,%3}, [%4];"
    : "=r"(r[0]), "=r"(r[1]), "=r"(r[2]), "=r"(r[3]) : "r"(saddr));
}
__device__ __forceinline__ void ldsm_x4t(uint32_t* r, uint32_t saddr){
  asm volatile("ldmatrix.sync.aligned.m8n8.x4.trans.shared.b16 {%0,%1,%2,%3}, [%4];"
    : "=r"(r[0]), "=r"(r[1]), "=r"(r[2]), "=r"(r[3]) : "r"(saddr));
}
__device__ __forceinline__ void cpasync16(void* dst, const void* src, int szbytes){
  uint32_t d = (uint32_t)__cvta_generic_to_shared(dst);
  asm volatile("cp.async.cg.shared.global [%0], [%1], 16, %2;\n"
               :: "r"(d), "l"(src), "r"(szbytes));
}
__device__ __forceinline__ void cp_commit(){ asm volatile("cp.async.commit_group;\n"); }
__device__ __forceinline__ void cp_wait0(){ asm volatile("cp.async.wait_group 0;\n"); }
__device__ __forceinline__ void cp_wait1(){ asm volatile("cp.async.wait_group 1;\n"); }

__device__ __forceinline__ void tsplit(float v, __nv_bfloat16& h, __nv_bfloat16& l){
  h = __float2bfloat16(v);
  l = __float2bfloat16(v - __bfloat162float(h));
}
__device__ __forceinline__ void tsplit(float v, __half& h, __half& l){
  h = __float2half_rn(v);
  l = __float2half_rn(v - __half2float(h));
}
__device__ __forceinline__ uint32_t tpack(__nv_bfloat16 a, __nv_bfloat16 b){
  return (uint32_t)__bfloat16_as_ushort(a) | ((uint32_t)__bfloat16_as_ushort(b) << 16);
}
__device__ __forceinline__ uint32_t tpack(__half a, __half b){
  return (uint32_t)__half_as_ushort(a) | ((uint32_t)__half_as_ushort(b) << 16);
}
__device__ __forceinline__ void bsplit(float v, __nv_bfloat16& h, __nv_bfloat16& l){ tsplit(v,h,l); }
__device__ __forceinline__ uint32_t bpack(__nv_bfloat16 a, __nv_bfloat16 b){ return tpack(a,b); }

// ---------------- tensor-core GEMM (typed, ldmatrix, K-tile 32, 2-stage, split-K) ----------------
// SL: store lo split output (0 = hi only).
template<typename T, int BI, int EPI, int AL, int BL, int SL, typename DT>
__global__ void __launch_bounds__(256,2) gemm3_kernel(
    const T* __restrict__ Ah, const T* __restrict__ Al, long sA,
    const T* __restrict__ Bh, const T* __restrict__ Bl, long sB,
    float* __restrict__ Cm, long sC,
    DT* __restrict__ Dh, DT* __restrict__ Dl, long sD,
    int M, int N, int K,
    const float* __restrict__ p0, const float* __restrict__ p1,
    const float* __restrict__ res, long sRes,
    const float* __restrict__ gamma, int ldT, int KS)
{
  constexpr int AROW = 40;
  constexpr int ABF  = 128*AROW;
  constexpr int ABYTES = 2*ABF*2;
  constexpr int BBF  = (BI==2) ? ABF : 32*136;
  constexpr int BBYTES = 2*BBF*2;
  constexpr int STAGEB = ABYTES + BBYTES;

  extern __shared__ char smc[];
  const uint32_t smem0 = (uint32_t)__cvta_generic_to_shared(smc);

  const int bz = blockIdx.z / KS;
  const int ksl = blockIdx.z - bz*KS;
  const int Kc = K / KS;
  const int k00 = ksl * Kc;

  Ah += (long)bz * sA;  if (AL) Al += (long)bz * sA;
  Bh += (long)bz * sB;  if (BL) Bl += (long)bz * sB;
  if (EPI == 7)      Cm += (long)blockIdx.z * ((long)M*N);
  else if (Cm)       Cm += (long)bz * sC;
  if (EPI >= 3 && EPI <= 6){ Dh += (long)bz * sD; if (SL) Dl += (long)bz * sD; }
  if (EPI == 2) res += (long)bz * sRes;

  const int tid  = threadIdx.x;
  const int warp = tid >> 5;
  const int lane = tid & 31;
  const int g    = lane >> 2;
  const int ct   = lane & 3;
  const int warpM = warp >> 2;
  const int warpN = warp & 3;
  const int m0 = blockIdx.y * 128;
  const int n0 = blockIdx.x * 128;

  const int lo8 = lane & 7, b3 = (lane>>3)&1, b4 = (lane>>4)&1;
  const uint32_t aoff  = ((warpM*64 + lo8 + b3*8)*AROW + b4*8)*2;
  const uint32_t boff2 = ((warpN*32 + lo8 + b4*8)*AROW + b3*8)*2;
  const uint32_t boff0 = ((lo8 + b3*8)*136 + warpN*32 + b4*8)*2;

  float acc[4][4][4];
  #pragma unroll
  for (int i=0;i<4;i++)
    #pragma unroll
    for (int j=0;j<4;j++)
      #pragma unroll
      for (int c=0;c<4;c++) acc[i][j][c]=0.f;

  auto loadT = [&](int s, int k0){
    char* st = smc + s*STAGEB;
    T* Ahs = (T*)st;
    constexpr int ACNT = AL ? 1024 : 512;
    #pragma unroll
    for (int c = tid; c < ACNT; c += 256){
      const T* base = (c < 512) ? Ah : Al;
      T* dst = Ahs + ((c < 512) ? 0 : ABF);
      int e = c & 511, row = e >> 2, q = e & 3;
      int gm = m0 + row;
      int sz = (gm < M) ? 16 : 0; if (gm >= M) gm = 0;
      cpasync16(dst + row*AROW + q*8, base + (long)gm*K + k0 + q*8, sz);
    }
    T* Bs = (T*)(st + ABYTES);
    constexpr int BCNT = BL ? 1024 : 512;
    if (BI == 2){
      #pragma unroll
      for (int c = tid; c < BCNT; c += 256){
        const T* base = (c < 512) ? Bh : Bl;
        T* dst = Bs + ((c < 512) ? 0 : ABF);
        int e = c & 511, row = e >> 2, q = e & 3;
        cpasync16(dst + row*AROW + q*8, base + (long)(n0+row)*K + k0 + q*8, 16);
      }
    } else {
      #pragma unroll
      for (int c = tid; c < BCNT; c += 256){
        const T* base = (c < 512) ? Bh : Bl;
        T* dst = Bs + ((c < 512) ? 0 : 32*136);
        int e = c & 511, row = e >> 4, ch = e & 15;
        cpasync16(dst + row*136 + ch*8, base + (long)(k0+row)*N + n0 + ch*8, 16);
      }
    }
  };

  const int T_ = Kc/32;
  loadT(0, k00); cp_commit();

  for (int i = 0; i < T_; i++){
    if (i + 1 < T_){ loadT((i+1)&1, k00 + (i+1)*32); cp_commit(); cp_wait1(); }
    else           { cp_wait0(); }
    __syncthreads();

    const uint32_t stb = smem0 + (uint32_t)((i&1)*STAGEB);
    const uint32_t bb  = stb + ABYTES;

    #pragma unroll
    for (int h = 0; h < 2; h++){
      const uint32_t aH = stb + aoff + h*32;
      const uint32_t aL = stb + ABF*2 + aoff + h*32;
      uint32_t ah[4][4], al[4][4], bhf[8], blf[8];
      #pragma unroll
      for (int mi=0; mi<4; mi++){
        ldsm_x4(ah[mi], aH + mi*(16*AROW*2));
        if (AL) ldsm_x4(al[mi], aL + mi*(16*AROW*2));
      }
      if (BI == 2){
        const uint32_t bH = bb + boff2 + h*32;
        const uint32_t bL = bb + ABF*2 + boff2 + h*32;
        ldsm_x4(bhf,   bH);
        ldsm_x4(bhf+4, bH + 16*AROW*2);
        if (BL){
          ldsm_x4(blf,   bL);
          ldsm_x4(blf+4, bL + 16*AROW*2);
        }
      } else {
        const uint32_t bH = bb + boff0 + h*(16*136*2);
        const uint32_t bL = bb + 32*136*2 + boff0 + h*(16*136*2);
        ldsm_x4t(bhf,   bH);
        ldsm_x4t(bhf+4, bH + 16*2);
        if (BL){
          ldsm_x4t(blf,   bL);
          ldsm_x4t(blf+4, bL + 16*2);
        }
      }
      #pragma unroll
      for (int mi=0; mi<4; mi++)
        #pragma unroll
        for (int nj=0; nj<4; nj++){
          mma_t<T>(acc[mi][nj], ah[mi], bhf + nj*2);
          if (BL) mma_t<T>(acc[mi][nj], ah[mi], blf + nj*2);
          if (AL) mma_t<T>(acc[mi][nj], al[mi], bhf + nj*2);
        }
    }
    __syncthreads();
  }

  // ---- epilogue
  #pragma unroll
  for (int mi=0; mi<4; mi++){
    int rr[2] = { m0 + warpM*64 + mi*16 + g, m0 + warpM*64 + mi*16 + g + 8 };
    float sc[2] = {0.f,0.f}, of[2] = {0.f,0.f};
    #pragma unroll
    for (int h=0; h<2; h++){
      if (rr[h] < M){
        if (EPI == 4){ sc[h] = p0[rr[h]]; of[h] = p1[rr[h]]; }
        else if (EPI == 0 || EPI == 5 || EPI == 6){ if (p0) of[h] = p0[rr[h]]; }
      }
    }
    #pragma unroll
    for (int nj=0; nj<4; nj++){
      int n = n0 + warpN*32 + nj*8 + 2*ct;
      #pragma unroll
      for (int h=0; h<2; h++){
        int r = rr[h];
        if (r >= M) continue;
        float wx = acc[mi][nj][2*h], wy = acc[mi][nj][2*h+1];
        if (EPI == 7){
          float2 w; w.x = wx; w.y = wy;
          *(float2*)&Cm[(long)r*N + n] = w;
          continue;
        }
        if (EPI == 0){ wx += of[h]; wy += of[h]; }
        else if (EPI == 2){
          float2 rv = *(const float2*)&res[(long)r*N + n];
          wx = gamma[0]*wx + rv.x; wy = gamma[0]*wy + rv.y;
        } else if (EPI == 4){
          wx = fmaxf(wx*sc[h] + of[h], 0.f);
          wy = fmaxf(wy*sc[h] + of[h], 0.f);
        } else { wx += of[h]; wy += of[h]; }
        if (EPI == 0 || EPI == 2){
          float2 w; w.x = wx; w.y = wy;
          *(float2*)&Cm[(long)r*N + n] = w;
        }
        if (EPI >= 3 && EPI <= 6){
          DT hx, lx, hy, ly;
          tsplit(wx, hx, lx); tsplit(wy, hy, ly);
          if (EPI == 6){
            Dh[(long)n*ldT + r] = hx;       Dh[(long)(n+1)*ldT + r] = hy;
            if (SL){ Dl[(long)n*ldT + r] = lx; Dl[(long)(n+1)*ldT + r] = ly; }
          } else {
            *(uint32_t*)&Dh[(long)r*N + n] = tpack(hx, hy);
            if (SL) *(uint32_t*)&Dl[(long)r*N + n] = tpack(lx, ly);
          }
        }
      }
    }
  }
}

// ---------------- split-K finalize (bf16 outputs) ----------------
template<int FM>
__global__ __launch_bounds__(256) void fin_kernel(
    const float* __restrict__ P, int KS, int M, int N,
    const float* __restrict__ p0, const float* __restrict__ p1,
    float* __restrict__ Cout, __nv_bfloat16* __restrict__ Dh,
    __nv_bfloat16* __restrict__ Dl, int ldT)
{
  const long MN = (long)M*N;
  long total2 = (long)NB*M*(N/2);
  long w = (long)blockIdx.x*256 + threadIdx.x;
  if (w >= total2) return;
  int n2 = (int)(w % (N/2));
  long t = w / (N/2);
  int r = (int)(t % M);
  int b = (int)(t / M);
  long base = ((long)(b*KS))*MN + (long)r*N + 2*n2;
  float vx = 0.f, vy = 0.f;
  for (int ks = 0; ks < KS; ks++){
    float2 pv = *(const float2*)&P[base + (long)ks*MN];
    vx += pv.x; vy += pv.y;
  }
  if (FM == 0){
    float of = p0 ? p0[r] : 0.f;
    float2 o; o.x = vx + of; o.y = vy + of;
    *(float2*)&Cout[(long)b*MN + (long)r*N + 2*n2] = o;
  } else if (FM == 4){
    float scv = p0[r], of = p1[r];
    vx = fmaxf(vx*scv + of, 0.f); vy = fmaxf(vy*scv + of, 0.f);
    __nv_bfloat16 hx,lx,hy,ly; bsplit(vx,hx,lx); bsplit(vy,hy,ly);
    long o = (long)b*MN + (long)r*N + 2*n2;
    *(uint32_t*)&Dh[o] = bpack(hx,hy);
    *(uint32_t*)&Dl[o] = bpack(lx,ly);
  } else if (FM == 5){
    float of = p0 ? p0[r] : 0.f;
    vx += of; vy += of;
    __nv_bfloat16 hx,lx,hy,ly; bsplit(vx,hx,lx); bsplit(vy,hy,ly);
    long o = (long)b*MN + (long)r*N + 2*n2;
    *(uint32_t*)&Dh[o] = bpack(hx,hy);
    *(uint32_t*)&Dl[o] = bpack(lx,ly);
  } else {
    float of = p0 ? p0[r] : 0.f;
    vx += of; vy += of;
    __nv_bfloat16 hx,lx,hy,ly; bsplit(vx,hx,lx); bsplit(vy,hy,ly);
    long ob = (long)b*MN;
    int n = 2*n2;
    Dh[ob + (long)n*ldT + r] = hx;     Dl[ob + (long)n*ldT + r] = lx;
    Dh[ob + (long)(n+1)*ldT + r] = hy; Dl[ob + (long)(n+1)*ldT + r] = ly;
  }
}

// ---------------- winograd F(2x2,3x3) transforms ----------------
__global__ __launch_bounds__(256) void wino_wt_kernel(const float* __restrict__ Wsrc,
    __half* __restrict__ Wh, __half* __restrict__ Wl)
{
  int idx = blockIdx.x*256 + threadIdx.x;
  if (idx >= CCH*CCH) return;
  int ic = idx & (CCH-1);
  int oc = idx >> 9;
  const float* gp = Wsrc + ((long)oc*CCH + ic)*9;
  float gm[3][3];
  #pragma unroll
  for (int i=0;i<3;i++)
    #pragma unroll
    for (int j=0;j<3;j++) gm[i][j] = gp[i*3+j];
  float r[4][3];
  #pragma unroll
  for (int j=0;j<3;j++){
    r[0][j] = gm[0][j];
    r[1][j] = 0.5f*(gm[0][j]+gm[1][j]+gm[2][j]);
    r[2][j] = 0.5f*(gm[0][j]-gm[1][j]+gm[2][j]);
    r[3][j] = gm[2][j];
  }
  #pragma unroll
  for (int u=0;u<4;u++){
    float w0 = r[u][0];
    float w1 = 0.5f*(r[u][0]+r[u][1]+r[u][2]);
    float w2 = 0.5f*(r[u][0]-r[u][1]+r[u][2]);
    float w3 = r[u][2];
    float wv[4] = {w0,w1,w2,w3};
    #pragma unroll
    for (int v=0;v<4;v++){
      __half h,l; tsplit(wv[v],h,l);
      long o = ((long)(u*4+v)*CCH + oc)*CCH + ic;
      Wh[o] = h; Wl[o] = l;
    }
  }
}

__global__ __launch_bounds__(256) void wino_in_kernel(const float* __restrict__ X,
    __half* __restrict__ Dd)
{
  long w = (long)blockIdx.x*256 + threadIdx.x;
  const long total = (long)NB*CCH*NT2;
  if (w >= total) return;
  int t = (int)(w % NT2);
  long r = w / NT2;
  int c = (int)(r % CCH);
  int b = (int)(r / CCH);
  int ty = t / 24, tx = t - (t/24)*24;
  const float* xs = X + ((long)(b*CCH + c))*NPIX;
  float d[4][4];
  #pragma unroll
  for (int i=0;i<4;i++){
    int iy = 2*ty - 1 + i;
    #pragma unroll
    for (int j=0;j<4;j++){
      int ix = 2*tx - 1 + j;
      d[i][j] = (iy >= 0 && iy < HW && ix >= 0 && ix < HW) ? xs[iy*HW+ix] : 0.f;
    }
  }
  float tb[4][4];
  #pragma unroll
  for (int j=0;j<4;j++){
    tb[0][j] = d[0][j] - d[2][j];
    tb[1][j] = d[1][j] + d[2][j];
    tb[2][j] = d[2][j] - d[1][j];
    tb[3][j] = d[1][j] - d[3][j];
  }
  long nidx = (long)b*NT2 + t;
  #pragma unroll
  for (int i=0;i<4;i++){
    float D0 = tb[i][0] - tb[i][2];
    float D1 = tb[i][1] + tb[i][2];
    float D2 = tb[i][2] - tb[i][1];
    float D3 = tb[i][1] - tb[i][3];
    float Dv[4] = {D0,D1,D2,D3};
    #pragma unroll
    for (int j=0;j<4;j++){
      long o = ((long)(i*4+j)*CCH + c)*NPIX + nidx;
      Dd[o] = __float2half_rn(Dv[j]);
    }
  }
}

// output transform: Y = A^T M A, BN+ReLU; fp32 + bf16 split + fp16 hi.
__global__ __launch_bounds__(256) void wino_out_kernel(const float* __restrict__ Mp,
    const float* __restrict__ scale, const float* __restrict__ bias,
    float* __restrict__ Y, __nv_bfloat16* __restrict__ Yh, __nv_bfloat16* __restrict__ Yl,
    __half* __restrict__ Fh)
{
  const long MN = (long)CCH*NPIX;
  long w = (long)blockIdx.x*256 + threadIdx.x;
  const long total = (long)NB*CCH*NT2;
  if (w >= total) return;
  int t = (int)(w % NT2);
  long r = w / NT2;
  int oc = (int)(r % CCH);
  int b  = (int)(r / CCH);
  int ty = t / 24, tx = t - (t/24)*24;
  long base = (long)oc*NPIX + (long)b*NT2 + t;
  float m[4][4];
  #pragma unroll
  for (int u=0;u<4;u++)
    #pragma unroll
    for (int v=0;v<4;v++) m[u][v] = Mp[(long)(u*4+v)*MN + base];
  float s0[4], s1[4];
  #pragma unroll
  for (int v=0;v<4;v++){
    s0[v] = m[0][v] + m[1][v] + m[2][v];
    s1[v] = m[1][v] - m[2][v] - m[3][v];
  }
  float y00 = s0[0]+s0[1]+s0[2], y01 = s0[1]-s0[2]-s0[3];
  float y10 = s1[0]+s1[1]+s1[2], y11 = s1[1]-s1[2]-s1[3];
  float sc = scale[oc], bi = bias[oc];
  y00 = fmaxf(y00*sc+bi, 0.f); y01 = fmaxf(y01*sc+bi, 0.f);
  y10 = fmaxf(y10*sc+bi, 0.f); y11 = fmaxf(y11*sc+bi, 0.f);
  long ob = ((long)(b*CCH + oc))*NPIX;
  long p0i = ob + (2*ty)*HW + 2*tx;
  long p1i = ob + (2*ty+1)*HW + 2*tx;
  float2 w0; w0.x = y00; w0.y = y01;
  float2 w1; w1.x = y10; w1.y = y11;
  *(float2*)&Y[p0i] = w0;
  *(float2*)&Y[p1i] = w1;
  __nv_bfloat16 h0,l0,h1,l1;
  bsplit(y00,h0,l0); bsplit(y01,h1,l1);
  *(uint32_t*)&Yh[p0i] = bpack(h0,h1);
  *(uint32_t*)&Yl[p0i] = bpack(l0,l1);
  bsplit(y10,h0,l0); bsplit(y11,h1,l1);
  *(uint32_t*)&Yh[p1i] = bpack(h0,h1);
  *(uint32_t*)&Yl[p1i] = bpack(l0,l1);
  *(uint32_t*)&Fh[p0i] = tpack(__float2half_rn(y00), __float2half_rn(y01));
  *(uint32_t*)&Fh[p1i] = tpack(__float2half_rn(y10), __float2half_rn(y11));
}

// ---------------- fused softmax: one exp per element, all 3 variants (fp16 out) ----------------
__global__ __launch_bounds__(288) void softmax_all_kernel(
    const float* __restrict__ E,
    const float* __restrict__ M1, const float* __restrict__ M2,
    __half* __restrict__ a0h, __half* __restrict__ a1h, __half* __restrict__ a2h)
{
  __shared__ float sh[32];
  long row = blockIdx.x;
  int  mr  = (int)(row % NPIX);
  const float* e  = E  + row * NPIX;
  const float* m1 = M1 + (long)mr * NPIX;
  const float* m2 = M2 + (long)mr * NPIX;
  int tid = threadIdx.x;

  float ev[8], w1[8], w2[8];
  float mx = -3.4e38f;
  #pragma unroll
  for (int j = 0; j < 4; j++){
    int n = 2*(tid + j*288);
    float2 e2 = *(const float2*)&e[n];
    float2 u1 = *(const float2*)&m1[n];
    float2 u2 = *(const float2*)&m2[n];
    ev[2*j]=e2.x; ev[2*j+1]=e2.y;
    w1[2*j]=u1.x; w1[2*j+1]=u1.y;
    w2[2*j]=u2.x; w2[2*j+1]=u2.y;
    mx = fmaxf(mx, fmaxf(e2.x, e2.y));
  }
  mx = blockMax(mx, sh);

  float x0[8];
  float s0 = 0.f, s1 = 0.f, s2 = 0.f;
  #pragma unroll
  for (int i = 0; i < 8; i++){
    x0[i] = __expf(ev[i] - mx);
    s0 += x0[i];
    if (w1[i] > 0.f) s1 += x0[i];
    if (w2[i] > 0.f) s2 += x0[i];
  }
  s0 = blockSum(s0, sh);
  s1 = blockSum(s1, sh);
  s2 = blockSum(s2, sh);
  float r0 = 1.f/s0, r1 = 1.f/s1, r2 = 1.f/s2;

  #pragma unroll
  for (int j = 0; j < 4; j++){
    int n = 2*(tid + j*288);
    long o = row * NPIX + n;
    float px = x0[2*j], py = x0[2*j+1];
    *(uint32_t*)&a0h[o] = tpack(__float2half_rn(px*r0), __float2half_rn(py*r0));
    float ax = (w1[2*j]   > 0.f) ? px*r1 : 0.f;
    float ay = (w1[2*j+1] > 0.f) ? py*r1 : 0.f;
    *(uint32_t*)&a1h[o] = tpack(__float2half_rn(ax), __float2half_rn(ay));
    ax = (w2[2*j]   > 0.f) ? px*r2 : 0.f;
    ay = (w2[2*j+1] > 0.f) ? py*r2 : 0.f;
    *(uint32_t*)&a2h[o] = tpack(__float2half_rn(ax), __float2half_rn(ay));
  }
}

// ---------------- chl softmax -> fp16 ----------------
__global__ __launch_bounds__(256) void chl_softmax_kernel(
    const float* __restrict__ E, __half* __restrict__ Ahd)
{
  __shared__ float sh[32];
  long row = blockIdx.x;
  const float* e = E + row * CCH;
  int tid = threadIdx.x;
  float v0 = e[tid], v1 = e[tid+256];
  float mn = blockMin(fminf(v0, v1), sh);
  float t0 = __expf(mn - v0), t1 = __expf(mn - v1);
  float s = blockSum(t0 + t1, sh);
  float rinv = 1.f/s;
  Ahd[row*CCH + tid]     = __float2half_rn(t0*rinv);
  Ahd[row*CCH + tid+256] = __float2half_rn(t1*rinv);
}

// ---------------- prepass: plain split (bf16) ----------------
__global__ __launch_bounds__(256) void split_nat_kernel(const float* __restrict__ X,
    __nv_bfloat16* __restrict__ H, __nv_bfloat16* __restrict__ L, long total)
{
  for (long i = (long)blockIdx.x*256 + threadIdx.x; i < total; i += (long)gridDim.x*256){
    __nv_bfloat16 h,l; bsplit(X[i], h, l); H[i] = h; L[i] = l;
  }
}

// ---------------- host ----------------
template<typename T, int BI, int EPI, int AL = 1, int BL = 1, int SL = 1, typename DT = T>
static void rg(const T* Ah, const T* Al, long sA,
               const T* Bh, const T* Bl, long sB,
               float* C, long sC,
               DT* Dh, DT* Dl, long sD,
               int M, int N, int K,
               const float* p0, const float* p1,
               const float* res, long sRes, const float* gamma, int ldT,
               int KS = 1, int NZ = NB)
{
  constexpr int ABYTES = 2*128*40*2;
  constexpr int BBYTES = (BI==2) ? ABYTES : 2*32*136*2;
  constexpr int SMEM = 2*(ABYTES + BBYTES);
  cudaFuncSetAttribute(gemm3_kernel<T,BI,EPI,AL,BL,SL,DT>,
                       cudaFuncAttributeMaxDynamicSharedMemorySize, SMEM);
  dim3 grid(N/128, (M+127)/128, NZ*KS);
  gemm3_kernel<T,BI,EPI,AL,BL,SL,DT><<<grid, 256, SMEM>>>(Ah, Al, sA, Bh, Bl, sB, C, sC,
                                                          Dh, Dl, sD, M, N, K, p0, p1, res, sRes, gamma, ldT, KS);
}

template<typename T>
static T* sym(const void* s){ void* p = nullptr; cudaGetSymbolAddress(&p, s); return (T*)p; }

static int gsz(long t){ return (int)((t + 255)/256); }

template<int FM>
static void fin(const float* P, int KS, int M, int N,
                const float* p0, const float* p1,
                float* Cout, __nv_bfloat16* Dh, __nv_bfloat16* Dl, int ldT)
{
  long total2 = (long)NB*M*(N/2);
  fin_kernel<FM><<<gsz(total2), 256>>>(P, KS, M, N, p0, p1, Cout, Dh, Dl, ldT);
}

extern "C" void kernel_launch(void* const* d_in, const int* in_sizes, int n_in,
                              void* d_out, int out_size)
{
  const float* x       = (const float*)d_in[0];
  const float* wq      = (const float*)d_in[1];
  const float* bq      = (const float*)d_in[2];
  const float* wk      = (const float*)d_in[3];
  const float* bk      = (const float*)d_in[4];
  const float* wv0     = (const float*)d_in[5];
  const float* bv0     = (const float*)d_in[6];
  const float* conv1_w = (const float*)d_in[7];
  const float* conv1_s = (const float*)d_in[8];
  const float* conv1_b = (const float*)d_in[9];
  const float* conv2_w = (const float*)d_in[10];
  const float* conv2_s = (const float*)d_in[11];
  const float* conv2_b = (const float*)d_in[12];
  const float* gamma   = (const float*)d_in[13];
  const float* gamma1  = (const float*)d_in[14];
  const float* gamma2  = (const float*)d_in[15];
  const float* c1_qw   = (const float*)d_in[16];
  const float* c1_qs   = (const float*)d_in[17];
  const float* c1_qb   = (const float*)d_in[18];
  const float* c1_ew   = (const float*)d_in[19];
  const float* c1_eb   = (const float*)d_in[20];
  const float* c2_qw   = (const float*)d_in[21];
  const float* c2_qs   = (const float*)d_in[22];
  const float* c2_qb   = (const float*)d_in[23];
  const float* c2_ew   = (const float*)d_in[24];
  const float* c2_eb   = (const float*)d_in[25];
  const float* mask1   = (const float*)d_in[26];
  const float* mask2   = (const float*)d_in[27];

  typedef __nv_bfloat16 bf;
  typedef __half hf;
  float* E    = sym<float>(g_E);
  float* buf0 = sym<float>(g_buf0); float* buf1 = sym<float>(g_buf1);
  float* out1 = sym<float>(g_out1); float* expd = sym<float>(g_expd);
  float* part = sym<float>(g_part); float* Mw   = sym<float>(g_M);
  bf *wq_h = sym<bf>(g_wq_h), *wq_l = sym<bf>(g_wq_l);
  bf *wk_h = sym<bf>(g_wk_h), *wk_l = sym<bf>(g_wk_l);
  bf *wv_h = sym<bf>(g_wv_h), *wv_l = sym<bf>(g_wv_l);
  hf *ww1_h = sym<hf>(g_ww1_h), *ww1_l = sym<hf>(g_ww1_l);
  hf *ww2_h = sym<hf>(g_ww2_h), *ww2_l = sym<hf>(g_ww2_l);
  hf *din  = sym<hf>(g_din);
  bf *qw1_h = sym<bf>(g_qw1_h), *qw1_l = sym<bf>(g_qw1_l);
  bf *qw2_h = sym<bf>(g_qw2_h), *qw2_l = sym<bf>(g_qw2_l);
  bf *ew1_h = sym<bf>(g_ew1_h), *ew1_l = sym<bf>(g_ew1_l);
  bf *ew2_h = sym<bf>(g_ew2_h), *ew2_l = sym<bf>(g_ew2_l);
  bf *x_h = sym<bf>(g_x_h), *x_l = sym<bf>(g_x_l);
  bf *qT_h = sym<bf>(g_qT_h), *qT_l = sym<bf>(g_qT_l);
  bf *k_h  = sym<bf>(g_k_h),  *k_l  = sym<bf>(g_k_l);
  bf *b0_h = sym<bf>(g_b0_h), *b0_l = sym<bf>(g_b0_l);
  bf *o1_h = sym<bf>(g_o1_h), *o1_l = sym<bf>(g_o1_l);
  bf *qc_h = sym<bf>(g_qc_h), *qc_l = sym<bf>(g_qc_l);
  bf *e2_h = sym<bf>(g_e2_h), *e2_l = sym<bf>(g_e2_l);
  hf *v_h  = sym<hf>(g_v_h);
  hf *vc_h = sym<hf>(g_vc_h);
  hf *b0f_h = sym<hf>(g_b0f_h);
  hf *o1f_h = sym<hf>(g_o1f_h);
  hf *at0_h = sym<hf>(g_at0_h);
  hf *at1_h = sym<hf>(g_at1_h);
  hf *at2_h = sym<hf>(g_at2_h);
  hf *ac_h  = sym<hf>(g_ac_h);
  float* out = (float*)d_out;

  const long sX  = (long)CCH*NPIX;
  const long sE  = (long)NPIX*NPIX;
  const long sQT = (long)NPIX*CR;
  const long sK  = (long)CR*NPIX;
  const long sQC = (long)CH4*NPIX;
  const long sE2 = (long)CH4*CCH;
  const long sCC = (long)CCH*CCH;
  const long sWW = (long)CCH*CCH;
  const long sDI = (long)CCH*NPIX;
  const int  R   = NB*NPIX;
  const long winoTot = (long)NB*CCH*NT2;

  // ---- prepass splits ----
  split_nat_kernel<<<gsz(CR*CCH),256>>>(wq, wq_h, wq_l, CR*CCH);
  split_nat_kernel<<<gsz(CR*CCH),256>>>(wk, wk_h, wk_l, CR*CCH);
  split_nat_kernel<<<gsz(CCH*CCH),256>>>(wv0, wv_h, wv_l, CCH*CCH);
  split_nat_kernel<<<gsz((long)NB*sX),256>>>(x, x_h, x_l, (long)NB*sX);

  // ---- Q, K (split-K KS=4), V (fp16 hi out) ----
  rg<bf,0,7>(wq_h, wq_l, 0, x_h, x_l, sX, part, 0, (bf*)nullptr,(bf*)nullptr,0,
          CR, NPIX, CCH, nullptr, nullptr, nullptr,0, nullptr, 0, 4);
  fin<6>(part, 4, CR, NPIX, bq, nullptr, nullptr, qT_h, qT_l, CR);
  rg<bf,0,7>(wk_h, wk_l, 0, x_h, x_l, sX, part, 0, (bf*)nullptr,(bf*)nullptr,0,
          CR, NPIX, CCH, nullptr, nullptr, nullptr,0, nullptr, 0, 4);
  fin<5>(part, 4, CR, NPIX, bk, nullptr, nullptr, k_h, k_l, 0);
  rg<bf,0,5,1,1,0,hf>(wv_h, wv_l, 0, x_h, x_l, sX, nullptr,0, v_h, (hf*)nullptr, sX,
          CCH, NPIX, CCH, bv0, nullptr, nullptr,0, nullptr, 0);

  // ---- energy = qT * k ----
  rg<bf,0,0>(qT_h, qT_l, sQT, k_h, k_l, sK, E, sE, (bf*)nullptr,(bf*)nullptr,0,
          NPIX, NPIX, CR, nullptr, nullptr, nullptr,0, nullptr, 0);

  // ---- remaining weight transforms/splits ----
  wino_wt_kernel<<<gsz(CCH*CCH),256>>>(conv1_w, ww1_h, ww1_l);
  wino_wt_kernel<<<gsz(CCH*CCH),256>>>(conv2_w, ww2_h, ww2_l);
  split_nat_kernel<<<gsz(CH4*CCH),256>>>(c1_qw, qw1_h, qw1_l, CH4*CCH);
  split_nat_kernel<<<gsz(CH4*CCH),256>>>(c2_qw, qw2_h, qw2_l, CH4*CCH);
  split_nat_kernel<<<gsz(CCH*CH4),256>>>(c1_ew, ew1_h, ew1_l, CCH*CH4);
  split_nat_kernel<<<gsz(CCH*CH4),256>>>(c2_ew, ew2_h, ew2_l, CCH*CH4);

  // ---- fused softmax (fp16 attention matrices) ----
  softmax_all_kernel<<<R, 288>>>(E, mask1, mask2, at0_h, at1_h, at2_h);

  // ---- pass 0: attention (fp16 single x single) ----
  rg<hf,2,2,0,0>(v_h, (hf*)nullptr, sX, at0_h, (hf*)nullptr, sE, buf1, sX, (hf*)nullptr,(hf*)nullptr,0,
          CCH, NPIX, NPIX, nullptr, nullptr, (const float*)x, sX, gamma, 0);
  wino_in_kernel<<<gsz(winoTot),256>>>(buf1, din);
  rg<hf,0,0,1,0>(ww1_h, ww1_l, sWW, din, (hf*)nullptr, sDI, Mw, sDI, (hf*)nullptr,(hf*)nullptr,0,
          CCH, NPIX, CCH, nullptr, nullptr, nullptr,0, nullptr, 0, 1, 16);
  wino_out_kernel<<<gsz(winoTot),256>>>(Mw, conv1_s, conv1_b, buf0, b0_h, b0_l, b0f_h);

  // chl #1 (split-K on qc/e2/expand)
  rg<bf,0,7>(qw1_h, qw1_l, 0, b0_h, b0_l, sX, part, 0, (bf*)nullptr,(bf*)nullptr,0,
          CH4, NPIX, CCH, nullptr, nullptr, nullptr,0, nullptr, 0, 4);
  fin<4>(part, 4, CH4, NPIX, c1_qs, c1_qb, nullptr, qc_h, qc_l, 0);
  rg<bf,2,7>(qc_h, qc_l, sQC, b0_h, b0_l, sX, part, 0, (bf*)nullptr,(bf*)nullptr,0,
          CH4, CCH, NPIX, nullptr, nullptr, nullptr,0, nullptr, 0, 18);
  fin<5>(part, 18, CH4, CCH, nullptr, nullptr, nullptr, e2_h, e2_l, 0);
  rg<bf,0,7>(ew1_h, ew1_l, 0, e2_h, e2_l, sE2, part, 0, (bf*)nullptr,(bf*)nullptr,0,
          CCH, CCH, CH4, nullptr, nullptr, nullptr,0, nullptr, 0, 4);
  fin<0>(part, 4, CCH, CCH, c1_eb, nullptr, expd, nullptr, nullptr, 0);
  chl_softmax_kernel<<<NB*CCH, 256>>>(expd, ac_h);
  rg<hf,0,5,0,0,0,hf>(ac_h, (hf*)nullptr, sCC, b0f_h, (hf*)nullptr, sX, nullptr,0, vc_h, (hf*)nullptr, sX,
          CCH, NPIX, CCH, nullptr, nullptr, nullptr,0, nullptr, 0);

  // ---- pass 1 ----
  rg<hf,2,2,0,0>(vc_h, (hf*)nullptr, sX, at1_h, (hf*)nullptr, sE, buf1, sX, (hf*)nullptr,(hf*)nullptr,0,
          CCH, NPIX, NPIX, nullptr, nullptr, buf0, sX, gamma1, 0);
  wino_in_kernel<<<gsz(winoTot),256>>>(buf1, din);
  rg<hf,0,0,1,0>(ww2_h, ww2_l, sWW, din, (hf*)nullptr, sDI, Mw, sDI, (hf*)nullptr,(hf*)nullptr,0,
          CCH, NPIX, CCH, nullptr, nullptr, nullptr,0, nullptr, 0, 1, 16);
  wino_out_kernel<<<gsz(winoTot),256>>>(Mw, conv2_s, conv2_b, out1, o1_h, o1_l, o1f_h);

  // chl #2
  rg<bf,0,7>(qw2_h, qw2_l, 0, o1_h, o1_l, sX, part, 0, (bf*)nullptr,(bf*)nullptr,0,
          CH4, NPIX, CCH, nullptr, nullptr, nullptr,0, nullptr, 0, 4);
  fin<4>(part, 4, CH4, NPIX, c2_qs, c2_qb, nullptr, qc_h, qc_l, 0);
  rg<bf,2,7>(qc_h, qc_l, sQC, o1_h, o1_l, sX, part, 0, (bf*)nullptr,(bf*)nullptr,0,
          CH4, CCH, NPIX, nullptr, nullptr, nullptr,0, nullptr, 0, 18);
  fin<5>(part, 18, CH4, CCH, nullptr, nullptr, nullptr, e2_h, e2_l, 0);
  rg<bf,0,7>(ew2_h, ew2_l, 0, e2_h, e2_l, sE2, part, 0, (bf*)nullptr,(bf*)nullptr,0,
          CCH, CCH, CH4, nullptr, nullptr, nullptr,0, nullptr, 0, 4);
  fin<0>(part, 4, CCH, CCH, c2_eb, nullptr, expd, nullptr, nullptr, 0);
  chl_softmax_kernel<<<NB*CCH, 256>>>(expd, ac_h);
  rg<hf,0,5,0,0,0,hf>(ac_h, (hf*)nullptr, sCC, o1f_h, (hf*)nullptr, sX, nullptr,0, vc_h, (hf*)nullptr, sX,
          CCH, NPIX, CCH, nullptr, nullptr, nullptr,0, nullptr, 0);

  // ---- pass 2 -> out ----
  rg<hf,2,2,0,0>(vc_h, (hf*)nullptr, sX, at2_h, (hf*)nullptr, sE, out, sX, (hf*)nullptr,(hf*)nullptr,0,
          CCH, NPIX, NPIX, nullptr, nullptr, out1, sX, gamma2, 0);

  (void)in_sizes; (void)n_in; (void)out_size;
}